// round 4
// baseline (speedup 1.0000x reference)
#include <cuda_runtime.h>
#include <math.h>

// ---------------------------------------------------------------------------
// VQ-VAE forward, fp32. Round 4: scalar FFMA (f32x2 reverted — measured
// half-rate), weight repack for float4 weight loads, unroll-2 ci loops,
// VQ grid fix.
// Output layout: [loss, x_recon(1572864), perplexity]
// ---------------------------------------------------------------------------

// Scratch (device globals; no allocation allowed)
__device__ float g_A[32u * 64 * 64 * 64];
__device__ float g_B[32u * 128 * 32 * 32];
__device__ float g_C[32u * 128 * 32 * 32];
__device__ float g_T[32u * 32 * 32 * 32];
__device__ float g_Z[32u * 64 * 32 * 32];
__device__ float g_Q[32u * 64 * 32 * 32];
__device__ float g_G[32u * 128 * 32 * 32];
__device__ int   g_idx[32768];
__device__ float g_cnorm[512];
__device__ float g_err[32768];
__device__ __align__(16) float g_W[393216];   // repacked weights

// ---------------------------------------------------------------------------
// Weight repack: 3x3 OIHW -> [g][ci][t*4+c], g=co/4, t=ky*3+kx
// ---------------------------------------------------------------------------
__global__ void repack3_k(const float* __restrict__ w, float* __restrict__ dst,
                          int COUT, int CIN)
{
    int i = blockIdx.x * 256 + threadIdx.x;
    int total = COUT * CIN * 9;
    if (i >= total) return;
    int t  = i % 9;
    int ci = (i / 9) % CIN;
    int co = i / (9 * CIN);
    dst[((size_t)((co >> 2) * CIN + ci)) * 36 + t * 4 + (co & 3)] = w[i];
}

// 1x1 OI -> [g][ci][c]
__global__ void repack1_k(const float* __restrict__ w, float* __restrict__ dst,
                          int COUT, int CIN)
{
    int i = blockIdx.x * 256 + threadIdx.x;
    if (i >= COUT * CIN) return;
    int ci = i % CIN;
    int co = i / CIN;
    dst[((size_t)((co >> 2) * CIN + ci)) * 4 + (co & 3)] = w[i];
}

// ---------------------------------------------------------------------------
// 3x3 s1 p1 conv on 32x32 maps, repacked weights. TX=8, TCO=4.
// One block = one (image, 4-co group): 128 threads x 8 outputs.
// ---------------------------------------------------------------------------
template <int CIN, int COUT, bool IN_RELU, bool BIAS>
__global__ __launch_bounds__(128)
void conv3r_k(const float* __restrict__ in, const float* __restrict__ wr,
              const float* __restrict__ bs, float* __restrict__ out)
{
    const int t   = threadIdx.x;
    const int ox0 = (t * 8) & 31;
    const int oy  = t >> 2;
    const int gco = blockIdx.y;
    const int b   = blockIdx.z;

    float acc[4][8];
#pragma unroll
    for (int c = 0; c < 4; c++) {
        float bv = BIAS ? __ldg(bs + gco * 4 + c) : 0.f;
#pragma unroll
        for (int j = 0; j < 8; j++) acc[c][j] = bv;
    }

    const float* inb = in + (size_t)b * CIN * 1024;
    const float4* wrb = (const float4*)wr + (size_t)gco * CIN * 9;

#pragma unroll 2
    for (int ci = 0; ci < CIN; ci++) {
        float4 W[9];
#pragma unroll
        for (int k = 0; k < 9; k++) W[k] = __ldg(wrb + ci * 9 + k);
        const float* ip = inb + ci * 1024;
#pragma unroll
        for (int ky = 0; ky < 3; ky++) {
            int iy = oy - 1 + ky;
            if (iy < 0 || iy >= 32) continue;
            const float* row = ip + iy * 32;
            float w[10];
            w[0] = (ox0 > 0) ? row[ox0 - 1] : 0.f;
            float4 v0 = *(const float4*)(row + ox0);
            float4 v1 = *(const float4*)(row + ox0 + 4);
            w[1] = v0.x; w[2] = v0.y; w[3] = v0.z; w[4] = v0.w;
            w[5] = v1.x; w[6] = v1.y; w[7] = v1.z; w[8] = v1.w;
            w[9] = (ox0 < 24) ? row[ox0 + 8] : 0.f;
            if (IN_RELU) {
#pragma unroll
                for (int m = 0; m < 10; m++) w[m] = fmaxf(w[m], 0.f);
            }
#pragma unroll
            for (int kx = 0; kx < 3; kx++) {
                float4 wv = W[ky * 3 + kx];
#pragma unroll
                for (int j = 0; j < 8; j++) {
                    acc[0][j] = fmaf(w[kx + j], wv.x, acc[0][j]);
                    acc[1][j] = fmaf(w[kx + j], wv.y, acc[1][j]);
                    acc[2][j] = fmaf(w[kx + j], wv.z, acc[2][j]);
                    acc[3][j] = fmaf(w[kx + j], wv.w, acc[3][j]);
                }
            }
        }
    }

#pragma unroll
    for (int c = 0; c < 4; c++) {
        size_t o = (((size_t)b * COUT + (gco * 4 + c)) * 32 + oy) * 32 + ox0;
        *(float4*)(out + o)     = make_float4(acc[c][0], acc[c][1], acc[c][2], acc[c][3]);
        *(float4*)(out + o + 4) = make_float4(acc[c][4], acc[c][5], acc[c][6], acc[c][7]);
    }
}

// ---------------------------------------------------------------------------
// 1x1 conv on 32x32 maps, repacked weights, relu-in always; optional bias/add.
// ---------------------------------------------------------------------------
template <int CIN, int COUT, bool BIAS, bool ADD>
__global__ __launch_bounds__(128)
void conv1r_k(const float* __restrict__ in, const float* __restrict__ wr,
              const float* __restrict__ bs, float* __restrict__ out,
              const float* __restrict__ res)
{
    const int t   = threadIdx.x;
    const int ox0 = (t * 8) & 31;
    const int oy  = t >> 2;
    const int gco = blockIdx.y;
    const int b   = blockIdx.z;

    float acc[4][8];
#pragma unroll
    for (int c = 0; c < 4; c++) {
        float bv = BIAS ? __ldg(bs + gco * 4 + c) : 0.f;
#pragma unroll
        for (int j = 0; j < 8; j++) acc[c][j] = bv;
    }

    const float* inb = in + (size_t)b * CIN * 1024 + oy * 32 + ox0;
    const float4* wrb = (const float4*)wr + (size_t)gco * CIN;

#pragma unroll 2
    for (int ci = 0; ci < CIN; ci++) {
        const float* p = inb + ci * 1024;
        float4 v0 = *(const float4*)p;
        float4 v1 = *(const float4*)(p + 4);
        float w[8] = {v0.x, v0.y, v0.z, v0.w, v1.x, v1.y, v1.z, v1.w};
#pragma unroll
        for (int m = 0; m < 8; m++) w[m] = fmaxf(w[m], 0.f);   // relu-in
        float4 wv = __ldg(wrb + ci);
#pragma unroll
        for (int j = 0; j < 8; j++) {
            acc[0][j] = fmaf(w[j], wv.x, acc[0][j]);
            acc[1][j] = fmaf(w[j], wv.y, acc[1][j]);
            acc[2][j] = fmaf(w[j], wv.z, acc[2][j]);
            acc[3][j] = fmaf(w[j], wv.w, acc[3][j]);
        }
    }

#pragma unroll
    for (int c = 0; c < 4; c++) {
        size_t o = (((size_t)b * COUT + (gco * 4 + c)) * 32 + oy) * 32 + ox0;
        float v[8];
#pragma unroll
        for (int j = 0; j < 8; j++) v[j] = acc[c][j];
        if (ADD) {
            float4 r0 = *(const float4*)(res + o);
            float4 r1 = *(const float4*)(res + o + 4);
            v[0] += r0.x; v[1] += r0.y; v[2] += r0.z; v[3] += r0.w;
            v[4] += r1.x; v[5] += r1.y; v[6] += r1.z; v[7] += r1.w;
        }
        *(float4*)(out + o)     = make_float4(v[0], v[1], v[2], v[3]);
        *(float4*)(out + o + 4) = make_float4(v[4], v[5], v[6], v[7]);
    }
}

// ---------------------------------------------------------------------------
// k4 s2 p1 conv (e1, e2). TX=8, TCO=4, float4 weight loads (contiguous 16/ci).
// ---------------------------------------------------------------------------
template <int TCO, int CIN, int HIN, int WIN, int COUT, int HOUT, int WOUT,
          bool OUT_RELU>
__global__ __launch_bounds__(128)
void conv4_k(const float* __restrict__ in, const float* __restrict__ wt,
             const float* __restrict__ bs, float* __restrict__ out)
{
    constexpr int TX   = 8;
    constexpr int WINW = 18;   // (8-1)*2 + 4
    static_assert((HOUT * WOUT / TX) % 128 == 0, "tiles fill blocks");

    int tid = blockIdx.x * 128 + threadIdx.x;
    int ox0 = (tid * TX) % WOUT;
    int oy  = (tid * TX) / WOUT;
    int co0 = blockIdx.y * TCO;
    int b   = blockIdx.z;

    float acc[TCO][TX];
#pragma unroll
    for (int c = 0; c < TCO; c++) {
        float bv = __ldg(bs + co0 + c);
#pragma unroll
        for (int j = 0; j < TX; j++) acc[c][j] = bv;
    }

    const float* inb = in + (size_t)b * CIN * HIN * WIN;
    const int ixb = ox0 * 2 - 1;

#pragma unroll 2
    for (int ci = 0; ci < CIN; ci++) {
        const float* ip  = inb + ci * HIN * WIN;
        const float* wci = wt + ((size_t)co0 * CIN + ci) * 16;
#pragma unroll
        for (int ky = 0; ky < 4; ky++) {
            int iy = oy * 2 - 1 + ky;
            if (iy < 0 || iy >= HIN) continue;
            const float* row = ip + iy * WIN;
            float w[WINW];
            w[0] = (ixb >= 0) ? row[ixb] : 0.f;
#pragma unroll
            for (int m = 0; m < 4; m++) {
                float4 v = *(const float4*)(row + ixb + 1 + 4 * m);
                w[1 + 4 * m] = v.x; w[2 + 4 * m] = v.y;
                w[3 + 4 * m] = v.z; w[4 + 4 * m] = v.w;
            }
            w[17] = (ixb + 17 < WIN) ? row[ixb + 17] : 0.f;
#pragma unroll
            for (int c = 0; c < TCO; c++) {
                float4 wv = *(const float4*)(wci + c * CIN * 16 + ky * 4);
                float wk[4] = {wv.x, wv.y, wv.z, wv.w};
#pragma unroll
                for (int kx = 0; kx < 4; kx++)
#pragma unroll
                    for (int j = 0; j < TX; j++)
                        acc[c][j] = fmaf(w[j * 2 + kx], wk[kx], acc[c][j]);
            }
        }
    }

#pragma unroll
    for (int c = 0; c < TCO; c++) {
        size_t o = (((size_t)b * COUT + (co0 + c)) * HOUT + oy) * WOUT + ox0;
        float v[TX];
#pragma unroll
        for (int j = 0; j < TX; j++) {
            v[j] = acc[c][j];
            if (OUT_RELU) v[j] = fmaxf(v[j], 0.f);
        }
        *(float4*)(out + o)     = make_float4(v[0], v[1], v[2], v[3]);
        *(float4*)(out + o + 4) = make_float4(v[4], v[5], v[6], v[7]);
    }
}

// ---------------------------------------------------------------------------
// ConvTranspose2d(k=4,s=2,p=1) direct gather. TX=8.
// ---------------------------------------------------------------------------
template <int TCO, int CIN, int HIN, int WIN, int COUT, int HOUT, int WOUT,
          bool IN_RELU, bool OUT_RELU, bool VEC_ST>
__global__ __launch_bounds__(128)
void deconv_k(const float* __restrict__ in, const float* __restrict__ wt,
              const float* __restrict__ bs, float* __restrict__ out)
{
    constexpr int TX = 8;
    static_assert((HOUT * WOUT / TX) % 128 == 0, "tiles fill blocks");

    int tid = blockIdx.x * 128 + threadIdx.x;
    int ox0 = (tid * TX) % WOUT;
    int oy  = (tid * TX) / WOUT;
    int co0 = blockIdx.y * TCO;
    int b   = blockIdx.z;

    float acc[TCO][TX];
#pragma unroll
    for (int c = 0; c < TCO; c++) {
        float bv = __ldg(bs + co0 + c);
#pragma unroll
        for (int j = 0; j < TX; j++) acc[c][j] = bv;
    }

    const int ixb = ox0 / 2 - 1;
    const int oyp = oy & 1;
    const float* inb = in + (size_t)b * CIN * HIN * WIN;

#pragma unroll 2
    for (int ci = 0; ci < CIN; ci++) {
        const float* ip  = inb + ci * HIN * WIN;
        const float* wci = wt + ((size_t)co0 * CIN + ci) * 16;
#pragma unroll
        for (int t = 0; t < 2; t++) {
            int ky = oyp + 2 * t;
            int iy = (oy - 2 + ky) >> 1;
            if (iy < 0 || iy >= HIN) continue;
            const float* row = ip + iy * WIN;
            float u[6];
            u[0] = (ixb >= 0) ? row[ixb] : 0.f;
            float4 v = *(const float4*)(row + ixb + 1);
            u[1] = v.x; u[2] = v.y; u[3] = v.z; u[4] = v.w;
            u[5] = (ixb + 5 < WIN) ? row[ixb + 5] : 0.f;
            if (IN_RELU) {
#pragma unroll
                for (int m = 0; m < 6; m++) u[m] = fmaxf(u[m], 0.f);
            }
#pragma unroll
            for (int c = 0; c < TCO; c++) {
                float4 wv = *(const float4*)(wci + c * CIN * 16 + ky * 4);
#pragma unroll
                for (int j = 0; j < TX; j++) {
                    const int jo = j & 1;
                    const int sh = (j + 1) >> 1;
                    float wl = jo ? wv.y : wv.x;
                    float wh = jo ? wv.w : wv.z;
                    acc[c][j] = fmaf(u[sh],     wl, acc[c][j]);
                    acc[c][j] = fmaf(u[sh + 1], wh, acc[c][j]);
                }
            }
        }
    }

#pragma unroll
    for (int c = 0; c < TCO; c++) {
        size_t o = (((size_t)b * COUT + (co0 + c)) * HOUT + oy) * WOUT + ox0;
        float v[TX];
#pragma unroll
        for (int j = 0; j < TX; j++) {
            v[j] = acc[c][j];
            if (OUT_RELU) v[j] = fmaxf(v[j], 0.f);
        }
        if constexpr (VEC_ST) {
            *(float4*)(out + o)     = make_float4(v[0], v[1], v[2], v[3]);
            *(float4*)(out + o + 4) = make_float4(v[4], v[5], v[6], v[7]);
        } else {
#pragma unroll
            for (int j = 0; j < TX; j++) out[o + j] = v[j];
        }
    }
}

// ---------------------------------------------------------------------------
// VQ
// ---------------------------------------------------------------------------
__global__ void cnorm_kernel(const float* __restrict__ cb, float* __restrict__ cn)
{
    int k = blockIdx.x * blockDim.x + threadIdx.x;
    if (k >= 512) return;
    const float* c = cb + k * 64;
    float s = 0.f;
#pragma unroll
    for (int d = 0; d < 64; d++) s = fmaf(c[d], c[d], s);
    cn[k] = s;
}

__global__ __launch_bounds__(128)
void vq_kernel(const float* __restrict__ z, const float* __restrict__ cb,
               const float* __restrict__ cn, int* __restrict__ idx,
               float* __restrict__ q, float* __restrict__ err)
{
    int p = blockIdx.x * 128 + threadIdx.x;  // 0..32767
    if (p >= 32768) return;
    int b = p >> 10, s = p & 1023;
    const float* zp = z + (size_t)b * 64 * 1024 + s;
    float zv[64];
#pragma unroll
    for (int d = 0; d < 64; d++) zv[d] = zp[d * 1024];

    float best = 3.4e38f;
    int bk = 0;
#pragma unroll 1
    for (int k = 0; k < 512; k++) {
        const float4* c4 = (const float4*)(cb + (size_t)k * 64);
        float d0 = 0.f, d1 = 0.f, d2 = 0.f, d3 = 0.f;
#pragma unroll
        for (int m = 0; m < 16; m++) {
            float4 cv = __ldg(c4 + m);
            d0 = fmaf(zv[4 * m],     cv.x, d0);
            d1 = fmaf(zv[4 * m + 1], cv.y, d1);
            d2 = fmaf(zv[4 * m + 2], cv.z, d2);
            d3 = fmaf(zv[4 * m + 3], cv.w, d3);
        }
        float dist = __ldg(cn + k) - 2.f * ((d0 + d1) + (d2 + d3));
        if (dist < best) { best = dist; bk = k; }   // strict <: first-min (jnp.argmin)
    }
    idx[p] = bk;
    float* qp = q + (size_t)b * 64 * 1024 + s;
    const float* c = cb + (size_t)bk * 64;
    float e = 0.f;
#pragma unroll
    for (int d = 0; d < 64; d++) {
        float cd = __ldg(c + d);
        qp[d * 1024] = cd;
        float df = zv[d] - cd;
        e = fmaf(df, df, e);
    }
    err[p] = e;
}

// hist + loss + perplexity in one block
__global__ __launch_bounds__(512)
void stats_kernel(const int* __restrict__ idx, const float* __restrict__ err,
                  float* __restrict__ out0, float* __restrict__ outp)
{
    __shared__ int   h[512];
    __shared__ float sm[512];
    int t = threadIdx.x;
    h[t] = 0;
    float s = 0.f;
    __syncthreads();
    for (int i = t; i < 32768; i += 512) {
        atomicAdd(&h[idx[i]], 1);
        s += err[i];
    }
    sm[t] = s;
    __syncthreads();
    for (int off = 256; off > 0; off >>= 1) {
        if (t < off) sm[t] += sm[t + off];
        __syncthreads();
    }
    if (t == 0) out0[0] = 1.25f * sm[0] / 2097152.0f;   // (1+beta)*mse
    __syncthreads();
    float pr = (float)h[t] * (1.0f / 32768.0f);
    sm[t] = pr * logf(pr + 1e-10f);
    __syncthreads();
    for (int off = 256; off > 0; off >>= 1) {
        if (t < off) sm[t] += sm[t + off];
        __syncthreads();
    }
    if (t == 0) outp[0] = expf(-sm[0]);
}

// ---------------------------------------------------------------------------
// Launch
// ---------------------------------------------------------------------------
extern "C" void kernel_launch(void* const* d_in, const int* in_sizes, int n_in,
                              void* d_out, int out_size)
{
    const float* x     = (const float*)d_in[0];
    const float* e_w1  = (const float*)d_in[1];
    const float* e_b1  = (const float*)d_in[2];
    const float* e_w2  = (const float*)d_in[3];
    const float* e_b2  = (const float*)d_in[4];
    const float* e_w3  = (const float*)d_in[5];
    const float* e_b3  = (const float*)d_in[6];
    const float* e_r1a = (const float*)d_in[7];
    const float* e_r1b = (const float*)d_in[8];
    const float* e_r2a = (const float*)d_in[9];
    const float* e_r2b = (const float*)d_in[10];
    const float* pre_w = (const float*)d_in[11];
    const float* pre_b = (const float*)d_in[12];
    const float* cb    = (const float*)d_in[13];
    const float* d_w1  = (const float*)d_in[14];
    const float* d_b1  = (const float*)d_in[15];
    const float* d_r1a = (const float*)d_in[16];
    const float* d_r1b = (const float*)d_in[17];
    const float* d_r2a = (const float*)d_in[18];
    const float* d_r2b = (const float*)d_in[19];
    const float* dt_w1 = (const float*)d_in[20];
    const float* dt_b1 = (const float*)d_in[21];
    const float* dt_w2 = (const float*)d_in[22];
    const float* dt_b2 = (const float*)d_in[23];
    float* out = (float*)d_out;

    float *A, *Bf, *Cc, *T, *Z, *Q, *G, *cn, *err, *W;
    int *idx;
    cudaGetSymbolAddress((void**)&A,    g_A);
    cudaGetSymbolAddress((void**)&Bf,   g_B);
    cudaGetSymbolAddress((void**)&Cc,   g_C);
    cudaGetSymbolAddress((void**)&T,    g_T);
    cudaGetSymbolAddress((void**)&Z,    g_Z);
    cudaGetSymbolAddress((void**)&Q,    g_Q);
    cudaGetSymbolAddress((void**)&G,    g_G);
    cudaGetSymbolAddress((void**)&cn,   g_cnorm);
    cudaGetSymbolAddress((void**)&err,  g_err);
    cudaGetSymbolAddress((void**)&idx,  g_idx);
    cudaGetSymbolAddress((void**)&W,    g_W);

    // repacked weight slots
    float* W_e3   = W + 0;        // 128x128x9 -> 147456
    float* W_er1a = W + 147456;   // 32x128x9  -> 36864
    float* W_er2a = W + 184320;
    float* W_dr1a = W + 221184;
    float* W_dr2a = W + 258048;
    float* W_d1   = W + 294912;   // 128x64x9  -> 73728
    float* W_er1b = W + 368640;   // 128x32    -> 4096
    float* W_er2b = W + 372736;
    float* W_dr1b = W + 376832;
    float* W_dr2b = W + 380928;
    float* W_pre  = W + 385024;   // 64x128    -> 8192

    // ---- weight repack (runs every call; deterministic) ----
    repack3_k<<<(128 * 128 * 9 + 255) / 256, 256>>>(e_w3,  W_e3,   128, 128);
    repack3_k<<<(32 * 128 * 9 + 255) / 256, 256>>>(e_r1a, W_er1a, 32, 128);
    repack3_k<<<(32 * 128 * 9 + 255) / 256, 256>>>(e_r2a, W_er2a, 32, 128);
    repack3_k<<<(32 * 128 * 9 + 255) / 256, 256>>>(d_r1a, W_dr1a, 32, 128);
    repack3_k<<<(32 * 128 * 9 + 255) / 256, 256>>>(d_r2a, W_dr2a, 32, 128);
    repack3_k<<<(128 * 64 * 9 + 255) / 256, 256>>>(d_w1,  W_d1,   128, 64);
    repack1_k<<<(128 * 32 + 255) / 256, 256>>>(e_r1b, W_er1b, 128, 32);
    repack1_k<<<(128 * 32 + 255) / 256, 256>>>(e_r2b, W_er2b, 128, 32);
    repack1_k<<<(128 * 32 + 255) / 256, 256>>>(d_r1b, W_dr1b, 128, 32);
    repack1_k<<<(128 * 32 + 255) / 256, 256>>>(d_r2b, W_dr2b, 128, 32);
    repack1_k<<<(64 * 128 + 255) / 256, 256>>>(pre_w, W_pre,  64, 128);

    dim3 blk(128);

    // ---- encoder ----
    conv4_k<4, 3,128,128, 64,64,64, true>
        <<<dim3(4, 16, 32), blk>>>(x, e_w1, e_b1, A);
    conv4_k<4, 64,64,64, 128,32,32, true>
        <<<dim3(1, 32, 32), blk>>>(A, e_w2, e_b2, Bf);
    conv3r_k<128, 128, false, true>
        <<<dim3(1, 32, 32), blk>>>(Bf, W_e3, e_b3, Cc);
    // res stack (x2), in-place on Cc
    conv3r_k<128, 32, true, false><<<dim3(1, 8, 32), blk>>>(Cc, W_er1a, nullptr, T);
    conv1r_k<32, 128, false, true><<<dim3(1, 32, 32), blk>>>(T, W_er1b, nullptr, Cc, Cc);
    conv3r_k<128, 32, true, false><<<dim3(1, 8, 32), blk>>>(Cc, W_er2a, nullptr, T);
    conv1r_k<32, 128, false, true><<<dim3(1, 32, 32), blk>>>(T, W_er2b, nullptr, Cc, Cc);
    // pre-VQ 1x1 (relu-in = final stack relu)
    conv1r_k<128, 64, true, false><<<dim3(1, 16, 32), blk>>>(Cc, W_pre, pre_b, Z, nullptr);

    // ---- vector quantizer ----
    cnorm_kernel<<<2, 256>>>(cb, cn);
    vq_kernel<<<256, 128>>>(Z, cb, cn, idx, Q, err);
    stats_kernel<<<1, 512>>>(idx, err, out, out + (out_size - 1));

    // ---- decoder ----
    conv3r_k<64, 128, false, true>
        <<<dim3(1, 32, 32), blk>>>(Q, W_d1, d_b1, G);
    conv3r_k<128, 32, true, false><<<dim3(1, 8, 32), blk>>>(G, W_dr1a, nullptr, T);
    conv1r_k<32, 128, false, true><<<dim3(1, 32, 32), blk>>>(T, W_dr1b, nullptr, G, G);
    conv3r_k<128, 32, true, false><<<dim3(1, 8, 32), blk>>>(G, W_dr2a, nullptr, T);
    conv1r_k<32, 128, false, true><<<dim3(1, 32, 32), blk>>>(T, W_dr2b, nullptr, G, G);
    // dt1: G -> A [32,64,64,64], relu-in + relu-out
    deconv_k<4, 128,32,32, 64,64,64, true,true,true>
        <<<dim3(4, 16, 32), blk>>>(G, dt_w1, dt_b1, A);
    // dt2: A -> x_recon into d_out+1 (misaligned base -> scalar stores)
    deconv_k<3, 64,64,64, 3,128,128, false,false,false>
        <<<dim3(16, 1, 32), blk>>>(A, dt_w2, dt_b2, out + 1);
}

// round 5
// speedup vs baseline: 1.1154x; 1.1154x over previous
#include <cuda_runtime.h>
#include <math.h>

// ---------------------------------------------------------------------------
// VQ-VAE forward, fp32. Round 5: R2 base + deterministic split-K (split-ci)
// for the latency-bound 32x32 convs; partial sums fused into consumers.
// Output layout: [loss, x_recon(1572864), perplexity]
// ---------------------------------------------------------------------------

// Scratch (device globals; no allocation allowed)
__device__ float g_A[32u * 64 * 64 * 64];    // e1 out / dt1 out / split partials
__device__ float g_B[32u * 128 * 32 * 32];   // e2 out
__device__ float g_C[32u * 128 * 32 * 32];   // e3 out + encoder res stack (also e2 partial)
__device__ float g_Z[32u * 64 * 32 * 32];    // pre-VQ z
__device__ float g_Q[32u * 64 * 32 * 32];    // quantized q
__device__ float g_G[32u * 128 * 32 * 32];   // decoder stack (also e2 partial)
__device__ int   g_idx[32768];
__device__ float g_cnorm[512];
__device__ float g_err[32768];

// ---------------------------------------------------------------------------
// Generic direct conv (R2, proven): TX=8 outputs along x, TCO channels.
// Used for e1 (k4s2) and pre (1x1).
// ---------------------------------------------------------------------------
template <int KH, int KW, int S, int P, int TCO,
          int CIN, int HIN, int WIN, int COUT, int HOUT, int WOUT,
          bool IN_RELU, bool OUT_RELU, bool BIAS, bool ADD>
__global__ __launch_bounds__(128)
void conv_k(const float* __restrict__ in, const float* __restrict__ wt,
            const float* __restrict__ bs, float* __restrict__ out,
            const float* __restrict__ res)
{
    constexpr int TX   = 8;
    constexpr int WINW = (TX - 1) * S + KW;
    static_assert((HOUT * WOUT / TX) % 128 == 0, "tiles fill blocks");

    int tid = blockIdx.x * 128 + threadIdx.x;
    int ox0 = (tid * TX) % WOUT;
    int oy  = (tid * TX) / WOUT;
    int co0 = blockIdx.y * TCO;
    int b   = blockIdx.z;

    float acc[TCO][TX];
#pragma unroll
    for (int c = 0; c < TCO; c++) {
        float bv = BIAS ? __ldg(bs + co0 + c) : 0.f;
#pragma unroll
        for (int j = 0; j < TX; j++) acc[c][j] = bv;
    }

    const float* inb = in + (size_t)b * CIN * HIN * WIN;
    const int ixb = ox0 * S - P;

#pragma unroll 1
    for (int ci = 0; ci < CIN; ci++) {
        const float* ip  = inb + ci * HIN * WIN;
        const float* wci = wt + ((size_t)co0 * CIN + ci) * KH * KW;
#pragma unroll
        for (int ky = 0; ky < KH; ky++) {
            int iy = oy * S - P + ky;
            if (P > 0 && (iy < 0 || iy >= HIN)) continue;
            const float* row = ip + iy * WIN;
            float w[WINW];
            if constexpr (P == 0) {
                float4 v0 = *(const float4*)(row + ox0);
                float4 v1 = *(const float4*)(row + ox0 + 4);
                w[0] = v0.x; w[1] = v0.y; w[2] = v0.z; w[3] = v0.w;
                w[4] = v1.x; w[5] = v1.y; w[6] = v1.z; w[7] = v1.w;
            } else {
                w[0] = (ixb >= 0) ? row[ixb] : 0.f;
#pragma unroll
                for (int m = 0; m < (WINW - 2) / 4; m++) {
                    float4 v = *(const float4*)(row + ixb + 1 + 4 * m);
                    w[1 + 4 * m] = v.x; w[2 + 4 * m] = v.y;
                    w[3 + 4 * m] = v.z; w[4 + 4 * m] = v.w;
                }
                w[WINW - 1] = (ixb + WINW - 1 < WIN) ? row[ixb + WINW - 1] : 0.f;
            }
            if (IN_RELU) {
#pragma unroll
                for (int m = 0; m < WINW; m++) w[m] = fmaxf(w[m], 0.f);
            }
#pragma unroll
            for (int c = 0; c < TCO; c++) {
                const float* wp = wci + c * CIN * KH * KW + ky * KW;
                if constexpr (KW == 4) {
                    float4 wv = *(const float4*)wp;
                    float wk[4] = {wv.x, wv.y, wv.z, wv.w};
#pragma unroll
                    for (int kx = 0; kx < 4; kx++)
#pragma unroll
                        for (int j = 0; j < TX; j++)
                            acc[c][j] = fmaf(w[j * S + kx], wk[kx], acc[c][j]);
                } else {
#pragma unroll
                    for (int kx = 0; kx < KW; kx++) {
                        float wv = __ldg(wp + kx);
#pragma unroll
                        for (int j = 0; j < TX; j++)
                            acc[c][j] = fmaf(w[j * S + kx], wv, acc[c][j]);
                    }
                }
            }
        }
    }

#pragma unroll
    for (int c = 0; c < TCO; c++) {
        size_t o = (((size_t)b * COUT + (co0 + c)) * HOUT + oy) * WOUT + ox0;
        float v[TX];
#pragma unroll
        for (int j = 0; j < TX; j++) v[j] = acc[c][j];
        if (ADD) {
            float4 r0 = *(const float4*)(res + o);
            float4 r1 = *(const float4*)(res + o + 4);
            v[0] += r0.x; v[1] += r0.y; v[2] += r0.z; v[3] += r0.w;
            v[4] += r1.x; v[5] += r1.y; v[6] += r1.z; v[7] += r1.w;
        }
        if (OUT_RELU) {
#pragma unroll
            for (int j = 0; j < TX; j++) v[j] = fmaxf(v[j], 0.f);
        }
        *(float4*)(out + o)     = make_float4(v[0], v[1], v[2], v[3]);
        *(float4*)(out + o + 4) = make_float4(v[4], v[5], v[6], v[7]);
    }
}

// ---------------------------------------------------------------------------
// Split-ci 3x3 s1 p1 conv on 32x32 maps. blockIdx.x = ci chunk.
// Writes partial sums: part[((b*NCH + chunk)*COUT + co)*1024 + sp]. No bias.
// ---------------------------------------------------------------------------
template <int CINC, int CIN_TOTAL, int COUT, int NCH, bool IN_RELU>
__global__ __launch_bounds__(128)
void conv3s_k(const float* __restrict__ in, const float* __restrict__ wt,
              float* __restrict__ part)
{
    const int t     = threadIdx.x;
    const int ox0   = (t * 8) & 31;
    const int oy    = t >> 2;
    const int chunk = blockIdx.x;
    const int co0   = blockIdx.y * 4;
    const int b     = blockIdx.z;
    const int ci0   = chunk * CINC;

    float acc[4][8];
#pragma unroll
    for (int c = 0; c < 4; c++)
#pragma unroll
        for (int j = 0; j < 8; j++) acc[c][j] = 0.f;

    const float* inb = in + (size_t)b * CIN_TOTAL * 1024 + ci0 * 1024;

#pragma unroll 1
    for (int ci = 0; ci < CINC; ci++) {
        const float* ip  = inb + ci * 1024;
        const float* wci = wt + ((size_t)co0 * CIN_TOTAL + ci0 + ci) * 9;
#pragma unroll
        for (int ky = 0; ky < 3; ky++) {
            int iy = oy - 1 + ky;
            if (iy < 0 || iy >= 32) continue;
            const float* row = ip + iy * 32;
            float w[10];
            w[0] = (ox0 > 0) ? row[ox0 - 1] : 0.f;
            float4 v0 = *(const float4*)(row + ox0);
            float4 v1 = *(const float4*)(row + ox0 + 4);
            w[1] = v0.x; w[2] = v0.y; w[3] = v0.z; w[4] = v0.w;
            w[5] = v1.x; w[6] = v1.y; w[7] = v1.z; w[8] = v1.w;
            w[9] = (ox0 < 24) ? row[ox0 + 8] : 0.f;
            if (IN_RELU) {
#pragma unroll
                for (int m = 0; m < 10; m++) w[m] = fmaxf(w[m], 0.f);
            }
#pragma unroll
            for (int c = 0; c < 4; c++) {
                const float* wp = wci + c * CIN_TOTAL * 9 + ky * 3;
                float w0 = __ldg(wp), w1 = __ldg(wp + 1), w2 = __ldg(wp + 2);
#pragma unroll
                for (int j = 0; j < 8; j++) {
                    acc[c][j] = fmaf(w[j],     w0, acc[c][j]);
                    acc[c][j] = fmaf(w[j + 1], w1, acc[c][j]);
                    acc[c][j] = fmaf(w[j + 2], w2, acc[c][j]);
                }
            }
        }
    }

#pragma unroll
    for (int c = 0; c < 4; c++) {
        size_t o = (((size_t)(b * NCH + chunk) * COUT + (co0 + c)) * 32 + oy) * 32 + ox0;
        *(float4*)(part + o)     = make_float4(acc[c][0], acc[c][1], acc[c][2], acc[c][3]);
        *(float4*)(part + o + 4) = make_float4(acc[c][4], acc[c][5], acc[c][6], acc[c][7]);
    }
}

// ---------------------------------------------------------------------------
// Split-ci k4 s2 p1 conv (e2): in 64x64 -> out 32x32. chunk selects CINC ci
// and destination buffer (p0 / p1). No bias/relu (applied in combine).
// ---------------------------------------------------------------------------
template <int CINC, int CIN_TOTAL, int COUT>
__global__ __launch_bounds__(128)
void conv4s_k(const float* __restrict__ in, const float* __restrict__ wt,
              float* __restrict__ p0, float* __restrict__ p1)
{
    const int t     = threadIdx.x;
    const int ox0   = (t * 8) & 31;
    const int oy    = t >> 2;
    const int chunk = blockIdx.x;
    const int co0   = blockIdx.y * 4;
    const int b     = blockIdx.z;
    const int ci0   = chunk * CINC;

    float acc[4][8];
#pragma unroll
    for (int c = 0; c < 4; c++)
#pragma unroll
        for (int j = 0; j < 8; j++) acc[c][j] = 0.f;

    const float* inb = in + (size_t)b * CIN_TOTAL * 4096 + ci0 * 4096;
    const int ixb = ox0 * 2 - 1;

#pragma unroll 1
    for (int ci = 0; ci < CINC; ci++) {
        const float* ip  = inb + ci * 4096;
        const float* wci = wt + ((size_t)co0 * CIN_TOTAL + ci0 + ci) * 16;
#pragma unroll
        for (int ky = 0; ky < 4; ky++) {
            int iy = oy * 2 - 1 + ky;
            if (iy < 0 || iy >= 64) continue;
            const float* row = ip + iy * 64;
            float w[18];
            w[0] = (ixb >= 0) ? row[ixb] : 0.f;
#pragma unroll
            for (int m = 0; m < 4; m++) {
                float4 v = *(const float4*)(row + ixb + 1 + 4 * m);
                w[1 + 4 * m] = v.x; w[2 + 4 * m] = v.y;
                w[3 + 4 * m] = v.z; w[4 + 4 * m] = v.w;
            }
            w[17] = (ixb + 17 < 64) ? row[ixb + 17] : 0.f;
#pragma unroll
            for (int c = 0; c < 4; c++) {
                float4 wv = *(const float4*)(wci + c * CIN_TOTAL * 16 + ky * 4);
                float wk[4] = {wv.x, wv.y, wv.z, wv.w};
#pragma unroll
                for (int kx = 0; kx < 4; kx++)
#pragma unroll
                    for (int j = 0; j < 8; j++)
                        acc[c][j] = fmaf(w[j * 2 + kx], wk[kx], acc[c][j]);
            }
        }
    }

    float* dst = (chunk == 0) ? p0 : p1;
#pragma unroll
    for (int c = 0; c < 4; c++) {
        size_t o = (((size_t)b * COUT + (co0 + c)) * 32 + oy) * 32 + ox0;
        *(float4*)(dst + o)     = make_float4(acc[c][0], acc[c][1], acc[c][2], acc[c][3]);
        *(float4*)(dst + o + 4) = make_float4(acc[c][4], acc[c][5], acc[c][6], acc[c][7]);
    }
}

// ---------------------------------------------------------------------------
// Combine 2 partials (+bias, optional relu). src index = dst index + b*bstr
// per buffer (bstr=COUT*1024 for interleaved-in-A layout, 0 for flat buffers).
// ---------------------------------------------------------------------------
template <int COUT, bool RELU>
__global__ __launch_bounds__(256)
void comb_k(const float* __restrict__ p0, const float* __restrict__ p1,
            const float* __restrict__ bs, float* __restrict__ dst, int bstr)
{
    int i4 = blockIdx.x * 256 + threadIdx.x;
    if (i4 >= 32 * COUT * 256) return;
    size_t i = (size_t)i4 * 4;
    int b  = i4 >> 8;         // i / 1024 ...
    int co = b % COUT;        // (i/1024) % COUT
    b = b / COUT;             // image
    size_t s = i + (size_t)b * bstr;
    float4 a0 = *(const float4*)(p0 + s);
    float4 a1 = *(const float4*)(p1 + s);
    float bv = __ldg(bs + co);
    float v0 = a0.x + a1.x + bv, v1 = a0.y + a1.y + bv;
    float v2 = a0.z + a1.z + bv, v3 = a0.w + a1.w + bv;
    if (RELU) {
        v0 = fmaxf(v0, 0.f); v1 = fmaxf(v1, 0.f);
        v2 = fmaxf(v2, 0.f); v3 = fmaxf(v3, 0.f);
    }
    *(float4*)(dst + i) = make_float4(v0, v1, v2, v3);
}

// ---------------------------------------------------------------------------
// Fused: sum 4 res3x3 partials -> relu -> 1x1 (32->128) -> + residual -> out.
// part layout: ((b*4 + chunk)*32 + ci)*1024 + sp.
// ---------------------------------------------------------------------------
__global__ __launch_bounds__(128)
void conv1r4_k(const float* __restrict__ part, const float* __restrict__ wt,
               const float* __restrict__ res, float* __restrict__ out)
{
    const int t   = threadIdx.x;
    const int ox0 = (t * 8) & 31;
    const int oy  = t >> 2;
    const int co0 = blockIdx.y * 4;
    const int b   = blockIdx.z;

    float acc[4][8];
#pragma unroll
    for (int c = 0; c < 4; c++)
#pragma unroll
        for (int j = 0; j < 8; j++) acc[c][j] = 0.f;

    const float* pb = part + (size_t)(b * 4) * 32 * 1024 + oy * 32 + ox0;

#pragma unroll 1
    for (int ci = 0; ci < 32; ci++) {
        const float* p = pb + ci * 1024;
        float w[8] = {0, 0, 0, 0, 0, 0, 0, 0};
#pragma unroll
        for (int ch = 0; ch < 4; ch++) {
            const float* pc = p + ch * 32 * 1024;
            float4 v0 = *(const float4*)pc;
            float4 v1 = *(const float4*)(pc + 4);
            w[0] += v0.x; w[1] += v0.y; w[2] += v0.z; w[3] += v0.w;
            w[4] += v1.x; w[5] += v1.y; w[6] += v1.z; w[7] += v1.w;
        }
#pragma unroll
        for (int m = 0; m < 8; m++) w[m] = fmaxf(w[m], 0.f);   // relu
        float wv0 = __ldg(wt + (co0 + 0) * 32 + ci);
        float wv1 = __ldg(wt + (co0 + 1) * 32 + ci);
        float wv2 = __ldg(wt + (co0 + 2) * 32 + ci);
        float wv3 = __ldg(wt + (co0 + 3) * 32 + ci);
#pragma unroll
        for (int j = 0; j < 8; j++) {
            acc[0][j] = fmaf(w[j], wv0, acc[0][j]);
            acc[1][j] = fmaf(w[j], wv1, acc[1][j]);
            acc[2][j] = fmaf(w[j], wv2, acc[2][j]);
            acc[3][j] = fmaf(w[j], wv3, acc[3][j]);
        }
    }

#pragma unroll
    for (int c = 0; c < 4; c++) {
        size_t o = (((size_t)b * 128 + (co0 + c)) * 32 + oy) * 32 + ox0;
        float4 r0 = *(const float4*)(res + o);
        float4 r1 = *(const float4*)(res + o + 4);
        *(float4*)(out + o) = make_float4(acc[c][0] + r0.x, acc[c][1] + r0.y,
                                          acc[c][2] + r0.z, acc[c][3] + r0.w);
        *(float4*)(out + o + 4) = make_float4(acc[c][4] + r1.x, acc[c][5] + r1.y,
                                              acc[c][6] + r1.z, acc[c][7] + r1.w);
    }
}

// ---------------------------------------------------------------------------
// ConvTranspose2d(k=4,s=2,p=1) direct gather (R2, proven).
// ---------------------------------------------------------------------------
template <int TCO, int CIN, int HIN, int WIN, int COUT, int HOUT, int WOUT,
          bool IN_RELU, bool OUT_RELU, bool VEC_ST>
__global__ __launch_bounds__(128)
void deconv_k(const float* __restrict__ in, const float* __restrict__ wt,
              const float* __restrict__ bs, float* __restrict__ out)
{
    constexpr int TX = 8;
    static_assert((HOUT * WOUT / TX) % 128 == 0, "tiles fill blocks");

    int tid = blockIdx.x * 128 + threadIdx.x;
    int ox0 = (tid * TX) % WOUT;
    int oy  = (tid * TX) / WOUT;
    int co0 = blockIdx.y * TCO;
    int b   = blockIdx.z;

    float acc[TCO][TX];
#pragma unroll
    for (int c = 0; c < TCO; c++) {
        float bv = __ldg(bs + co0 + c);
#pragma unroll
        for (int j = 0; j < TX; j++) acc[c][j] = bv;
    }

    const int ixb = ox0 / 2 - 1;
    const int oyp = oy & 1;
    const float* inb = in + (size_t)b * CIN * HIN * WIN;

#pragma unroll 1
    for (int ci = 0; ci < CIN; ci++) {
        const float* ip  = inb + ci * HIN * WIN;
        const float* wci = wt + ((size_t)co0 * CIN + ci) * 16;
#pragma unroll
        for (int t = 0; t < 2; t++) {
            int ky = oyp + 2 * t;
            int iy = (oy - 2 + ky) >> 1;
            if (iy < 0 || iy >= HIN) continue;
            const float* row = ip + iy * WIN;
            float u[6];
            u[0] = (ixb >= 0) ? row[ixb] : 0.f;
            float4 v = *(const float4*)(row + ixb + 1);
            u[1] = v.x; u[2] = v.y; u[3] = v.z; u[4] = v.w;
            u[5] = (ixb + 5 < WIN) ? row[ixb + 5] : 0.f;
            if (IN_RELU) {
#pragma unroll
                for (int m = 0; m < 6; m++) u[m] = fmaxf(u[m], 0.f);
            }
#pragma unroll
            for (int c = 0; c < TCO; c++) {
                float4 wv = *(const float4*)(wci + c * CIN * 16 + ky * 4);
#pragma unroll
                for (int j = 0; j < TX; j++) {
                    const int jo = j & 1;
                    const int sh = (j + 1) >> 1;
                    float wl = jo ? wv.y : wv.x;
                    float wh = jo ? wv.w : wv.z;
                    acc[c][j] = fmaf(u[sh],     wl, acc[c][j]);
                    acc[c][j] = fmaf(u[sh + 1], wh, acc[c][j]);
                }
            }
        }
    }

#pragma unroll
    for (int c = 0; c < TCO; c++) {
        size_t o = (((size_t)b * COUT + (co0 + c)) * HOUT + oy) * WOUT + ox0;
        float v[TX];
#pragma unroll
        for (int j = 0; j < TX; j++) {
            v[j] = acc[c][j];
            if (OUT_RELU) v[j] = fmaxf(v[j], 0.f);
        }
        if constexpr (VEC_ST) {
            *(float4*)(out + o)     = make_float4(v[0], v[1], v[2], v[3]);
            *(float4*)(out + o + 4) = make_float4(v[4], v[5], v[6], v[7]);
        } else {
#pragma unroll
            for (int j = 0; j < TX; j++) out[o + j] = v[j];
        }
    }
}

// ---------------------------------------------------------------------------
// VQ (R2, proven)
// ---------------------------------------------------------------------------
__global__ void cnorm_kernel(const float* __restrict__ cb, float* __restrict__ cn)
{
    int k = blockIdx.x * blockDim.x + threadIdx.x;
    if (k >= 512) return;
    const float* c = cb + k * 64;
    float s = 0.f;
#pragma unroll
    for (int d = 0; d < 64; d++) s = fmaf(c[d], c[d], s);
    cn[k] = s;
}

__global__ __launch_bounds__(256)
void vq_kernel(const float* __restrict__ z, const float* __restrict__ cb,
               const float* __restrict__ cn, int* __restrict__ idx,
               float* __restrict__ q, float* __restrict__ err)
{
    int p = blockIdx.x * blockDim.x + threadIdx.x;  // 0..32767
    if (p >= 32768) return;
    int b = p >> 10, s = p & 1023;
    const float* zp = z + (size_t)b * 64 * 1024 + s;
    float zv[64];
#pragma unroll
    for (int d = 0; d < 64; d++) zv[d] = zp[d * 1024];

    float best = 3.4e38f;
    int bk = 0;
#pragma unroll 1
    for (int k = 0; k < 512; k++) {
        const float4* c4 = (const float4*)(cb + (size_t)k * 64);
        float d0 = 0.f, d1 = 0.f, d2 = 0.f, d3 = 0.f;
#pragma unroll
        for (int m = 0; m < 16; m++) {
            float4 cv = __ldg(c4 + m);
            d0 = fmaf(zv[4 * m],     cv.x, d0);
            d1 = fmaf(zv[4 * m + 1], cv.y, d1);
            d2 = fmaf(zv[4 * m + 2], cv.z, d2);
            d3 = fmaf(zv[4 * m + 3], cv.w, d3);
        }
        float dist = __ldg(cn + k) - 2.f * ((d0 + d1) + (d2 + d3));
        if (dist < best) { best = dist; bk = k; }   // strict <: first-min (jnp.argmin)
    }
    idx[p] = bk;
    float* qp = q + (size_t)b * 64 * 1024 + s;
    const float* c = cb + (size_t)bk * 64;
    float e = 0.f;
#pragma unroll
    for (int d = 0; d < 64; d++) {
        float cd = __ldg(c + d);
        qp[d * 1024] = cd;
        float df = zv[d] - cd;
        e = fmaf(df, df, e);
    }
    err[p] = e;
}

__global__ __launch_bounds__(512)
void stats_kernel(const int* __restrict__ idx, const float* __restrict__ err,
                  float* __restrict__ out0, float* __restrict__ outp)
{
    __shared__ int   h[512];
    __shared__ float sm[512];
    int t = threadIdx.x;
    h[t] = 0;
    float s = 0.f;
    __syncthreads();
    for (int i = t; i < 32768; i += 512) {
        atomicAdd(&h[idx[i]], 1);
        s += err[i];
    }
    sm[t] = s;
    __syncthreads();
    for (int off = 256; off > 0; off >>= 1) {
        if (t < off) sm[t] += sm[t + off];
        __syncthreads();
    }
    if (t == 0) out0[0] = 1.25f * sm[0] / 2097152.0f;   // (1+beta)*mse
    __syncthreads();
    float pr = (float)h[t] * (1.0f / 32768.0f);
    sm[t] = pr * logf(pr + 1e-10f);
    __syncthreads();
    for (int off = 256; off > 0; off >>= 1) {
        if (t < off) sm[t] += sm[t + off];
        __syncthreads();
    }
    if (t == 0) outp[0] = expf(-sm[0]);
}

// ---------------------------------------------------------------------------
// Launch
// ---------------------------------------------------------------------------
extern "C" void kernel_launch(void* const* d_in, const int* in_sizes, int n_in,
                              void* d_out, int out_size)
{
    const float* x     = (const float*)d_in[0];
    const float* e_w1  = (const float*)d_in[1];
    const float* e_b1  = (const float*)d_in[2];
    const float* e_w2  = (const float*)d_in[3];
    const float* e_b2  = (const float*)d_in[4];
    const float* e_w3  = (const float*)d_in[5];
    const float* e_b3  = (const float*)d_in[6];
    const float* e_r1a = (const float*)d_in[7];
    const float* e_r1b = (const float*)d_in[8];
    const float* e_r2a = (const float*)d_in[9];
    const float* e_r2b = (const float*)d_in[10];
    const float* pre_w = (const float*)d_in[11];
    const float* pre_b = (const float*)d_in[12];
    const float* cb    = (const float*)d_in[13];
    const float* d_w1  = (const float*)d_in[14];
    const float* d_b1  = (const float*)d_in[15];
    const float* d_r1a = (const float*)d_in[16];
    const float* d_r1b = (const float*)d_in[17];
    const float* d_r2a = (const float*)d_in[18];
    const float* d_r2b = (const float*)d_in[19];
    const float* dt_w1 = (const float*)d_in[20];
    const float* dt_b1 = (const float*)d_in[21];
    const float* dt_w2 = (const float*)d_in[22];
    const float* dt_b2 = (const float*)d_in[23];
    float* out = (float*)d_out;

    float *A, *Bf, *Cc, *Z, *Q, *G, *cn, *err;
    int *idx;
    cudaGetSymbolAddress((void**)&A,    g_A);
    cudaGetSymbolAddress((void**)&Bf,   g_B);
    cudaGetSymbolAddress((void**)&Cc,   g_C);
    cudaGetSymbolAddress((void**)&Z,    g_Z);
    cudaGetSymbolAddress((void**)&Q,    g_Q);
    cudaGetSymbolAddress((void**)&G,    g_G);
    cudaGetSymbolAddress((void**)&cn,   g_cnorm);
    cudaGetSymbolAddress((void**)&err,  g_err);
    cudaGetSymbolAddress((void**)&idx,  g_idx);

    dim3 blk(128);
    const int CB128 = 32 * 128 * 256;   // float4 count for COUT=128 combine

    // ---- encoder ----
    // e1: [32,3,128,128] -> A [32,64,64,64], k4 s2 p1, relu (CIN=3, no split)
    conv_k<4,4,2,1,4, 3,128,128, 64,64,64, false,true,true,false>
        <<<dim3(4, 16, 32), blk>>>(x, e_w1, e_b1, A, nullptr);
    // e2 split-2: A -> partials (G, Cc); combine -> Bf (relu+bias)
    conv4s_k<32, 64, 128><<<dim3(2, 32, 32), blk>>>(A, e_w2, G, Cc);
    comb_k<128, true><<<(CB128 + 255) / 256, 256>>>(G, Cc, e_b2, Bf, 0);
    // e3 split-2: Bf -> partials in A; combine -> Cc (bias, no relu)
    conv3s_k<64, 128, 128, 2, false><<<dim3(2, 32, 32), blk>>>(Bf, e_w3, A);
    comb_k<128, false><<<(CB128 + 255) / 256, 256>>>(A, A + 128 * 1024, e_b3, Cc,
                                                     128 * 1024);
    // encoder res stack (x2): split-4 3x3 -> A partials; fused 1x1+residual
    conv3s_k<32, 128, 32, 4, true><<<dim3(4, 8, 32), blk>>>(Cc, e_r1a, A);
    conv1r4_k<<<dim3(1, 32, 32), blk>>>(A, e_r1b, Cc, Cc);
    conv3s_k<32, 128, 32, 4, true><<<dim3(4, 8, 32), blk>>>(Cc, e_r2a, A);
    conv1r4_k<<<dim3(1, 32, 32), blk>>>(A, e_r2b, Cc, Cc);
    // pre-VQ 1x1 (relu-in = final stack relu): Cc -> Z
    conv_k<1,1,1,0,4, 128,32,32, 64,32,32, true,false,true,false>
        <<<dim3(1, 16, 32), blk>>>(Cc, pre_w, pre_b, Z, nullptr);

    // ---- vector quantizer ----
    cnorm_kernel<<<2, 256>>>(cb, cn);
    vq_kernel<<<128, 256>>>(Z, cb, cn, idx, Q, err);
    stats_kernel<<<1, 512>>>(idx, err, out, out + (out_size - 1));

    // ---- decoder ----
    // d1 split-2: Q -> partials in A; combine -> G (bias, no relu)
    conv3s_k<32, 64, 128, 2, false><<<dim3(2, 32, 32), blk>>>(Q, d_w1, A);
    comb_k<128, false><<<(CB128 + 255) / 256, 256>>>(A, A + 128 * 1024, d_b1, G,
                                                     128 * 1024);
    // decoder res stack (x2)
    conv3s_k<32, 128, 32, 4, true><<<dim3(4, 8, 32), blk>>>(G, d_r1a, A);
    conv1r4_k<<<dim3(1, 32, 32), blk>>>(A, d_r1b, G, G);
    conv3s_k<32, 128, 32, 4, true><<<dim3(4, 8, 32), blk>>>(G, d_r2a, A);
    conv1r4_k<<<dim3(1, 32, 32), blk>>>(A, d_r2b, G, G);
    // dt1: G -> A [32,64,64,64], relu-in + relu-out
    deconv_k<4, 128,32,32, 64,64,64, true,true,true>
        <<<dim3(4, 16, 32), blk>>>(G, dt_w1, dt_b1, A);
    // dt2: A -> x_recon into d_out+1 (misaligned base -> scalar stores)
    deconv_k<3, 64,64,64, 3,128,128, false,false,false>
        <<<dim3(16, 1, 32), blk>>>(A, dt_w2, dt_b2, out + 1);
}

// round 6
// speedup vs baseline: 1.2097x; 1.0845x over previous
#include <cuda_runtime.h>
#include <math.h>

// ---------------------------------------------------------------------------
// VQ-VAE forward, fp32. Round 6: smem-staged 3x3 convs (input tiles + weights
// in shared memory, padded rows for conflict-free access); e3/d1 unsplit;
// res stack keeps split-4 + fused 1x1 combine. Rest identical to R5.
// Output layout: [loss, x_recon(1572864), perplexity]
// ---------------------------------------------------------------------------

// Scratch (device globals; no allocation allowed)
__device__ float g_A[32u * 64 * 64 * 64];    // e1 out / dt1 out / res partials
__device__ float g_B[32u * 128 * 32 * 32];   // e2 out
__device__ float g_C[32u * 128 * 32 * 32];   // e3 out + encoder res stack
__device__ float g_Z[32u * 64 * 32 * 32];    // pre-VQ z
__device__ float g_Q[32u * 64 * 32 * 32];    // quantized q
__device__ float g_G[32u * 128 * 32 * 32];   // decoder stack (also e2 partial)
__device__ int   g_idx[32768];
__device__ float g_cnorm[512];
__device__ float g_err[32768];

// ---------------------------------------------------------------------------
// Generic direct conv (R2, proven): used for e1 (k4s2) and pre (1x1).
// ---------------------------------------------------------------------------
template <int KH, int KW, int S, int P, int TCO,
          int CIN, int HIN, int WIN, int COUT, int HOUT, int WOUT,
          bool IN_RELU, bool OUT_RELU, bool BIAS, bool ADD>
__global__ __launch_bounds__(128)
void conv_k(const float* __restrict__ in, const float* __restrict__ wt,
            const float* __restrict__ bs, float* __restrict__ out,
            const float* __restrict__ res)
{
    constexpr int TX   = 8;
    constexpr int WINW = (TX - 1) * S + KW;
    static_assert((HOUT * WOUT / TX) % 128 == 0, "tiles fill blocks");

    int tid = blockIdx.x * 128 + threadIdx.x;
    int ox0 = (tid * TX) % WOUT;
    int oy  = (tid * TX) / WOUT;
    int co0 = blockIdx.y * TCO;
    int b   = blockIdx.z;

    float acc[TCO][TX];
#pragma unroll
    for (int c = 0; c < TCO; c++) {
        float bv = BIAS ? __ldg(bs + co0 + c) : 0.f;
#pragma unroll
        for (int j = 0; j < TX; j++) acc[c][j] = bv;
    }

    const float* inb = in + (size_t)b * CIN * HIN * WIN;
    const int ixb = ox0 * S - P;

#pragma unroll 1
    for (int ci = 0; ci < CIN; ci++) {
        const float* ip  = inb + ci * HIN * WIN;
        const float* wci = wt + ((size_t)co0 * CIN + ci) * KH * KW;
#pragma unroll
        for (int ky = 0; ky < KH; ky++) {
            int iy = oy * S - P + ky;
            if (P > 0 && (iy < 0 || iy >= HIN)) continue;
            const float* row = ip + iy * WIN;
            float w[WINW];
            if constexpr (P == 0) {
                float4 v0 = *(const float4*)(row + ox0);
                float4 v1 = *(const float4*)(row + ox0 + 4);
                w[0] = v0.x; w[1] = v0.y; w[2] = v0.z; w[3] = v0.w;
                w[4] = v1.x; w[5] = v1.y; w[6] = v1.z; w[7] = v1.w;
            } else {
                w[0] = (ixb >= 0) ? row[ixb] : 0.f;
#pragma unroll
                for (int m = 0; m < (WINW - 2) / 4; m++) {
                    float4 v = *(const float4*)(row + ixb + 1 + 4 * m);
                    w[1 + 4 * m] = v.x; w[2 + 4 * m] = v.y;
                    w[3 + 4 * m] = v.z; w[4 + 4 * m] = v.w;
                }
                w[WINW - 1] = (ixb + WINW - 1 < WIN) ? row[ixb + WINW - 1] : 0.f;
            }
            if (IN_RELU) {
#pragma unroll
                for (int m = 0; m < WINW; m++) w[m] = fmaxf(w[m], 0.f);
            }
#pragma unroll
            for (int c = 0; c < TCO; c++) {
                const float* wp = wci + c * CIN * KH * KW + ky * KW;
                if constexpr (KW == 4) {
                    float4 wv = *(const float4*)wp;
                    float wk[4] = {wv.x, wv.y, wv.z, wv.w};
#pragma unroll
                    for (int kx = 0; kx < 4; kx++)
#pragma unroll
                        for (int j = 0; j < TX; j++)
                            acc[c][j] = fmaf(w[j * S + kx], wk[kx], acc[c][j]);
                } else {
#pragma unroll
                    for (int kx = 0; kx < KW; kx++) {
                        float wv = __ldg(wp + kx);
#pragma unroll
                        for (int j = 0; j < TX; j++)
                            acc[c][j] = fmaf(w[j * S + kx], wv, acc[c][j]);
                    }
                }
            }
        }
    }

#pragma unroll
    for (int c = 0; c < TCO; c++) {
        size_t o = (((size_t)b * COUT + (co0 + c)) * HOUT + oy) * WOUT + ox0;
        float v[TX];
#pragma unroll
        for (int j = 0; j < TX; j++) v[j] = acc[c][j];
        if (ADD) {
            float4 r0 = *(const float4*)(res + o);
            float4 r1 = *(const float4*)(res + o + 4);
            v[0] += r0.x; v[1] += r0.y; v[2] += r0.z; v[3] += r0.w;
            v[4] += r1.x; v[5] += r1.y; v[6] += r1.z; v[7] += r1.w;
        }
        if (OUT_RELU) {
#pragma unroll
            for (int j = 0; j < TX; j++) v[j] = fmaxf(v[j], 0.f);
        }
        *(float4*)(out + o)     = make_float4(v[0], v[1], v[2], v[3]);
        *(float4*)(out + o + 4) = make_float4(v[4], v[5], v[6], v[7]);
    }
}

// ---------------------------------------------------------------------------
// Smem-staged 3x3 s1 p1 conv on 32x32 maps. Input channels staged 4 at a
// time into padded (36-float) rows; all block weights staged once.
// NCH==1: writes final output (+bias). NCH>1: writes partials, layout
// ((b*NCH + chunk)*COUT + co)*1024 + sp (consumed by conv1r4_k / comb).
// ---------------------------------------------------------------------------
template <int CINC, int CIN_TOTAL, int COUT, int NCH, bool IN_RELU, bool BIAS>
__global__ __launch_bounds__(128)
void conv3m_k(const float* __restrict__ in, const float* __restrict__ wt,
              const float* __restrict__ bs, float* __restrict__ out)
{
    __shared__ float sW[CINC * 36];       // [ci][c*9 + tap]
    __shared__ float sI[4 * 36 * 32];     // 4 channels, rows padded to 36

    const int t     = threadIdx.x;
    const int ox0   = (t & 3) * 8;
    const int oy    = t >> 2;
    const int chunk = blockIdx.x;
    const int co0   = blockIdx.y * 4;
    const int b     = blockIdx.z;
    const int ci0   = chunk * CINC;

    // One-time weight stage: wt[((co0+c)*CIN_TOTAL + ci0+ci)*9 + tap]
    for (int i = t; i < CINC * 36; i += 128) {
        int ci  = i / 36;
        int r   = i - ci * 36;
        int c   = r / 9;
        int tap = r - c * 9;
        sW[i] = __ldg(wt + ((size_t)(co0 + c) * CIN_TOTAL + ci0 + ci) * 9 + tap);
    }

    float acc[4][8];
#pragma unroll
    for (int c = 0; c < 4; c++) {
        float bv = (NCH == 1 && BIAS) ? __ldg(bs + co0 + c) : 0.f;
#pragma unroll
        for (int j = 0; j < 8; j++) acc[c][j] = bv;
    }

    const float* inb = in + ((size_t)b * CIN_TOTAL + ci0) * 1024;

#pragma unroll 1
    for (int cc = 0; cc < CINC; cc += 4) {
        __syncthreads();   // protect previous tile reads (also covers sW 1st iter)
        // fill 4 channels: 1024 float4 total, 8 per thread, coalesced
#pragma unroll
        for (int m = 0; m < 8; m++) {
            int idx = m * 128 + t;
            int q   = idx >> 8;
            int rem = idx & 255;
            int y   = rem >> 3;
            int xg  = (rem & 7) * 4;
            float4 v = *(const float4*)(inb + (cc + q) * 1024 + y * 32 + xg);
            if (IN_RELU) {
                v.x = fmaxf(v.x, 0.f); v.y = fmaxf(v.y, 0.f);
                v.z = fmaxf(v.z, 0.f); v.w = fmaxf(v.w, 0.f);
            }
            *(float4*)(sI + q * 1152 + y * 36 + xg) = v;
        }
        __syncthreads();

#pragma unroll
        for (int q = 0; q < 4; q++) {
            const float* sw = sW + (cc + q) * 36;
            const float* si = sI + q * 1152;
#pragma unroll
            for (int ky = 0; ky < 3; ky++) {
                int iy = oy - 1 + ky;
                if (iy < 0 || iy >= 32) continue;
                const float* row = si + iy * 36;
                float w[10];
                w[0] = (ox0 > 0) ? row[ox0 - 1] : 0.f;
                float4 v0 = *(const float4*)(row + ox0);
                float4 v1 = *(const float4*)(row + ox0 + 4);
                w[1] = v0.x; w[2] = v0.y; w[3] = v0.z; w[4] = v0.w;
                w[5] = v1.x; w[6] = v1.y; w[7] = v1.z; w[8] = v1.w;
                w[9] = (ox0 < 24) ? row[ox0 + 8] : 0.f;
#pragma unroll
                for (int c = 0; c < 4; c++) {
                    float w0 = sw[c * 9 + ky * 3];
                    float w1 = sw[c * 9 + ky * 3 + 1];
                    float w2 = sw[c * 9 + ky * 3 + 2];
#pragma unroll
                    for (int j = 0; j < 8; j++) {
                        acc[c][j] = fmaf(w[j],     w0, acc[c][j]);
                        acc[c][j] = fmaf(w[j + 1], w1, acc[c][j]);
                        acc[c][j] = fmaf(w[j + 2], w2, acc[c][j]);
                    }
                }
            }
        }
    }

#pragma unroll
    for (int c = 0; c < 4; c++) {
        size_t o;
        if (NCH == 1)
            o = (((size_t)b * COUT + (co0 + c)) * 32 + oy) * 32 + ox0;
        else
            o = (((size_t)(b * NCH + chunk) * COUT + (co0 + c)) * 32 + oy) * 32 + ox0;
        *(float4*)(out + o)     = make_float4(acc[c][0], acc[c][1], acc[c][2], acc[c][3]);
        *(float4*)(out + o + 4) = make_float4(acc[c][4], acc[c][5], acc[c][6], acc[c][7]);
    }
}

// ---------------------------------------------------------------------------
// Split-ci k4 s2 p1 conv (e2): in 64x64 -> out 32x32 (R5, proven).
// ---------------------------------------------------------------------------
template <int CINC, int CIN_TOTAL, int COUT>
__global__ __launch_bounds__(128)
void conv4s_k(const float* __restrict__ in, const float* __restrict__ wt,
              float* __restrict__ p0, float* __restrict__ p1)
{
    const int t     = threadIdx.x;
    const int ox0   = (t * 8) & 31;
    const int oy    = t >> 2;
    const int chunk = blockIdx.x;
    const int co0   = blockIdx.y * 4;
    const int b     = blockIdx.z;
    const int ci0   = chunk * CINC;

    float acc[4][8];
#pragma unroll
    for (int c = 0; c < 4; c++)
#pragma unroll
        for (int j = 0; j < 8; j++) acc[c][j] = 0.f;

    const float* inb = in + (size_t)b * CIN_TOTAL * 4096 + ci0 * 4096;
    const int ixb = ox0 * 2 - 1;

#pragma unroll 1
    for (int ci = 0; ci < CINC; ci++) {
        const float* ip  = inb + ci * 4096;
        const float* wci = wt + ((size_t)co0 * CIN_TOTAL + ci0 + ci) * 16;
#pragma unroll
        for (int ky = 0; ky < 4; ky++) {
            int iy = oy * 2 - 1 + ky;
            if (iy < 0 || iy >= 64) continue;
            const float* row = ip + iy * 64;
            float w[18];
            w[0] = (ixb >= 0) ? row[ixb] : 0.f;
#pragma unroll
            for (int m = 0; m < 4; m++) {
                float4 v = *(const float4*)(row + ixb + 1 + 4 * m);
                w[1 + 4 * m] = v.x; w[2 + 4 * m] = v.y;
                w[3 + 4 * m] = v.z; w[4 + 4 * m] = v.w;
            }
            w[17] = (ixb + 17 < 64) ? row[ixb + 17] : 0.f;
#pragma unroll
            for (int c = 0; c < 4; c++) {
                float4 wv = *(const float4*)(wci + c * CIN_TOTAL * 16 + ky * 4);
                float wk[4] = {wv.x, wv.y, wv.z, wv.w};
#pragma unroll
                for (int kx = 0; kx < 4; kx++)
#pragma unroll
                    for (int j = 0; j < 8; j++)
                        acc[c][j] = fmaf(w[j * 2 + kx], wk[kx], acc[c][j]);
            }
        }
    }

    float* dst = (chunk == 0) ? p0 : p1;
#pragma unroll
    for (int c = 0; c < 4; c++) {
        size_t o = (((size_t)b * COUT + (co0 + c)) * 32 + oy) * 32 + ox0;
        *(float4*)(dst + o)     = make_float4(acc[c][0], acc[c][1], acc[c][2], acc[c][3]);
        *(float4*)(dst + o + 4) = make_float4(acc[c][4], acc[c][5], acc[c][6], acc[c][7]);
    }
}

// ---------------------------------------------------------------------------
// Combine 2 partials (+bias, optional relu) — used by e2 only.
// ---------------------------------------------------------------------------
template <int COUT, bool RELU>
__global__ __launch_bounds__(256)
void comb_k(const float* __restrict__ p0, const float* __restrict__ p1,
            const float* __restrict__ bs, float* __restrict__ dst, int bstr)
{
    int i4 = blockIdx.x * 256 + threadIdx.x;
    if (i4 >= 32 * COUT * 256) return;
    size_t i = (size_t)i4 * 4;
    int b  = i4 >> 8;
    int co = b % COUT;
    b = b / COUT;
    size_t s = i + (size_t)b * bstr;
    float4 a0 = *(const float4*)(p0 + s);
    float4 a1 = *(const float4*)(p1 + s);
    float bv = __ldg(bs + co);
    float v0 = a0.x + a1.x + bv, v1 = a0.y + a1.y + bv;
    float v2 = a0.z + a1.z + bv, v3 = a0.w + a1.w + bv;
    if (RELU) {
        v0 = fmaxf(v0, 0.f); v1 = fmaxf(v1, 0.f);
        v2 = fmaxf(v2, 0.f); v3 = fmaxf(v3, 0.f);
    }
    *(float4*)(dst + i) = make_float4(v0, v1, v2, v3);
}

// ---------------------------------------------------------------------------
// Fused: sum 4 res3x3 partials -> relu -> 1x1 (32->128) -> + residual (R5).
// ---------------------------------------------------------------------------
__global__ __launch_bounds__(128)
void conv1r4_k(const float* __restrict__ part, const float* __restrict__ wt,
               const float* __restrict__ res, float* __restrict__ out)
{
    const int t   = threadIdx.x;
    const int ox0 = (t * 8) & 31;
    const int oy  = t >> 2;
    const int co0 = blockIdx.y * 4;
    const int b   = blockIdx.z;

    float acc[4][8];
#pragma unroll
    for (int c = 0; c < 4; c++)
#pragma unroll
        for (int j = 0; j < 8; j++) acc[c][j] = 0.f;

    const float* pb = part + (size_t)(b * 4) * 32 * 1024 + oy * 32 + ox0;

#pragma unroll 1
    for (int ci = 0; ci < 32; ci++) {
        const float* p = pb + ci * 1024;
        float w[8] = {0, 0, 0, 0, 0, 0, 0, 0};
#pragma unroll
        for (int ch = 0; ch < 4; ch++) {
            const float* pc = p + ch * 32 * 1024;
            float4 v0 = *(const float4*)pc;
            float4 v1 = *(const float4*)(pc + 4);
            w[0] += v0.x; w[1] += v0.y; w[2] += v0.z; w[3] += v0.w;
            w[4] += v1.x; w[5] += v1.y; w[6] += v1.z; w[7] += v1.w;
        }
#pragma unroll
        for (int m = 0; m < 8; m++) w[m] = fmaxf(w[m], 0.f);
        float wv0 = __ldg(wt + (co0 + 0) * 32 + ci);
        float wv1 = __ldg(wt + (co0 + 1) * 32 + ci);
        float wv2 = __ldg(wt + (co0 + 2) * 32 + ci);
        float wv3 = __ldg(wt + (co0 + 3) * 32 + ci);
#pragma unroll
        for (int j = 0; j < 8; j++) {
            acc[0][j] = fmaf(w[j], wv0, acc[0][j]);
            acc[1][j] = fmaf(w[j], wv1, acc[1][j]);
            acc[2][j] = fmaf(w[j], wv2, acc[2][j]);
            acc[3][j] = fmaf(w[j], wv3, acc[3][j]);
        }
    }

#pragma unroll
    for (int c = 0; c < 4; c++) {
        size_t o = (((size_t)b * 128 + (co0 + c)) * 32 + oy) * 32 + ox0;
        float4 r0 = *(const float4*)(res + o);
        float4 r1 = *(const float4*)(res + o + 4);
        *(float4*)(out + o) = make_float4(acc[c][0] + r0.x, acc[c][1] + r0.y,
                                          acc[c][2] + r0.z, acc[c][3] + r0.w);
        *(float4*)(out + o + 4) = make_float4(acc[c][4] + r1.x, acc[c][5] + r1.y,
                                              acc[c][6] + r1.z, acc[c][7] + r1.w);
    }
}

// ---------------------------------------------------------------------------
// ConvTranspose2d(k=4,s=2,p=1) direct gather (R2, proven).
// ---------------------------------------------------------------------------
template <int TCO, int CIN, int HIN, int WIN, int COUT, int HOUT, int WOUT,
          bool IN_RELU, bool OUT_RELU, bool VEC_ST>
__global__ __launch_bounds__(128)
void deconv_k(const float* __restrict__ in, const float* __restrict__ wt,
              const float* __restrict__ bs, float* __restrict__ out)
{
    constexpr int TX = 8;
    static_assert((HOUT * WOUT / TX) % 128 == 0, "tiles fill blocks");

    int tid = blockIdx.x * 128 + threadIdx.x;
    int ox0 = (tid * TX) % WOUT;
    int oy  = (tid * TX) / WOUT;
    int co0 = blockIdx.y * TCO;
    int b   = blockIdx.z;

    float acc[TCO][TX];
#pragma unroll
    for (int c = 0; c < TCO; c++) {
        float bv = __ldg(bs + co0 + c);
#pragma unroll
        for (int j = 0; j < TX; j++) acc[c][j] = bv;
    }

    const int ixb = ox0 / 2 - 1;
    const int oyp = oy & 1;
    const float* inb = in + (size_t)b * CIN * HIN * WIN;

#pragma unroll 1
    for (int ci = 0; ci < CIN; ci++) {
        const float* ip  = inb + ci * HIN * WIN;
        const float* wci = wt + ((size_t)co0 * CIN + ci) * 16;
#pragma unroll
        for (int t = 0; t < 2; t++) {
            int ky = oyp + 2 * t;
            int iy = (oy - 2 + ky) >> 1;
            if (iy < 0 || iy >= HIN) continue;
            const float* row = ip + iy * WIN;
            float u[6];
            u[0] = (ixb >= 0) ? row[ixb] : 0.f;
            float4 v = *(const float4*)(row + ixb + 1);
            u[1] = v.x; u[2] = v.y; u[3] = v.z; u[4] = v.w;
            u[5] = (ixb + 5 < WIN) ? row[ixb + 5] : 0.f;
            if (IN_RELU) {
#pragma unroll
                for (int m = 0; m < 6; m++) u[m] = fmaxf(u[m], 0.f);
            }
#pragma unroll
            for (int c = 0; c < TCO; c++) {
                float4 wv = *(const float4*)(wci + c * CIN * 16 + ky * 4);
#pragma unroll
                for (int j = 0; j < TX; j++) {
                    const int jo = j & 1;
                    const int sh = (j + 1) >> 1;
                    float wl = jo ? wv.y : wv.x;
                    float wh = jo ? wv.w : wv.z;
                    acc[c][j] = fmaf(u[sh],     wl, acc[c][j]);
                    acc[c][j] = fmaf(u[sh + 1], wh, acc[c][j]);
                }
            }
        }
    }

#pragma unroll
    for (int c = 0; c < TCO; c++) {
        size_t o = (((size_t)b * COUT + (co0 + c)) * HOUT + oy) * WOUT + ox0;
        float v[TX];
#pragma unroll
        for (int j = 0; j < TX; j++) {
            v[j] = acc[c][j];
            if (OUT_RELU) v[j] = fmaxf(v[j], 0.f);
        }
        if constexpr (VEC_ST) {
            *(float4*)(out + o)     = make_float4(v[0], v[1], v[2], v[3]);
            *(float4*)(out + o + 4) = make_float4(v[4], v[5], v[6], v[7]);
        } else {
#pragma unroll
            for (int j = 0; j < TX; j++) out[o + j] = v[j];
        }
    }
}

// ---------------------------------------------------------------------------
// VQ (R2, proven)
// ---------------------------------------------------------------------------
__global__ void cnorm_kernel(const float* __restrict__ cb, float* __restrict__ cn)
{
    int k = blockIdx.x * blockDim.x + threadIdx.x;
    if (k >= 512) return;
    const float* c = cb + k * 64;
    float s = 0.f;
#pragma unroll
    for (int d = 0; d < 64; d++) s = fmaf(c[d], c[d], s);
    cn[k] = s;
}

__global__ __launch_bounds__(256)
void vq_kernel(const float* __restrict__ z, const float* __restrict__ cb,
               const float* __restrict__ cn, int* __restrict__ idx,
               float* __restrict__ q, float* __restrict__ err)
{
    int p = blockIdx.x * blockDim.x + threadIdx.x;  // 0..32767
    if (p >= 32768) return;
    int b = p >> 10, s = p & 1023;
    const float* zp = z + (size_t)b * 64 * 1024 + s;
    float zv[64];
#pragma unroll
    for (int d = 0; d < 64; d++) zv[d] = zp[d * 1024];

    float best = 3.4e38f;
    int bk = 0;
#pragma unroll 1
    for (int k = 0; k < 512; k++) {
        const float4* c4 = (const float4*)(cb + (size_t)k * 64);
        float d0 = 0.f, d1 = 0.f, d2 = 0.f, d3 = 0.f;
#pragma unroll
        for (int m = 0; m < 16; m++) {
            float4 cv = __ldg(c4 + m);
            d0 = fmaf(zv[4 * m],     cv.x, d0);
            d1 = fmaf(zv[4 * m + 1], cv.y, d1);
            d2 = fmaf(zv[4 * m + 2], cv.z, d2);
            d3 = fmaf(zv[4 * m + 3], cv.w, d3);
        }
        float dist = __ldg(cn + k) - 2.f * ((d0 + d1) + (d2 + d3));
        if (dist < best) { best = dist; bk = k; }   // strict <: first-min (jnp.argmin)
    }
    idx[p] = bk;
    float* qp = q + (size_t)b * 64 * 1024 + s;
    const float* c = cb + (size_t)bk * 64;
    float e = 0.f;
#pragma unroll
    for (int d = 0; d < 64; d++) {
        float cd = __ldg(c + d);
        qp[d * 1024] = cd;
        float df = zv[d] - cd;
        e = fmaf(df, df, e);
    }
    err[p] = e;
}

__global__ __launch_bounds__(512)
void stats_kernel(const int* __restrict__ idx, const float* __restrict__ err,
                  float* __restrict__ out0, float* __restrict__ outp)
{
    __shared__ int   h[512];
    __shared__ float sm[512];
    int t = threadIdx.x;
    h[t] = 0;
    float s = 0.f;
    __syncthreads();
    for (int i = t; i < 32768; i += 512) {
        atomicAdd(&h[idx[i]], 1);
        s += err[i];
    }
    sm[t] = s;
    __syncthreads();
    for (int off = 256; off > 0; off >>= 1) {
        if (t < off) sm[t] += sm[t + off];
        __syncthreads();
    }
    if (t == 0) out0[0] = 1.25f * sm[0] / 2097152.0f;   // (1+beta)*mse
    __syncthreads();
    float pr = (float)h[t] * (1.0f / 32768.0f);
    sm[t] = pr * logf(pr + 1e-10f);
    __syncthreads();
    for (int off = 256; off > 0; off >>= 1) {
        if (t < off) sm[t] += sm[t + off];
        __syncthreads();
    }
    if (t == 0) outp[0] = expf(-sm[0]);
}

// ---------------------------------------------------------------------------
// Launch
// ---------------------------------------------------------------------------
extern "C" void kernel_launch(void* const* d_in, const int* in_sizes, int n_in,
                              void* d_out, int out_size)
{
    const float* x     = (const float*)d_in[0];
    const float* e_w1  = (const float*)d_in[1];
    const float* e_b1  = (const float*)d_in[2];
    const float* e_w2  = (const float*)d_in[3];
    const float* e_b2  = (const float*)d_in[4];
    const float* e_w3  = (const float*)d_in[5];
    const float* e_b3  = (const float*)d_in[6];
    const float* e_r1a = (const float*)d_in[7];
    const float* e_r1b = (const float*)d_in[8];
    const float* e_r2a = (const float*)d_in[9];
    const float* e_r2b = (const float*)d_in[10];
    const float* pre_w = (const float*)d_in[11];
    const float* pre_b = (const float*)d_in[12];
    const float* cb    = (const float*)d_in[13];
    const float* d_w1  = (const float*)d_in[14];
    const float* d_b1  = (const float*)d_in[15];
    const float* d_r1a = (const float*)d_in[16];
    const float* d_r1b = (const float*)d_in[17];
    const float* d_r2a = (const float*)d_in[18];
    const float* d_r2b = (const float*)d_in[19];
    const float* dt_w1 = (const float*)d_in[20];
    const float* dt_b1 = (const float*)d_in[21];
    const float* dt_w2 = (const float*)d_in[22];
    const float* dt_b2 = (const float*)d_in[23];
    float* out = (float*)d_out;

    float *A, *Bf, *Cc, *Z, *Q, *G, *cn, *err;
    int *idx;
    cudaGetSymbolAddress((void**)&A,    g_A);
    cudaGetSymbolAddress((void**)&Bf,   g_B);
    cudaGetSymbolAddress((void**)&Cc,   g_C);
    cudaGetSymbolAddress((void**)&Z,    g_Z);
    cudaGetSymbolAddress((void**)&Q,    g_Q);
    cudaGetSymbolAddress((void**)&G,    g_G);
    cudaGetSymbolAddress((void**)&cn,   g_cnorm);
    cudaGetSymbolAddress((void**)&err,  g_err);
    cudaGetSymbolAddress((void**)&idx,  g_idx);

    dim3 blk(128);
    const int CB128 = 32 * 128 * 256;   // float4 count for COUT=128 combine

    // ---- encoder ----
    // e1: [32,3,128,128] -> A, k4 s2 p1, relu
    conv_k<4,4,2,1,4, 3,128,128, 64,64,64, false,true,true,false>
        <<<dim3(4, 16, 32), blk>>>(x, e_w1, e_b1, A, nullptr);
    // e2 split-2: A -> partials (G, Cc); combine -> Bf (relu+bias)
    conv4s_k<32, 64, 128><<<dim3(2, 32, 32), blk>>>(A, e_w2, G, Cc);
    comb_k<128, true><<<(CB128 + 255) / 256, 256>>>(G, Cc, e_b2, Bf, 0);
    // e3 (smem, unsplit): Bf -> Cc (bias, no relu)
    conv3m_k<128, 128, 128, 1, false, true>
        <<<dim3(1, 32, 32), blk>>>(Bf, e_w3, e_b3, Cc);
    // encoder res stack (x2): smem split-4 3x3 -> A partials; fused 1x1+residual
    conv3m_k<32, 128, 32, 4, true, false>
        <<<dim3(4, 8, 32), blk>>>(Cc, e_r1a, nullptr, A);
    conv1r4_k<<<dim3(1, 32, 32), blk>>>(A, e_r1b, Cc, Cc);
    conv3m_k<32, 128, 32, 4, true, false>
        <<<dim3(4, 8, 32), blk>>>(Cc, e_r2a, nullptr, A);
    conv1r4_k<<<dim3(1, 32, 32), blk>>>(A, e_r2b, Cc, Cc);
    // pre-VQ 1x1 (relu-in = final stack relu): Cc -> Z
    conv_k<1,1,1,0,4, 128,32,32, 64,32,32, true,false,true,false>
        <<<dim3(1, 16, 32), blk>>>(Cc, pre_w, pre_b, Z, nullptr);

    // ---- vector quantizer ----
    cnorm_kernel<<<2, 256>>>(cb, cn);
    vq_kernel<<<128, 256>>>(Z, cb, cn, idx, Q, err);
    stats_kernel<<<1, 512>>>(idx, err, out, out + (out_size - 1));

    // ---- decoder ----
    // d1 (smem, unsplit): Q -> G (bias, no relu)
    conv3m_k<64, 64, 128, 1, false, true>
        <<<dim3(1, 32, 32), blk>>>(Q, d_w1, d_b1, G);
    // decoder res stack (x2)
    conv3m_k<32, 128, 32, 4, true, false>
        <<<dim3(4, 8, 32), blk>>>(G, d_r1a, nullptr, A);
    conv1r4_k<<<dim3(1, 32, 32), blk>>>(A, d_r1b, G, G);
    conv3m_k<32, 128, 32, 4, true, false>
        <<<dim3(4, 8, 32), blk>>>(G, d_r2a, nullptr, A);
    conv1r4_k<<<dim3(1, 32, 32), blk>>>(A, d_r2b, G, G);
    // dt1: G -> A [32,64,64,64], relu-in + relu-out
    deconv_k<4, 128,32,32, 64,64,64, true,true,true>
        <<<dim3(4, 16, 32), blk>>>(G, dt_w1, dt_b1, A);
    // dt2: A -> x_recon into d_out+1 (misaligned base -> scalar stores)
    deconv_k<3, 64,64,64, 3,128,128, false,false,false>
        <<<dim3(16, 1, 32), blk>>>(A, dt_w2, dt_b2, out + 1);
}

// round 8
// speedup vs baseline: 1.2265x; 1.0139x over previous
#include <cuda_runtime.h>
#include <math.h>

// ---------------------------------------------------------------------------
// VQ-VAE forward, fp32. Round 8: R7 with the weight-stage bug fixed
// (144 smem weights staged by 128 threads -> strided loop, not t<144).
// conv3m smem ~19KB -> 12 blocks/SM capacity. Rest identical to R6/R7.
// Output layout: [loss, x_recon(1572864), perplexity]
// ---------------------------------------------------------------------------

// Scratch (device globals; no allocation allowed)
__device__ float g_A[32u * 64 * 64 * 64];    // e1 out / dt1 out / res partials
__device__ float g_B[32u * 128 * 32 * 32];   // e2 out
__device__ float g_C[32u * 128 * 32 * 32];   // e3 out + encoder res stack
__device__ float g_Z[32u * 64 * 32 * 32];    // pre-VQ z
__device__ float g_Q[32u * 64 * 32 * 32];    // quantized q
__device__ float g_G[32u * 128 * 32 * 32];   // decoder stack (also e2 partial)
__device__ int   g_idx[32768];
__device__ float g_cnorm[512];
__device__ float g_err[32768];

// ---------------------------------------------------------------------------
// Generic direct conv (R2, proven): used for e1 (k4s2) and pre (1x1).
// ---------------------------------------------------------------------------
template <int KH, int KW, int S, int P, int TCO,
          int CIN, int HIN, int WIN, int COUT, int HOUT, int WOUT,
          bool IN_RELU, bool OUT_RELU, bool BIAS, bool ADD>
__global__ __launch_bounds__(128)
void conv_k(const float* __restrict__ in, const float* __restrict__ wt,
            const float* __restrict__ bs, float* __restrict__ out,
            const float* __restrict__ res)
{
    constexpr int TX   = 8;
    constexpr int WINW = (TX - 1) * S + KW;
    static_assert((HOUT * WOUT / TX) % 128 == 0, "tiles fill blocks");

    int tid = blockIdx.x * 128 + threadIdx.x;
    int ox0 = (tid * TX) % WOUT;
    int oy  = (tid * TX) / WOUT;
    int co0 = blockIdx.y * TCO;
    int b   = blockIdx.z;

    float acc[TCO][TX];
#pragma unroll
    for (int c = 0; c < TCO; c++) {
        float bv = BIAS ? __ldg(bs + co0 + c) : 0.f;
#pragma unroll
        for (int j = 0; j < TX; j++) acc[c][j] = bv;
    }

    const float* inb = in + (size_t)b * CIN * HIN * WIN;
    const int ixb = ox0 * S - P;

#pragma unroll 1
    for (int ci = 0; ci < CIN; ci++) {
        const float* ip  = inb + ci * HIN * WIN;
        const float* wci = wt + ((size_t)co0 * CIN + ci) * KH * KW;
#pragma unroll
        for (int ky = 0; ky < KH; ky++) {
            int iy = oy * S - P + ky;
            if (P > 0 && (iy < 0 || iy >= HIN)) continue;
            const float* row = ip + iy * WIN;
            float w[WINW];
            if constexpr (P == 0) {
                float4 v0 = *(const float4*)(row + ox0);
                float4 v1 = *(const float4*)(row + ox0 + 4);
                w[0] = v0.x; w[1] = v0.y; w[2] = v0.z; w[3] = v0.w;
                w[4] = v1.x; w[5] = v1.y; w[6] = v1.z; w[7] = v1.w;
            } else {
                w[0] = (ixb >= 0) ? row[ixb] : 0.f;
#pragma unroll
                for (int m = 0; m < (WINW - 2) / 4; m++) {
                    float4 v = *(const float4*)(row + ixb + 1 + 4 * m);
                    w[1 + 4 * m] = v.x; w[2 + 4 * m] = v.y;
                    w[3 + 4 * m] = v.z; w[4 + 4 * m] = v.w;
                }
                w[WINW - 1] = (ixb + WINW - 1 < WIN) ? row[ixb + WINW - 1] : 0.f;
            }
            if (IN_RELU) {
#pragma unroll
                for (int m = 0; m < WINW; m++) w[m] = fmaxf(w[m], 0.f);
            }
#pragma unroll
            for (int c = 0; c < TCO; c++) {
                const float* wp = wci + c * CIN * KH * KW + ky * KW;
                if constexpr (KW == 4) {
                    float4 wv = *(const float4*)wp;
                    float wk[4] = {wv.x, wv.y, wv.z, wv.w};
#pragma unroll
                    for (int kx = 0; kx < 4; kx++)
#pragma unroll
                        for (int j = 0; j < TX; j++)
                            acc[c][j] = fmaf(w[j * S + kx], wk[kx], acc[c][j]);
                } else {
#pragma unroll
                    for (int kx = 0; kx < KW; kx++) {
                        float wv = __ldg(wp + kx);
#pragma unroll
                        for (int j = 0; j < TX; j++)
                            acc[c][j] = fmaf(w[j * S + kx], wv, acc[c][j]);
                    }
                }
            }
        }
    }

#pragma unroll
    for (int c = 0; c < TCO; c++) {
        size_t o = (((size_t)b * COUT + (co0 + c)) * HOUT + oy) * WOUT + ox0;
        float v[TX];
#pragma unroll
        for (int j = 0; j < TX; j++) v[j] = acc[c][j];
        if (ADD) {
            float4 r0 = *(const float4*)(res + o);
            float4 r1 = *(const float4*)(res + o + 4);
            v[0] += r0.x; v[1] += r0.y; v[2] += r0.z; v[3] += r0.w;
            v[4] += r1.x; v[5] += r1.y; v[6] += r1.z; v[7] += r1.w;
        }
        if (OUT_RELU) {
#pragma unroll
            for (int j = 0; j < TX; j++) v[j] = fmaxf(v[j], 0.f);
        }
        *(float4*)(out + o)     = make_float4(v[0], v[1], v[2], v[3]);
        *(float4*)(out + o + 4) = make_float4(v[4], v[5], v[6], v[7]);
    }
}

// ---------------------------------------------------------------------------
// Smem-staged 3x3 s1 p1 conv on 32x32 maps. Per 4-ci chunk: inputs staged
// into padded (36-float) rows AND the 4*4co*9=144 weights staged alongside
// (smem ~19KB -> 12 blocks/SM capacity).
// NCH==1: final output (+bias). NCH>1: partials at
// ((b*NCH + chunk)*COUT + co)*1024 + sp.
// ---------------------------------------------------------------------------
template <int CINC, int CIN_TOTAL, int COUT, int NCH, bool IN_RELU, bool BIAS>
__global__ __launch_bounds__(128)
void conv3m_k(const float* __restrict__ in, const float* __restrict__ wt,
              const float* __restrict__ bs, float* __restrict__ out)
{
    __shared__ float sW[4 * 36];          // current 4 ci: [q][c*9 + tap]
    __shared__ float sI[4 * 36 * 32];     // 4 channels, rows padded to 36

    const int t     = threadIdx.x;
    const int ox0   = (t & 3) * 8;
    const int oy    = t >> 2;
    const int chunk = blockIdx.x;
    const int co0   = blockIdx.y * 4;
    const int b     = blockIdx.z;
    const int ci0   = chunk * CINC;

    float acc[4][8];
#pragma unroll
    for (int c = 0; c < 4; c++) {
        float bv = (NCH == 1 && BIAS) ? __ldg(bs + co0 + c) : 0.f;
#pragma unroll
        for (int j = 0; j < 8; j++) acc[c][j] = bv;
    }

    const float* inb = in + ((size_t)b * CIN_TOTAL + ci0) * 1024;

#pragma unroll 1
    for (int cc = 0; cc < CINC; cc += 4) {
        __syncthreads();   // previous tile fully consumed
        // stage 4 input channels (8 float4 per thread, coalesced)
#pragma unroll
        for (int m = 0; m < 8; m++) {
            int idx = m * 128 + t;
            int q   = idx >> 8;
            int rem = idx & 255;
            int y   = rem >> 3;
            int xg  = (rem & 7) * 4;
            float4 v = *(const float4*)(inb + (cc + q) * 1024 + y * 32 + xg);
            if (IN_RELU) {
                v.x = fmaxf(v.x, 0.f); v.y = fmaxf(v.y, 0.f);
                v.z = fmaxf(v.z, 0.f); v.w = fmaxf(v.w, 0.f);
            }
            *(float4*)(sI + q * 1152 + y * 36 + xg) = v;
        }
        // stage the 4*4*9 = 144 weights for this chunk (STRIDED: 128 threads)
        for (int i = t; i < 144; i += 128) {
            int q   = i / 36;            // ci within chunk
            int r   = i - q * 36;
            int c   = r / 9;
            int tap = r - c * 9;
            sW[i] =
                __ldg(wt + ((size_t)(co0 + c) * CIN_TOTAL + ci0 + cc + q) * 9 + tap);
        }
        __syncthreads();

#pragma unroll
        for (int q = 0; q < 4; q++) {
            const float* sw = sW + q * 36;
            const float* si = sI + q * 1152;
#pragma unroll
            for (int ky = 0; ky < 3; ky++) {
                int iy = oy - 1 + ky;
                if (iy < 0 || iy >= 32) continue;
                const float* row = si + iy * 36;
                float w[10];
                w[0] = (ox0 > 0) ? row[ox0 - 1] : 0.f;
                float4 v0 = *(const float4*)(row + ox0);
                float4 v1 = *(const float4*)(row + ox0 + 4);
                w[1] = v0.x; w[2] = v0.y; w[3] = v0.z; w[4] = v0.w;
                w[5] = v1.x; w[6] = v1.y; w[7] = v1.z; w[8] = v1.w;
                w[9] = (ox0 < 24) ? row[ox0 + 8] : 0.f;
#pragma unroll
                for (int c = 0; c < 4; c++) {
                    float w0 = sw[c * 9 + ky * 3];
                    float w1 = sw[c * 9 + ky * 3 + 1];
                    float w2 = sw[c * 9 + ky * 3 + 2];
#pragma unroll
                    for (int j = 0; j < 8; j++) {
                        acc[c][j] = fmaf(w[j],     w0, acc[c][j]);
                        acc[c][j] = fmaf(w[j + 1], w1, acc[c][j]);
                        acc[c][j] = fmaf(w[j + 2], w2, acc[c][j]);
                    }
                }
            }
        }
    }

#pragma unroll
    for (int c = 0; c < 4; c++) {
        size_t o;
        if (NCH == 1)
            o = (((size_t)b * COUT + (co0 + c)) * 32 + oy) * 32 + ox0;
        else
            o = (((size_t)(b * NCH + chunk) * COUT + (co0 + c)) * 32 + oy) * 32 + ox0;
        *(float4*)(out + o)     = make_float4(acc[c][0], acc[c][1], acc[c][2], acc[c][3]);
        *(float4*)(out + o + 4) = make_float4(acc[c][4], acc[c][5], acc[c][6], acc[c][7]);
    }
}

// ---------------------------------------------------------------------------
// Split-ci k4 s2 p1 conv (e2): in 64x64 -> out 32x32 (R5, proven).
// ---------------------------------------------------------------------------
template <int CINC, int CIN_TOTAL, int COUT>
__global__ __launch_bounds__(128)
void conv4s_k(const float* __restrict__ in, const float* __restrict__ wt,
              float* __restrict__ p0, float* __restrict__ p1)
{
    const int t     = threadIdx.x;
    const int ox0   = (t * 8) & 31;
    const int oy    = t >> 2;
    const int chunk = blockIdx.x;
    const int co0   = blockIdx.y * 4;
    const int b     = blockIdx.z;
    const int ci0   = chunk * CINC;

    float acc[4][8];
#pragma unroll
    for (int c = 0; c < 4; c++)
#pragma unroll
        for (int j = 0; j < 8; j++) acc[c][j] = 0.f;

    const float* inb = in + (size_t)b * CIN_TOTAL * 4096 + ci0 * 4096;
    const int ixb = ox0 * 2 - 1;

#pragma unroll 1
    for (int ci = 0; ci < CINC; ci++) {
        const float* ip  = inb + ci * 4096;
        const float* wci = wt + ((size_t)co0 * CIN_TOTAL + ci0 + ci) * 16;
#pragma unroll
        for (int ky = 0; ky < 4; ky++) {
            int iy = oy * 2 - 1 + ky;
            if (iy < 0 || iy >= 64) continue;
            const float* row = ip + iy * 64;
            float w[18];
            w[0] = (ixb >= 0) ? row[ixb] : 0.f;
#pragma unroll
            for (int m = 0; m < 4; m++) {
                float4 v = *(const float4*)(row + ixb + 1 + 4 * m);
                w[1 + 4 * m] = v.x; w[2 + 4 * m] = v.y;
                w[3 + 4 * m] = v.z; w[4 + 4 * m] = v.w;
            }
            w[17] = (ixb + 17 < 64) ? row[ixb + 17] : 0.f;
#pragma unroll
            for (int c = 0; c < 4; c++) {
                float4 wv = *(const float4*)(wci + c * CIN_TOTAL * 16 + ky * 4);
                float wk[4] = {wv.x, wv.y, wv.z, wv.w};
#pragma unroll
                for (int kx = 0; kx < 4; kx++)
#pragma unroll
                    for (int j = 0; j < 8; j++)
                        acc[c][j] = fmaf(w[j * 2 + kx], wk[kx], acc[c][j]);
            }
        }
    }

    float* dst = (chunk == 0) ? p0 : p1;
#pragma unroll
    for (int c = 0; c < 4; c++) {
        size_t o = (((size_t)b * COUT + (co0 + c)) * 32 + oy) * 32 + ox0;
        *(float4*)(dst + o)     = make_float4(acc[c][0], acc[c][1], acc[c][2], acc[c][3]);
        *(float4*)(dst + o + 4) = make_float4(acc[c][4], acc[c][5], acc[c][6], acc[c][7]);
    }
}

// ---------------------------------------------------------------------------
// Combine 2 partials (+bias, optional relu) — used by e2 only.
// ---------------------------------------------------------------------------
template <int COUT, bool RELU>
__global__ __launch_bounds__(256)
void comb_k(const float* __restrict__ p0, const float* __restrict__ p1,
            const float* __restrict__ bs, float* __restrict__ dst, int bstr)
{
    int i4 = blockIdx.x * 256 + threadIdx.x;
    if (i4 >= 32 * COUT * 256) return;
    size_t i = (size_t)i4 * 4;
    int b  = i4 >> 8;
    int co = b % COUT;
    b = b / COUT;
    size_t s = i + (size_t)b * bstr;
    float4 a0 = *(const float4*)(p0 + s);
    float4 a1 = *(const float4*)(p1 + s);
    float bv = __ldg(bs + co);
    float v0 = a0.x + a1.x + bv, v1 = a0.y + a1.y + bv;
    float v2 = a0.z + a1.z + bv, v3 = a0.w + a1.w + bv;
    if (RELU) {
        v0 = fmaxf(v0, 0.f); v1 = fmaxf(v1, 0.f);
        v2 = fmaxf(v2, 0.f); v3 = fmaxf(v3, 0.f);
    }
    *(float4*)(dst + i) = make_float4(v0, v1, v2, v3);
}

// ---------------------------------------------------------------------------
// Fused: sum 4 res3x3 partials -> relu -> 1x1 (32->128) -> + residual (R5).
// ---------------------------------------------------------------------------
__global__ __launch_bounds__(128)
void conv1r4_k(const float* __restrict__ part, const float* __restrict__ wt,
               const float* __restrict__ res, float* __restrict__ out)
{
    const int t   = threadIdx.x;
    const int ox0 = (t * 8) & 31;
    const int oy  = t >> 2;
    const int co0 = blockIdx.y * 4;
    const int b   = blockIdx.z;

    float acc[4][8];
#pragma unroll
    for (int c = 0; c < 4; c++)
#pragma unroll
        for (int j = 0; j < 8; j++) acc[c][j] = 0.f;

    const float* pb = part + (size_t)(b * 4) * 32 * 1024 + oy * 32 + ox0;

#pragma unroll 1
    for (int ci = 0; ci < 32; ci++) {
        const float* p = pb + ci * 1024;
        float w[8] = {0, 0, 0, 0, 0, 0, 0, 0};
#pragma unroll
        for (int ch = 0; ch < 4; ch++) {
            const float* pc = p + ch * 32 * 1024;
            float4 v0 = *(const float4*)pc;
            float4 v1 = *(const float4*)(pc + 4);
            w[0] += v0.x; w[1] += v0.y; w[2] += v0.z; w[3] += v0.w;
            w[4] += v1.x; w[5] += v1.y; w[6] += v1.z; w[7] += v1.w;
        }
#pragma unroll
        for (int m = 0; m < 8; m++) w[m] = fmaxf(w[m], 0.f);
        float wv0 = __ldg(wt + (co0 + 0) * 32 + ci);
        float wv1 = __ldg(wt + (co0 + 1) * 32 + ci);
        float wv2 = __ldg(wt + (co0 + 2) * 32 + ci);
        float wv3 = __ldg(wt + (co0 + 3) * 32 + ci);
#pragma unroll
        for (int j = 0; j < 8; j++) {
            acc[0][j] = fmaf(w[j], wv0, acc[0][j]);
            acc[1][j] = fmaf(w[j], wv1, acc[1][j]);
            acc[2][j] = fmaf(w[j], wv2, acc[2][j]);
            acc[3][j] = fmaf(w[j], wv3, acc[3][j]);
        }
    }

#pragma unroll
    for (int c = 0; c < 4; c++) {
        size_t o = (((size_t)b * 128 + (co0 + c)) * 32 + oy) * 32 + ox0;
        float4 r0 = *(const float4*)(res + o);
        float4 r1 = *(const float4*)(res + o + 4);
        *(float4*)(out + o) = make_float4(acc[c][0] + r0.x, acc[c][1] + r0.y,
                                          acc[c][2] + r0.z, acc[c][3] + r0.w);
        *(float4*)(out + o + 4) = make_float4(acc[c][4] + r1.x, acc[c][5] + r1.y,
                                              acc[c][6] + r1.z, acc[c][7] + r1.w);
    }
}

// ---------------------------------------------------------------------------
// ConvTranspose2d(k=4,s=2,p=1) direct gather (R2, proven).
// ---------------------------------------------------------------------------
template <int TCO, int CIN, int HIN, int WIN, int COUT, int HOUT, int WOUT,
          bool IN_RELU, bool OUT_RELU, bool VEC_ST>
__global__ __launch_bounds__(128)
void deconv_k(const float* __restrict__ in, const float* __restrict__ wt,
              const float* __restrict__ bs, float* __restrict__ out)
{
    constexpr int TX = 8;
    static_assert((HOUT * WOUT / TX) % 128 == 0, "tiles fill blocks");

    int tid = blockIdx.x * 128 + threadIdx.x;
    int ox0 = (tid * TX) % WOUT;
    int oy  = (tid * TX) / WOUT;
    int co0 = blockIdx.y * TCO;
    int b   = blockIdx.z;

    float acc[TCO][TX];
#pragma unroll
    for (int c = 0; c < TCO; c++) {
        float bv = __ldg(bs + co0 + c);
#pragma unroll
        for (int j = 0; j < TX; j++) acc[c][j] = bv;
    }

    const int ixb = ox0 / 2 - 1;
    const int oyp = oy & 1;
    const float* inb = in + (size_t)b * CIN * HIN * WIN;

#pragma unroll 1
    for (int ci = 0; ci < CIN; ci++) {
        const float* ip  = inb + ci * HIN * WIN;
        const float* wci = wt + ((size_t)co0 * CIN + ci) * 16;
#pragma unroll
        for (int t = 0; t < 2; t++) {
            int ky = oyp + 2 * t;
            int iy = (oy - 2 + ky) >> 1;
            if (iy < 0 || iy >= HIN) continue;
            const float* row = ip + iy * WIN;
            float u[6];
            u[0] = (ixb >= 0) ? row[ixb] : 0.f;
            float4 v = *(const float4*)(row + ixb + 1);
            u[1] = v.x; u[2] = v.y; u[3] = v.z; u[4] = v.w;
            u[5] = (ixb + 5 < WIN) ? row[ixb + 5] : 0.f;
            if (IN_RELU) {
#pragma unroll
                for (int m = 0; m < 6; m++) u[m] = fmaxf(u[m], 0.f);
            }
#pragma unroll
            for (int c = 0; c < TCO; c++) {
                float4 wv = *(const float4*)(wci + c * CIN * 16 + ky * 4);
#pragma unroll
                for (int j = 0; j < TX; j++) {
                    const int jo = j & 1;
                    const int sh = (j + 1) >> 1;
                    float wl = jo ? wv.y : wv.x;
                    float wh = jo ? wv.w : wv.z;
                    acc[c][j] = fmaf(u[sh],     wl, acc[c][j]);
                    acc[c][j] = fmaf(u[sh + 1], wh, acc[c][j]);
                }
            }
        }
    }

#pragma unroll
    for (int c = 0; c < TCO; c++) {
        size_t o = (((size_t)b * COUT + (co0 + c)) * HOUT + oy) * WOUT + ox0;
        float v[TX];
#pragma unroll
        for (int j = 0; j < TX; j++) {
            v[j] = acc[c][j];
            if (OUT_RELU) v[j] = fmaxf(v[j], 0.f);
        }
        if constexpr (VEC_ST) {
            *(float4*)(out + o)     = make_float4(v[0], v[1], v[2], v[3]);
            *(float4*)(out + o + 4) = make_float4(v[4], v[5], v[6], v[7]);
        } else {
#pragma unroll
            for (int j = 0; j < TX; j++) out[o + j] = v[j];
        }
    }
}

// ---------------------------------------------------------------------------
// VQ (R2, proven)
// ---------------------------------------------------------------------------
__global__ void cnorm_kernel(const float* __restrict__ cb, float* __restrict__ cn)
{
    int k = blockIdx.x * blockDim.x + threadIdx.x;
    if (k >= 512) return;
    const float* c = cb + k * 64;
    float s = 0.f;
#pragma unroll
    for (int d = 0; d < 64; d++) s = fmaf(c[d], c[d], s);
    cn[k] = s;
}

__global__ __launch_bounds__(256)
void vq_kernel(const float* __restrict__ z, const float* __restrict__ cb,
               const float* __restrict__ cn, int* __restrict__ idx,
               float* __restrict__ q, float* __restrict__ err)
{
    int p = blockIdx.x * blockDim.x + threadIdx.x;  // 0..32767
    if (p >= 32768) return;
    int b = p >> 10, s = p & 1023;
    const float* zp = z + (size_t)b * 64 * 1024 + s;
    float zv[64];
#pragma unroll
    for (int d = 0; d < 64; d++) zv[d] = zp[d * 1024];

    float best = 3.4e38f;
    int bk = 0;
#pragma unroll 1
    for (int k = 0; k < 512; k++) {
        const float4* c4 = (const float4*)(cb + (size_t)k * 64);
        float d0 = 0.f, d1 = 0.f, d2 = 0.f, d3 = 0.f;
#pragma unroll
        for (int m = 0; m < 16; m++) {
            float4 cv = __ldg(c4 + m);
            d0 = fmaf(zv[4 * m],     cv.x, d0);
            d1 = fmaf(zv[4 * m + 1], cv.y, d1);
            d2 = fmaf(zv[4 * m + 2], cv.z, d2);
            d3 = fmaf(zv[4 * m + 3], cv.w, d3);
        }
        float dist = __ldg(cn + k) - 2.f * ((d0 + d1) + (d2 + d3));
        if (dist < best) { best = dist; bk = k; }   // strict <: first-min (jnp.argmin)
    }
    idx[p] = bk;
    float* qp = q + (size_t)b * 64 * 1024 + s;
    const float* c = cb + (size_t)bk * 64;
    float e = 0.f;
#pragma unroll
    for (int d = 0; d < 64; d++) {
        float cd = __ldg(c + d);
        qp[d * 1024] = cd;
        float df = zv[d] - cd;
        e = fmaf(df, df, e);
    }
    err[p] = e;
}

__global__ __launch_bounds__(512)
void stats_kernel(const int* __restrict__ idx, const float* __restrict__ err,
                  float* __restrict__ out0, float* __restrict__ outp)
{
    __shared__ int   h[512];
    __shared__ float sm[512];
    int t = threadIdx.x;
    h[t] = 0;
    float s = 0.f;
    __syncthreads();
    for (int i = t; i < 32768; i += 512) {
        atomicAdd(&h[idx[i]], 1);
        s += err[i];
    }
    sm[t] = s;
    __syncthreads();
    for (int off = 256; off > 0; off >>= 1) {
        if (t < off) sm[t] += sm[t + off];
        __syncthreads();
    }
    if (t == 0) out0[0] = 1.25f * sm[0] / 2097152.0f;   // (1+beta)*mse
    __syncthreads();
    float pr = (float)h[t] * (1.0f / 32768.0f);
    sm[t] = pr * logf(pr + 1e-10f);
    __syncthreads();
    for (int off = 256; off > 0; off >>= 1) {
        if (t < off) sm[t] += sm[t + off];
        __syncthreads();
    }
    if (t == 0) outp[0] = expf(-sm[0]);
}

// ---------------------------------------------------------------------------
// Launch
// ---------------------------------------------------------------------------
extern "C" void kernel_launch(void* const* d_in, const int* in_sizes, int n_in,
                              void* d_out, int out_size)
{
    const float* x     = (const float*)d_in[0];
    const float* e_w1  = (const float*)d_in[1];
    const float* e_b1  = (const float*)d_in[2];
    const float* e_w2  = (const float*)d_in[3];
    const float* e_b2  = (const float*)d_in[4];
    const float* e_w3  = (const float*)d_in[5];
    const float* e_b3  = (const float*)d_in[6];
    const float* e_r1a = (const float*)d_in[7];
    const float* e_r1b = (const float*)d_in[8];
    const float* e_r2a = (const float*)d_in[9];
    const float* e_r2b = (const float*)d_in[10];
    const float* pre_w = (const float*)d_in[11];
    const float* pre_b = (const float*)d_in[12];
    const float* cb    = (const float*)d_in[13];
    const float* d_w1  = (const float*)d_in[14];
    const float* d_b1  = (const float*)d_in[15];
    const float* d_r1a = (const float*)d_in[16];
    const float* d_r1b = (const float*)d_in[17];
    const float* d_r2a = (const float*)d_in[18];
    const float* d_r2b = (const float*)d_in[19];
    const float* dt_w1 = (const float*)d_in[20];
    const float* dt_b1 = (const float*)d_in[21];
    const float* dt_w2 = (const float*)d_in[22];
    const float* dt_b2 = (const float*)d_in[23];
    float* out = (float*)d_out;

    float *A, *Bf, *Cc, *Z, *Q, *G, *cn, *err;
    int *idx;
    cudaGetSymbolAddress((void**)&A,    g_A);
    cudaGetSymbolAddress((void**)&Bf,   g_B);
    cudaGetSymbolAddress((void**)&Cc,   g_C);
    cudaGetSymbolAddress((void**)&Z,    g_Z);
    cudaGetSymbolAddress((void**)&Q,    g_Q);
    cudaGetSymbolAddress((void**)&G,    g_G);
    cudaGetSymbolAddress((void**)&cn,   g_cnorm);
    cudaGetSymbolAddress((void**)&err,  g_err);
    cudaGetSymbolAddress((void**)&idx,  g_idx);

    dim3 blk(128);
    const int CB128 = 32 * 128 * 256;   // float4 count for COUT=128 combine

    // ---- encoder ----
    // e1: [32,3,128,128] -> A, k4 s2 p1, relu
    conv_k<4,4,2,1,4, 3,128,128, 64,64,64, false,true,true,false>
        <<<dim3(4, 16, 32), blk>>>(x, e_w1, e_b1, A, nullptr);
    // e2 split-2: A -> partials (G, Cc); combine -> Bf (relu+bias)
    conv4s_k<32, 64, 128><<<dim3(2, 32, 32), blk>>>(A, e_w2, G, Cc);
    comb_k<128, true><<<(CB128 + 255) / 256, 256>>>(G, Cc, e_b2, Bf, 0);
    // e3 (smem, unsplit): Bf -> Cc (bias, no relu)
    conv3m_k<128, 128, 128, 1, false, true>
        <<<dim3(1, 32, 32), blk>>>(Bf, e_w3, e_b3, Cc);
    // encoder res stack (x2): smem split-4 3x3 -> A partials; fused 1x1+residual
    conv3m_k<32, 128, 32, 4, true, false>
        <<<dim3(4, 8, 32), blk>>>(Cc, e_r1a, nullptr, A);
    conv1r4_k<<<dim3(1, 32, 32), blk>>>(A, e_r1b, Cc, Cc);
    conv3m_k<32, 128, 32, 4, true, false>
        <<<dim3(4, 8, 32), blk>>>(Cc, e_r2a, nullptr, A);
    conv1r4_k<<<dim3(1, 32, 32), blk>>>(A, e_r2b, Cc, Cc);
    // pre-VQ 1x1 (relu-in = final stack relu): Cc -> Z
    conv_k<1,1,1,0,4, 128,32,32, 64,32,32, true,false,true,false>
        <<<dim3(1, 16, 32), blk>>>(Cc, pre_w, pre_b, Z, nullptr);

    // ---- vector quantizer ----
    cnorm_kernel<<<2, 256>>>(cb, cn);
    vq_kernel<<<128, 256>>>(Z, cb, cn, idx, Q, err);
    stats_kernel<<<1, 512>>>(idx, err, out, out + (out_size - 1));

    // ---- decoder ----
    // d1 (smem, unsplit): Q -> G (bias, no relu)
    conv3m_k<64, 64, 128, 1, false, true>
        <<<dim3(1, 32, 32), blk>>>(Q, d_w1, d_b1, G);
    // decoder res stack (x2)
    conv3m_k<32, 128, 32, 4, true, false>
        <<<dim3(4, 8, 32), blk>>>(G, d_r1a, nullptr, A);
    conv1r4_k<<<dim3(1, 32, 32), blk>>>(A, d_r1b, G, G);
    conv3m_k<32, 128, 32, 4, true, false>
        <<<dim3(4, 8, 32), blk>>>(G, d_r2a, nullptr, A);
    conv1r4_k<<<dim3(1, 32, 32), blk>>>(A, d_r2b, G, G);
    // dt1: G -> A [32,64,64,64], relu-in + relu-out
    deconv_k<4, 128,32,32, 64,64,64, true,true,true>
        <<<dim3(4, 16, 32), blk>>>(G, dt_w1, dt_b1, A);
    // dt2: A -> x_recon into d_out+1 (misaligned base -> scalar stores)
    deconv_k<3, 64,64,64, 3,128,128, false,false,false>
        <<<dim3(16, 1, 32), blk>>>(A, dt_w2, dt_b2, out + 1);
}

// round 9
// speedup vs baseline: 1.3785x; 1.1239x over previous
#include <cuda_runtime.h>
#include <math.h>

// ---------------------------------------------------------------------------
// VQ-VAE forward, fp32. Round 9: smem staging extended to e2 (conv4m_k,
// unsplit, combine removed) and dt1 deconv (dc4m_k). Zero-border smem tiles
// make inner loops branch-free. Rest identical to R8.
// Output layout: [loss, x_recon(1572864), perplexity]
// ---------------------------------------------------------------------------

// Scratch (device globals; no allocation allowed)
__device__ float g_A[32u * 64 * 64 * 64];    // e1 out / dt1 out / res partials
__device__ float g_B[32u * 128 * 32 * 32];   // e2 out
__device__ float g_C[32u * 128 * 32 * 32];   // e3 out + encoder res stack
__device__ float g_Z[32u * 64 * 32 * 32];    // pre-VQ z
__device__ float g_Q[32u * 64 * 32 * 32];    // quantized q
__device__ float g_G[32u * 128 * 32 * 32];   // decoder stack
__device__ int   g_idx[32768];
__device__ float g_cnorm[512];
__device__ float g_err[32768];

// ---------------------------------------------------------------------------
// Generic direct conv (R2, proven): used for e1 (k4s2) and pre (1x1).
// ---------------------------------------------------------------------------
template <int KH, int KW, int S, int P, int TCO,
          int CIN, int HIN, int WIN, int COUT, int HOUT, int WOUT,
          bool IN_RELU, bool OUT_RELU, bool BIAS, bool ADD>
__global__ __launch_bounds__(128)
void conv_k(const float* __restrict__ in, const float* __restrict__ wt,
            const float* __restrict__ bs, float* __restrict__ out,
            const float* __restrict__ res)
{
    constexpr int TX   = 8;
    constexpr int WINW = (TX - 1) * S + KW;
    static_assert((HOUT * WOUT / TX) % 128 == 0, "tiles fill blocks");

    int tid = blockIdx.x * 128 + threadIdx.x;
    int ox0 = (tid * TX) % WOUT;
    int oy  = (tid * TX) / WOUT;
    int co0 = blockIdx.y * TCO;
    int b   = blockIdx.z;

    float acc[TCO][TX];
#pragma unroll
    for (int c = 0; c < TCO; c++) {
        float bv = BIAS ? __ldg(bs + co0 + c) : 0.f;
#pragma unroll
        for (int j = 0; j < TX; j++) acc[c][j] = bv;
    }

    const float* inb = in + (size_t)b * CIN * HIN * WIN;
    const int ixb = ox0 * S - P;

#pragma unroll 1
    for (int ci = 0; ci < CIN; ci++) {
        const float* ip  = inb + ci * HIN * WIN;
        const float* wci = wt + ((size_t)co0 * CIN + ci) * KH * KW;
#pragma unroll
        for (int ky = 0; ky < KH; ky++) {
            int iy = oy * S - P + ky;
            if (P > 0 && (iy < 0 || iy >= HIN)) continue;
            const float* row = ip + iy * WIN;
            float w[WINW];
            if constexpr (P == 0) {
                float4 v0 = *(const float4*)(row + ox0);
                float4 v1 = *(const float4*)(row + ox0 + 4);
                w[0] = v0.x; w[1] = v0.y; w[2] = v0.z; w[3] = v0.w;
                w[4] = v1.x; w[5] = v1.y; w[6] = v1.z; w[7] = v1.w;
            } else {
                w[0] = (ixb >= 0) ? row[ixb] : 0.f;
#pragma unroll
                for (int m = 0; m < (WINW - 2) / 4; m++) {
                    float4 v = *(const float4*)(row + ixb + 1 + 4 * m);
                    w[1 + 4 * m] = v.x; w[2 + 4 * m] = v.y;
                    w[3 + 4 * m] = v.z; w[4 + 4 * m] = v.w;
                }
                w[WINW - 1] = (ixb + WINW - 1 < WIN) ? row[ixb + WINW - 1] : 0.f;
            }
            if (IN_RELU) {
#pragma unroll
                for (int m = 0; m < WINW; m++) w[m] = fmaxf(w[m], 0.f);
            }
#pragma unroll
            for (int c = 0; c < TCO; c++) {
                const float* wp = wci + c * CIN * KH * KW + ky * KW;
                if constexpr (KW == 4) {
                    float4 wv = *(const float4*)wp;
                    float wk[4] = {wv.x, wv.y, wv.z, wv.w};
#pragma unroll
                    for (int kx = 0; kx < 4; kx++)
#pragma unroll
                        for (int j = 0; j < TX; j++)
                            acc[c][j] = fmaf(w[j * S + kx], wk[kx], acc[c][j]);
                } else {
#pragma unroll
                    for (int kx = 0; kx < KW; kx++) {
                        float wv = __ldg(wp + kx);
#pragma unroll
                        for (int j = 0; j < TX; j++)
                            acc[c][j] = fmaf(w[j * S + kx], wv, acc[c][j]);
                    }
                }
            }
        }
    }

#pragma unroll
    for (int c = 0; c < TCO; c++) {
        size_t o = (((size_t)b * COUT + (co0 + c)) * HOUT + oy) * WOUT + ox0;
        float v[TX];
#pragma unroll
        for (int j = 0; j < TX; j++) v[j] = acc[c][j];
        if (ADD) {
            float4 r0 = *(const float4*)(res + o);
            float4 r1 = *(const float4*)(res + o + 4);
            v[0] += r0.x; v[1] += r0.y; v[2] += r0.z; v[3] += r0.w;
            v[4] += r1.x; v[5] += r1.y; v[6] += r1.z; v[7] += r1.w;
        }
        if (OUT_RELU) {
#pragma unroll
            for (int j = 0; j < TX; j++) v[j] = fmaxf(v[j], 0.f);
        }
        *(float4*)(out + o)     = make_float4(v[0], v[1], v[2], v[3]);
        *(float4*)(out + o + 4) = make_float4(v[4], v[5], v[6], v[7]);
    }
}

// ---------------------------------------------------------------------------
// Smem-staged 3x3 s1 p1 conv on 32x32 maps (R8, proven).
// ---------------------------------------------------------------------------
template <int CINC, int CIN_TOTAL, int COUT, int NCH, bool IN_RELU, bool BIAS>
__global__ __launch_bounds__(128)
void conv3m_k(const float* __restrict__ in, const float* __restrict__ wt,
              const float* __restrict__ bs, float* __restrict__ out)
{
    __shared__ float sW[4 * 36];          // current 4 ci: [q][c*9 + tap]
    __shared__ float sI[4 * 36 * 32];     // 4 channels, rows padded to 36

    const int t     = threadIdx.x;
    const int ox0   = (t & 3) * 8;
    const int oy    = t >> 2;
    const int chunk = blockIdx.x;
    const int co0   = blockIdx.y * 4;
    const int b     = blockIdx.z;
    const int ci0   = chunk * CINC;

    float acc[4][8];
#pragma unroll
    for (int c = 0; c < 4; c++) {
        float bv = (NCH == 1 && BIAS) ? __ldg(bs + co0 + c) : 0.f;
#pragma unroll
        for (int j = 0; j < 8; j++) acc[c][j] = bv;
    }

    const float* inb = in + ((size_t)b * CIN_TOTAL + ci0) * 1024;

#pragma unroll 1
    for (int cc = 0; cc < CINC; cc += 4) {
        __syncthreads();
#pragma unroll
        for (int m = 0; m < 8; m++) {
            int idx = m * 128 + t;
            int q   = idx >> 8;
            int rem = idx & 255;
            int y   = rem >> 3;
            int xg  = (rem & 7) * 4;
            float4 v = *(const float4*)(inb + (cc + q) * 1024 + y * 32 + xg);
            if (IN_RELU) {
                v.x = fmaxf(v.x, 0.f); v.y = fmaxf(v.y, 0.f);
                v.z = fmaxf(v.z, 0.f); v.w = fmaxf(v.w, 0.f);
            }
            *(float4*)(sI + q * 1152 + y * 36 + xg) = v;
        }
        for (int i = t; i < 144; i += 128) {
            int q   = i / 36;
            int r   = i - q * 36;
            int c   = r / 9;
            int tap = r - c * 9;
            sW[i] =
                __ldg(wt + ((size_t)(co0 + c) * CIN_TOTAL + ci0 + cc + q) * 9 + tap);
        }
        __syncthreads();

#pragma unroll
        for (int q = 0; q < 4; q++) {
            const float* sw = sW + q * 36;
            const float* si = sI + q * 1152;
#pragma unroll
            for (int ky = 0; ky < 3; ky++) {
                int iy = oy - 1 + ky;
                if (iy < 0 || iy >= 32) continue;
                const float* row = si + iy * 36;
                float w[10];
                w[0] = (ox0 > 0) ? row[ox0 - 1] : 0.f;
                float4 v0 = *(const float4*)(row + ox0);
                float4 v1 = *(const float4*)(row + ox0 + 4);
                w[1] = v0.x; w[2] = v0.y; w[3] = v0.z; w[4] = v0.w;
                w[5] = v1.x; w[6] = v1.y; w[7] = v1.z; w[8] = v1.w;
                w[9] = (ox0 < 24) ? row[ox0 + 8] : 0.f;
#pragma unroll
                for (int c = 0; c < 4; c++) {
                    float w0 = sw[c * 9 + ky * 3];
                    float w1 = sw[c * 9 + ky * 3 + 1];
                    float w2 = sw[c * 9 + ky * 3 + 2];
#pragma unroll
                    for (int j = 0; j < 8; j++) {
                        acc[c][j] = fmaf(w[j],     w0, acc[c][j]);
                        acc[c][j] = fmaf(w[j + 1], w1, acc[c][j]);
                        acc[c][j] = fmaf(w[j + 2], w2, acc[c][j]);
                    }
                }
            }
        }
    }

#pragma unroll
    for (int c = 0; c < 4; c++) {
        size_t o;
        if (NCH == 1)
            o = (((size_t)b * COUT + (co0 + c)) * 32 + oy) * 32 + ox0;
        else
            o = (((size_t)(b * NCH + chunk) * COUT + (co0 + c)) * 32 + oy) * 32 + ox0;
        *(float4*)(out + o)     = make_float4(acc[c][0], acc[c][1], acc[c][2], acc[c][3]);
        *(float4*)(out + o + 4) = make_float4(acc[c][4], acc[c][5], acc[c][6], acc[c][7]);
    }
}

// ---------------------------------------------------------------------------
// NEW: smem-staged k4 s2 p1 conv (e2): in 64x64 -> out 32x32, bias + relu.
// Full input channel staged with zero borders (rows -1/64, cols 64..67) so
// the inner loop is branch-free. Block = full 32x32 output map, 4 co.
// ---------------------------------------------------------------------------
template <int CIN, int COUT>
__global__ __launch_bounds__(128)
void conv4m_k(const float* __restrict__ in, const float* __restrict__ wt,
              const float* __restrict__ bs, float* __restrict__ out)
{
    __shared__ float sI[66 * 68];   // rows iy=-1..64 at r=iy+1, cols 0..63 (+4 pad)
    __shared__ float sW[64];        // 4 co x 16 taps (current ci)

    const int t   = threadIdx.x;
    const int ox0 = (t & 3) * 8;
    const int oy  = t >> 2;
    const int co0 = blockIdx.y * 4;
    const int b   = blockIdx.z;
    const int ixb = ox0 * 2 - 1;

    // zero whole tile once; borders persist (staging writes rows 1..64, cols 0..63)
    for (int i = t; i < (66 * 68) / 4; i += 128)
        *(float4*)(sI + i * 4) = make_float4(0.f, 0.f, 0.f, 0.f);

    float acc[4][8];
#pragma unroll
    for (int c = 0; c < 4; c++) {
        float bv = __ldg(bs + co0 + c);
#pragma unroll
        for (int j = 0; j < 8; j++) acc[c][j] = bv;
    }

    const float* inb = in + (size_t)b * CIN * 4096;

#pragma unroll 1
    for (int ci = 0; ci < CIN; ci++) {
        __syncthreads();   // previous tile consumed (first iter: zero-fill done)
        const float* ip = inb + ci * 4096;
#pragma unroll
        for (int m = 0; m < 8; m++) {
            int idx = m * 128 + t;
            int y   = idx >> 4;
            int xg  = (idx & 15) * 4;
            float4 v = *(const float4*)(ip + y * 64 + xg);
            *(float4*)(sI + (y + 1) * 68 + xg) = v;
        }
        if (t < 16) {
            int c  = t >> 2;
            int ky = t & 3;
            *(float4*)(sW + t * 4) =
                *(const float4*)(wt + ((size_t)(co0 + c) * CIN + ci) * 16 + ky * 4);
        }
        __syncthreads();

#pragma unroll
        for (int ky = 0; ky < 4; ky++) {
            const float* row = sI + (oy * 2 + ky) * 68;   // buffer row = iy+1
            float w[18];
            w[0] = (ox0 > 0) ? row[ixb] : 0.f;
#pragma unroll
            for (int m = 0; m < 4; m++) {
                float4 v = *(const float4*)(row + 2 * ox0 + 4 * m);  // aligned
                w[1 + 4 * m] = v.x; w[2 + 4 * m] = v.y;
                w[3 + 4 * m] = v.z; w[4 + 4 * m] = v.w;
            }
            w[17] = row[ixb + 17];   // <= col 64: zero pad
#pragma unroll
            for (int c = 0; c < 4; c++) {
                float4 wv = *(const float4*)(sW + (c * 4 + ky) * 4);
                float wk[4] = {wv.x, wv.y, wv.z, wv.w};
#pragma unroll
                for (int kx = 0; kx < 4; kx++)
#pragma unroll
                    for (int j = 0; j < 8; j++)
                        acc[c][j] = fmaf(w[j * 2 + kx], wk[kx], acc[c][j]);
            }
        }
    }

#pragma unroll
    for (int c = 0; c < 4; c++) {
        size_t o = (((size_t)b * COUT + (co0 + c)) * 32 + oy) * 32 + ox0;
        float v[8];
#pragma unroll
        for (int j = 0; j < 8; j++) v[j] = fmaxf(acc[c][j], 0.f);
        *(float4*)(out + o)     = make_float4(v[0], v[1], v[2], v[3]);
        *(float4*)(out + o + 4) = make_float4(v[4], v[5], v[6], v[7]);
    }
}

// ---------------------------------------------------------------------------
// NEW: smem-staged ConvTranspose2d(k=4,s=2,p=1) for dt1: in 32x32 -> out 64x64,
// relu-in (at staging) + bias + relu-out. 4-ci chunks of 10 padded rows.
// ---------------------------------------------------------------------------
template <int CIN, int COUT>
__global__ __launch_bounds__(128)
void dc4m_k(const float* __restrict__ in, const float* __restrict__ wt,
            const float* __restrict__ bs, float* __restrict__ out)
{
    __shared__ float sI[4 * 360];   // 4 ci x 10 rows x 36 (cols 32..35 zero pad)
    __shared__ float sW[4 * 64];    // 4 ci x 4 co x 16 taps

    const int t   = threadIdx.x;
    const int bx  = blockIdx.x;
    const int ox0 = (t & 7) * 8;
    const int oy  = bx * 16 + (t >> 3);
    const int co0 = blockIdx.y * 4;
    const int b   = blockIdx.z;
    const int iy0 = bx * 8 - 1;        // global iy of staged row r=0
    const int ixb = ox0 / 2 - 1;
    const int oyp = oy & 1;

    float acc[4][8];
#pragma unroll
    for (int c = 0; c < 4; c++) {
        float bv = __ldg(bs + co0 + c);
#pragma unroll
        for (int j = 0; j < 8; j++) acc[c][j] = bv;
    }

    const float* inb = in + (size_t)b * CIN * 1024;

#pragma unroll 1
    for (int cc = 0; cc < CIN; cc += 4) {
        __syncthreads();
        // stage 4 ci x 10 rows x 9 float4 (last f4 = zero pad; OOB rows = zero)
        for (int i = t; i < 360; i += 128) {
            int q   = i / 90;
            int rem = i - q * 90;
            int r   = rem / 9;
            int xf  = rem - r * 9;
            int iy  = iy0 + r;
            float4 v = make_float4(0.f, 0.f, 0.f, 0.f);
            if (xf < 8 && iy >= 0 && iy < 32) {
                v = *(const float4*)(inb + (cc + q) * 1024 + iy * 32 + xf * 4);
                v.x = fmaxf(v.x, 0.f); v.y = fmaxf(v.y, 0.f);   // relu-in
                v.z = fmaxf(v.z, 0.f); v.w = fmaxf(v.w, 0.f);
            }
            *(float4*)(sI + q * 360 + r * 36 + xf * 4) = v;
        }
        // stage weights: 4 ci x 4 co x 4 ky float4
        for (int i = t; i < 64; i += 128) {
            int q  = i >> 4;
            int rm = i & 15;
            int c  = rm >> 2;
            int ky = rm & 3;
            *(float4*)(sW + i * 4) =
                *(const float4*)(wt + ((size_t)(co0 + c) * CIN + cc + q) * 16 + ky * 4);
        }
        __syncthreads();

#pragma unroll
        for (int q = 0; q < 4; q++) {
            const float* si = sI + q * 360;
#pragma unroll
            for (int tt = 0; tt < 2; tt++) {
                int ky = oyp + 2 * tt;
                int r  = ((oy - 2 + ky) >> 1) - iy0;
                const float* row = si + r * 36;
                float u[6];
                u[0] = (ixb >= 0) ? row[ixb] : 0.f;
                float4 v = *(const float4*)(row + ixb + 1);   // aligned (ox0/2 mult 4)
                u[1] = v.x; u[2] = v.y; u[3] = v.z; u[4] = v.w;
                u[5] = row[ixb + 5];                          // <= col 32: zero pad
#pragma unroll
                for (int c = 0; c < 4; c++) {
                    float4 wv = *(const float4*)(sW + (q * 16 + c * 4 + ky) * 4);
#pragma unroll
                    for (int j = 0; j < 8; j++) {
                        const int jo = j & 1;
                        const int sh = (j + 1) >> 1;
                        float wl = jo ? wv.y : wv.x;
                        float wh = jo ? wv.w : wv.z;
                        acc[c][j] = fmaf(u[sh],     wl, acc[c][j]);
                        acc[c][j] = fmaf(u[sh + 1], wh, acc[c][j]);
                    }
                }
            }
        }
    }

#pragma unroll
    for (int c = 0; c < 4; c++) {
        size_t o = (((size_t)b * COUT + (co0 + c)) * 64 + oy) * 64 + ox0;
        float v[8];
#pragma unroll
        for (int j = 0; j < 8; j++) v[j] = fmaxf(acc[c][j], 0.f);   // relu-out
        *(float4*)(out + o)     = make_float4(v[0], v[1], v[2], v[3]);
        *(float4*)(out + o + 4) = make_float4(v[4], v[5], v[6], v[7]);
    }
}

// ---------------------------------------------------------------------------
// Fused: sum 4 res3x3 partials -> relu -> 1x1 (32->128) -> + residual (R5).
// ---------------------------------------------------------------------------
__global__ __launch_bounds__(128)
void conv1r4_k(const float* __restrict__ part, const float* __restrict__ wt,
               const float* __restrict__ res, float* __restrict__ out)
{
    const int t   = threadIdx.x;
    const int ox0 = (t * 8) & 31;
    const int oy  = t >> 2;
    const int co0 = blockIdx.y * 4;
    const int b   = blockIdx.z;

    float acc[4][8];
#pragma unroll
    for (int c = 0; c < 4; c++)
#pragma unroll
        for (int j = 0; j < 8; j++) acc[c][j] = 0.f;

    const float* pb = part + (size_t)(b * 4) * 32 * 1024 + oy * 32 + ox0;

#pragma unroll 1
    for (int ci = 0; ci < 32; ci++) {
        const float* p = pb + ci * 1024;
        float w[8] = {0, 0, 0, 0, 0, 0, 0, 0};
#pragma unroll
        for (int ch = 0; ch < 4; ch++) {
            const float* pc = p + ch * 32 * 1024;
            float4 v0 = *(const float4*)pc;
            float4 v1 = *(const float4*)(pc + 4);
            w[0] += v0.x; w[1] += v0.y; w[2] += v0.z; w[3] += v0.w;
            w[4] += v1.x; w[5] += v1.y; w[6] += v1.z; w[7] += v1.w;
        }
#pragma unroll
        for (int m = 0; m < 8; m++) w[m] = fmaxf(w[m], 0.f);
        float wv0 = __ldg(wt + (co0 + 0) * 32 + ci);
        float wv1 = __ldg(wt + (co0 + 1) * 32 + ci);
        float wv2 = __ldg(wt + (co0 + 2) * 32 + ci);
        float wv3 = __ldg(wt + (co0 + 3) * 32 + ci);
#pragma unroll
        for (int j = 0; j < 8; j++) {
            acc[0][j] = fmaf(w[j], wv0, acc[0][j]);
            acc[1][j] = fmaf(w[j], wv1, acc[1][j]);
            acc[2][j] = fmaf(w[j], wv2, acc[2][j]);
            acc[3][j] = fmaf(w[j], wv3, acc[3][j]);
        }
    }

#pragma unroll
    for (int c = 0; c < 4; c++) {
        size_t o = (((size_t)b * 128 + (co0 + c)) * 32 + oy) * 32 + ox0;
        float4 r0 = *(const float4*)(res + o);
        float4 r1 = *(const float4*)(res + o + 4);
        *(float4*)(out + o) = make_float4(acc[c][0] + r0.x, acc[c][1] + r0.y,
                                          acc[c][2] + r0.z, acc[c][3] + r0.w);
        *(float4*)(out + o + 4) = make_float4(acc[c][4] + r1.x, acc[c][5] + r1.y,
                                              acc[c][6] + r1.z, acc[c][7] + r1.w);
    }
}

// ---------------------------------------------------------------------------
// ConvTranspose2d(k=4,s=2,p=1) direct gather (R2, proven) — used by dt2 only.
// ---------------------------------------------------------------------------
template <int TCO, int CIN, int HIN, int WIN, int COUT, int HOUT, int WOUT,
          bool IN_RELU, bool OUT_RELU, bool VEC_ST>
__global__ __launch_bounds__(128)
void deconv_k(const float* __restrict__ in, const float* __restrict__ wt,
              const float* __restrict__ bs, float* __restrict__ out)
{
    constexpr int TX = 8;
    static_assert((HOUT * WOUT / TX) % 128 == 0, "tiles fill blocks");

    int tid = blockIdx.x * 128 + threadIdx.x;
    int ox0 = (tid * TX) % WOUT;
    int oy  = (tid * TX) / WOUT;
    int co0 = blockIdx.y * TCO;
    int b   = blockIdx.z;

    float acc[TCO][TX];
#pragma unroll
    for (int c = 0; c < TCO; c++) {
        float bv = __ldg(bs + co0 + c);
#pragma unroll
        for (int j = 0; j < TX; j++) acc[c][j] = bv;
    }

    const int ixb = ox0 / 2 - 1;
    const int oyp = oy & 1;
    const float* inb = in + (size_t)b * CIN * HIN * WIN;

#pragma unroll 1
    for (int ci = 0; ci < CIN; ci++) {
        const float* ip  = inb + ci * HIN * WIN;
        const float* wci = wt + ((size_t)co0 * CIN + ci) * 16;
#pragma unroll
        for (int t = 0; t < 2; t++) {
            int ky = oyp + 2 * t;
            int iy = (oy - 2 + ky) >> 1;
            if (iy < 0 || iy >= HIN) continue;
            const float* row = ip + iy * WIN;
            float u[6];
            u[0] = (ixb >= 0) ? row[ixb] : 0.f;
            float4 v = *(const float4*)(row + ixb + 1);
            u[1] = v.x; u[2] = v.y; u[3] = v.z; u[4] = v.w;
            u[5] = (ixb + 5 < WIN) ? row[ixb + 5] : 0.f;
            if (IN_RELU) {
#pragma unroll
                for (int m = 0; m < 6; m++) u[m] = fmaxf(u[m], 0.f);
            }
#pragma unroll
            for (int c = 0; c < TCO; c++) {
                float4 wv = *(const float4*)(wci + c * CIN * 16 + ky * 4);
#pragma unroll
                for (int j = 0; j < TX; j++) {
                    const int jo = j & 1;
                    const int sh = (j + 1) >> 1;
                    float wl = jo ? wv.y : wv.x;
                    float wh = jo ? wv.w : wv.z;
                    acc[c][j] = fmaf(u[sh],     wl, acc[c][j]);
                    acc[c][j] = fmaf(u[sh + 1], wh, acc[c][j]);
                }
            }
        }
    }

#pragma unroll
    for (int c = 0; c < TCO; c++) {
        size_t o = (((size_t)b * COUT + (co0 + c)) * HOUT + oy) * WOUT + ox0;
        float v[TX];
#pragma unroll
        for (int j = 0; j < TX; j++) {
            v[j] = acc[c][j];
            if (OUT_RELU) v[j] = fmaxf(v[j], 0.f);
        }
        if constexpr (VEC_ST) {
            *(float4*)(out + o)     = make_float4(v[0], v[1], v[2], v[3]);
            *(float4*)(out + o + 4) = make_float4(v[4], v[5], v[6], v[7]);
        } else {
#pragma unroll
            for (int j = 0; j < TX; j++) out[o + j] = v[j];
        }
    }
}

// ---------------------------------------------------------------------------
// VQ (R2, proven)
// ---------------------------------------------------------------------------
__global__ void cnorm_kernel(const float* __restrict__ cb, float* __restrict__ cn)
{
    int k = blockIdx.x * blockDim.x + threadIdx.x;
    if (k >= 512) return;
    const float* c = cb + k * 64;
    float s = 0.f;
#pragma unroll
    for (int d = 0; d < 64; d++) s = fmaf(c[d], c[d], s);
    cn[k] = s;
}

__global__ __launch_bounds__(256)
void vq_kernel(const float* __restrict__ z, const float* __restrict__ cb,
               const float* __restrict__ cn, int* __restrict__ idx,
               float* __restrict__ q, float* __restrict__ err)
{
    int p = blockIdx.x * blockDim.x + threadIdx.x;  // 0..32767
    if (p >= 32768) return;
    int b = p >> 10, s = p & 1023;
    const float* zp = z + (size_t)b * 64 * 1024 + s;
    float zv[64];
#pragma unroll
    for (int d = 0; d < 64; d++) zv[d] = zp[d * 1024];

    float best = 3.4e38f;
    int bk = 0;
#pragma unroll 1
    for (int k = 0; k < 512; k++) {
        const float4* c4 = (const float4*)(cb + (size_t)k * 64);
        float d0 = 0.f, d1 = 0.f, d2 = 0.f, d3 = 0.f;
#pragma unroll
        for (int m = 0; m < 16; m++) {
            float4 cv = __ldg(c4 + m);
            d0 = fmaf(zv[4 * m],     cv.x, d0);
            d1 = fmaf(zv[4 * m + 1], cv.y, d1);
            d2 = fmaf(zv[4 * m + 2], cv.z, d2);
            d3 = fmaf(zv[4 * m + 3], cv.w, d3);
        }
        float dist = __ldg(cn + k) - 2.f * ((d0 + d1) + (d2 + d3));
        if (dist < best) { best = dist; bk = k; }   // strict <: first-min (jnp.argmin)
    }
    idx[p] = bk;
    float* qp = q + (size_t)b * 64 * 1024 + s;
    const float* c = cb + (size_t)bk * 64;
    float e = 0.f;
#pragma unroll
    for (int d = 0; d < 64; d++) {
        float cd = __ldg(c + d);
        qp[d * 1024] = cd;
        float df = zv[d] - cd;
        e = fmaf(df, df, e);
    }
    err[p] = e;
}

__global__ __launch_bounds__(512)
void stats_kernel(const int* __restrict__ idx, const float* __restrict__ err,
                  float* __restrict__ out0, float* __restrict__ outp)
{
    __shared__ int   h[512];
    __shared__ float sm[512];
    int t = threadIdx.x;
    h[t] = 0;
    float s = 0.f;
    __syncthreads();
    for (int i = t; i < 32768; i += 512) {
        atomicAdd(&h[idx[i]], 1);
        s += err[i];
    }
    sm[t] = s;
    __syncthreads();
    for (int off = 256; off > 0; off >>= 1) {
        if (t < off) sm[t] += sm[t + off];
        __syncthreads();
    }
    if (t == 0) out0[0] = 1.25f * sm[0] / 2097152.0f;   // (1+beta)*mse
    __syncthreads();
    float pr = (float)h[t] * (1.0f / 32768.0f);
    sm[t] = pr * logf(pr + 1e-10f);
    __syncthreads();
    for (int off = 256; off > 0; off >>= 1) {
        if (t < off) sm[t] += sm[t + off];
        __syncthreads();
    }
    if (t == 0) outp[0] = expf(-sm[0]);
}

// ---------------------------------------------------------------------------
// Launch
// ---------------------------------------------------------------------------
extern "C" void kernel_launch(void* const* d_in, const int* in_sizes, int n_in,
                              void* d_out, int out_size)
{
    const float* x     = (const float*)d_in[0];
    const float* e_w1  = (const float*)d_in[1];
    const float* e_b1  = (const float*)d_in[2];
    const float* e_w2  = (const float*)d_in[3];
    const float* e_b2  = (const float*)d_in[4];
    const float* e_w3  = (const float*)d_in[5];
    const float* e_b3  = (const float*)d_in[6];
    const float* e_r1a = (const float*)d_in[7];
    const float* e_r1b = (const float*)d_in[8];
    const float* e_r2a = (const float*)d_in[9];
    const float* e_r2b = (const float*)d_in[10];
    const float* pre_w = (const float*)d_in[11];
    const float* pre_b = (const float*)d_in[12];
    const float* cb    = (const float*)d_in[13];
    const float* d_w1  = (const float*)d_in[14];
    const float* d_b1  = (const float*)d_in[15];
    const float* d_r1a = (const float*)d_in[16];
    const float* d_r1b = (const float*)d_in[17];
    const float* d_r2a = (const float*)d_in[18];
    const float* d_r2b = (const float*)d_in[19];
    const float* dt_w1 = (const float*)d_in[20];
    const float* dt_b1 = (const float*)d_in[21];
    const float* dt_w2 = (const float*)d_in[22];
    const float* dt_b2 = (const float*)d_in[23];
    float* out = (float*)d_out;

    float *A, *Bf, *Cc, *Z, *Q, *G, *cn, *err;
    int *idx;
    cudaGetSymbolAddress((void**)&A,    g_A);
    cudaGetSymbolAddress((void**)&Bf,   g_B);
    cudaGetSymbolAddress((void**)&Cc,   g_C);
    cudaGetSymbolAddress((void**)&Z,    g_Z);
    cudaGetSymbolAddress((void**)&Q,    g_Q);
    cudaGetSymbolAddress((void**)&G,    g_G);
    cudaGetSymbolAddress((void**)&cn,   g_cnorm);
    cudaGetSymbolAddress((void**)&err,  g_err);
    cudaGetSymbolAddress((void**)&idx,  g_idx);

    dim3 blk(128);

    // ---- encoder ----
    // e1: [32,3,128,128] -> A, k4 s2 p1, relu
    conv_k<4,4,2,1,4, 3,128,128, 64,64,64, false,true,true,false>
        <<<dim3(4, 16, 32), blk>>>(x, e_w1, e_b1, A, nullptr);
    // e2 (smem, unsplit): A -> Bf, k4 s2 p1, bias+relu
    conv4m_k<64, 128><<<dim3(1, 32, 32), blk>>>(A, e_w2, e_b2, Bf);
    // e3 (smem, unsplit): Bf -> Cc (bias, no relu)
    conv3m_k<128, 128, 128, 1, false, true>
        <<<dim3(1, 32, 32), blk>>>(Bf, e_w3, e_b3, Cc);
    // encoder res stack (x2): smem split-4 3x3 -> A partials; fused 1x1+residual
    conv3m_k<32, 128, 32, 4, true, false>
        <<<dim3(4, 8, 32), blk>>>(Cc, e_r1a, nullptr, A);
    conv1r4_k<<<dim3(1, 32, 32), blk>>>(A, e_r1b, Cc, Cc);
    conv3m_k<32, 128, 32, 4, true, false>
        <<<dim3(4, 8, 32), blk>>>(Cc, e_r2a, nullptr, A);
    conv1r4_k<<<dim3(1, 32, 32), blk>>>(A, e_r2b, Cc, Cc);
    // pre-VQ 1x1 (relu-in = final stack relu): Cc -> Z
    conv_k<1,1,1,0,4, 128,32,32, 64,32,32, true,false,true,false>
        <<<dim3(1, 16, 32), blk>>>(Cc, pre_w, pre_b, Z, nullptr);

    // ---- vector quantizer ----
    cnorm_kernel<<<2, 256>>>(cb, cn);
    vq_kernel<<<128, 256>>>(Z, cb, cn, idx, Q, err);
    stats_kernel<<<1, 512>>>(idx, err, out, out + (out_size - 1));

    // ---- decoder ----
    // d1 (smem, unsplit): Q -> G (bias, no relu)
    conv3m_k<64, 64, 128, 1, false, true>
        <<<dim3(1, 32, 32), blk>>>(Q, d_w1, d_b1, G);
    // decoder res stack (x2)
    conv3m_k<32, 128, 32, 4, true, false>
        <<<dim3(4, 8, 32), blk>>>(G, d_r1a, nullptr, A);
    conv1r4_k<<<dim3(1, 32, 32), blk>>>(A, d_r1b, G, G);
    conv3m_k<32, 128, 32, 4, true, false>
        <<<dim3(4, 8, 32), blk>>>(G, d_r2a, nullptr, A);
    conv1r4_k<<<dim3(1, 32, 32), blk>>>(A, d_r2b, G, G);
    // dt1 (smem): G -> A [32,64,64,64], relu-in + bias + relu-out
    dc4m_k<128, 64><<<dim3(4, 16, 32), blk>>>(G, dt_w1, dt_b1, A);
    // dt2: A -> x_recon into d_out+1 (misaligned base -> scalar stores)
    deconv_k<3, 64,64,64, 3,128,128, false,false,false>
        <<<dim3(16, 1, 32), blk>>>(A, dt_w2, dt_b2, out + 1);
}

// round 10
// speedup vs baseline: 1.4107x; 1.0234x over previous
#include <cuda_runtime.h>
#include <math.h>

// ---------------------------------------------------------------------------
// VQ-VAE forward, fp32. Round 10: conv1r TCO=8 (halves partial re-read
// traffic), dt2 smem-staged deconv, VQ grid 256x128. Rest identical to R9.
// Output layout: [loss, x_recon(1572864), perplexity]
// ---------------------------------------------------------------------------

// Scratch (device globals; no allocation allowed)
__device__ float g_A[32u * 64 * 64 * 64];    // e1 out / dt1 out / res partials
__device__ float g_B[32u * 128 * 32 * 32];   // e2 out
__device__ float g_C[32u * 128 * 32 * 32];   // e3 out + encoder res stack
__device__ float g_Z[32u * 64 * 32 * 32];    // pre-VQ z
__device__ float g_Q[32u * 64 * 32 * 32];    // quantized q
__device__ float g_G[32u * 128 * 32 * 32];   // decoder stack
__device__ int   g_idx[32768];
__device__ float g_cnorm[512];
__device__ float g_err[32768];

// ---------------------------------------------------------------------------
// Generic direct conv (R2, proven): used for e1 (k4s2) and pre (1x1).
// ---------------------------------------------------------------------------
template <int KH, int KW, int S, int P, int TCO,
          int CIN, int HIN, int WIN, int COUT, int HOUT, int WOUT,
          bool IN_RELU, bool OUT_RELU, bool BIAS, bool ADD>
__global__ __launch_bounds__(128)
void conv_k(const float* __restrict__ in, const float* __restrict__ wt,
            const float* __restrict__ bs, float* __restrict__ out,
            const float* __restrict__ res)
{
    constexpr int TX   = 8;
    constexpr int WINW = (TX - 1) * S + KW;
    static_assert((HOUT * WOUT / TX) % 128 == 0, "tiles fill blocks");

    int tid = blockIdx.x * 128 + threadIdx.x;
    int ox0 = (tid * TX) % WOUT;
    int oy  = (tid * TX) / WOUT;
    int co0 = blockIdx.y * TCO;
    int b   = blockIdx.z;

    float acc[TCO][TX];
#pragma unroll
    for (int c = 0; c < TCO; c++) {
        float bv = BIAS ? __ldg(bs + co0 + c) : 0.f;
#pragma unroll
        for (int j = 0; j < TX; j++) acc[c][j] = bv;
    }

    const float* inb = in + (size_t)b * CIN * HIN * WIN;
    const int ixb = ox0 * S - P;

#pragma unroll 1
    for (int ci = 0; ci < CIN; ci++) {
        const float* ip  = inb + ci * HIN * WIN;
        const float* wci = wt + ((size_t)co0 * CIN + ci) * KH * KW;
#pragma unroll
        for (int ky = 0; ky < KH; ky++) {
            int iy = oy * S - P + ky;
            if (P > 0 && (iy < 0 || iy >= HIN)) continue;
            const float* row = ip + iy * WIN;
            float w[WINW];
            if constexpr (P == 0) {
                float4 v0 = *(const float4*)(row + ox0);
                float4 v1 = *(const float4*)(row + ox0 + 4);
                w[0] = v0.x; w[1] = v0.y; w[2] = v0.z; w[3] = v0.w;
                w[4] = v1.x; w[5] = v1.y; w[6] = v1.z; w[7] = v1.w;
            } else {
                w[0] = (ixb >= 0) ? row[ixb] : 0.f;
#pragma unroll
                for (int m = 0; m < (WINW - 2) / 4; m++) {
                    float4 v = *(const float4*)(row + ixb + 1 + 4 * m);
                    w[1 + 4 * m] = v.x; w[2 + 4 * m] = v.y;
                    w[3 + 4 * m] = v.z; w[4 + 4 * m] = v.w;
                }
                w[WINW - 1] = (ixb + WINW - 1 < WIN) ? row[ixb + WINW - 1] : 0.f;
            }
            if (IN_RELU) {
#pragma unroll
                for (int m = 0; m < WINW; m++) w[m] = fmaxf(w[m], 0.f);
            }
#pragma unroll
            for (int c = 0; c < TCO; c++) {
                const float* wp = wci + c * CIN * KH * KW + ky * KW;
                if constexpr (KW == 4) {
                    float4 wv = *(const float4*)wp;
                    float wk[4] = {wv.x, wv.y, wv.z, wv.w};
#pragma unroll
                    for (int kx = 0; kx < 4; kx++)
#pragma unroll
                        for (int j = 0; j < TX; j++)
                            acc[c][j] = fmaf(w[j * S + kx], wk[kx], acc[c][j]);
                } else {
#pragma unroll
                    for (int kx = 0; kx < KW; kx++) {
                        float wv = __ldg(wp + kx);
#pragma unroll
                        for (int j = 0; j < TX; j++)
                            acc[c][j] = fmaf(w[j * S + kx], wv, acc[c][j]);
                    }
                }
            }
        }
    }

#pragma unroll
    for (int c = 0; c < TCO; c++) {
        size_t o = (((size_t)b * COUT + (co0 + c)) * HOUT + oy) * WOUT + ox0;
        float v[TX];
#pragma unroll
        for (int j = 0; j < TX; j++) v[j] = acc[c][j];
        if (ADD) {
            float4 r0 = *(const float4*)(res + o);
            float4 r1 = *(const float4*)(res + o + 4);
            v[0] += r0.x; v[1] += r0.y; v[2] += r0.z; v[3] += r0.w;
            v[4] += r1.x; v[5] += r1.y; v[6] += r1.z; v[7] += r1.w;
        }
        if (OUT_RELU) {
#pragma unroll
            for (int j = 0; j < TX; j++) v[j] = fmaxf(v[j], 0.f);
        }
        *(float4*)(out + o)     = make_float4(v[0], v[1], v[2], v[3]);
        *(float4*)(out + o + 4) = make_float4(v[4], v[5], v[6], v[7]);
    }
}

// ---------------------------------------------------------------------------
// Smem-staged 3x3 s1 p1 conv on 32x32 maps (R8, proven).
// ---------------------------------------------------------------------------
template <int CINC, int CIN_TOTAL, int COUT, int NCH, bool IN_RELU, bool BIAS>
__global__ __launch_bounds__(128)
void conv3m_k(const float* __restrict__ in, const float* __restrict__ wt,
              const float* __restrict__ bs, float* __restrict__ out)
{
    __shared__ float sW[4 * 36];          // current 4 ci: [q][c*9 + tap]
    __shared__ float sI[4 * 36 * 32];     // 4 channels, rows padded to 36

    const int t     = threadIdx.x;
    const int ox0   = (t & 3) * 8;
    const int oy    = t >> 2;
    const int chunk = blockIdx.x;
    const int co0   = blockIdx.y * 4;
    const int b     = blockIdx.z;
    const int ci0   = chunk * CINC;

    float acc[4][8];
#pragma unroll
    for (int c = 0; c < 4; c++) {
        float bv = (NCH == 1 && BIAS) ? __ldg(bs + co0 + c) : 0.f;
#pragma unroll
        for (int j = 0; j < 8; j++) acc[c][j] = bv;
    }

    const float* inb = in + ((size_t)b * CIN_TOTAL + ci0) * 1024;

#pragma unroll 1
    for (int cc = 0; cc < CINC; cc += 4) {
        __syncthreads();
#pragma unroll
        for (int m = 0; m < 8; m++) {
            int idx = m * 128 + t;
            int q   = idx >> 8;
            int rem = idx & 255;
            int y   = rem >> 3;
            int xg  = (rem & 7) * 4;
            float4 v = *(const float4*)(inb + (cc + q) * 1024 + y * 32 + xg);
            if (IN_RELU) {
                v.x = fmaxf(v.x, 0.f); v.y = fmaxf(v.y, 0.f);
                v.z = fmaxf(v.z, 0.f); v.w = fmaxf(v.w, 0.f);
            }
            *(float4*)(sI + q * 1152 + y * 36 + xg) = v;
        }
        for (int i = t; i < 144; i += 128) {
            int q   = i / 36;
            int r   = i - q * 36;
            int c   = r / 9;
            int tap = r - c * 9;
            sW[i] =
                __ldg(wt + ((size_t)(co0 + c) * CIN_TOTAL + ci0 + cc + q) * 9 + tap);
        }
        __syncthreads();

#pragma unroll
        for (int q = 0; q < 4; q++) {
            const float* sw = sW + q * 36;
            const float* si = sI + q * 1152;
#pragma unroll
            for (int ky = 0; ky < 3; ky++) {
                int iy = oy - 1 + ky;
                if (iy < 0 || iy >= 32) continue;
                const float* row = si + iy * 36;
                float w[10];
                w[0] = (ox0 > 0) ? row[ox0 - 1] : 0.f;
                float4 v0 = *(const float4*)(row + ox0);
                float4 v1 = *(const float4*)(row + ox0 + 4);
                w[1] = v0.x; w[2] = v0.y; w[3] = v0.z; w[4] = v0.w;
                w[5] = v1.x; w[6] = v1.y; w[7] = v1.z; w[8] = v1.w;
                w[9] = (ox0 < 24) ? row[ox0 + 8] : 0.f;
#pragma unroll
                for (int c = 0; c < 4; c++) {
                    float w0 = sw[c * 9 + ky * 3];
                    float w1 = sw[c * 9 + ky * 3 + 1];
                    float w2 = sw[c * 9 + ky * 3 + 2];
#pragma unroll
                    for (int j = 0; j < 8; j++) {
                        acc[c][j] = fmaf(w[j],     w0, acc[c][j]);
                        acc[c][j] = fmaf(w[j + 1], w1, acc[c][j]);
                        acc[c][j] = fmaf(w[j + 2], w2, acc[c][j]);
                    }
                }
            }
        }
    }

#pragma unroll
    for (int c = 0; c < 4; c++) {
        size_t o;
        if (NCH == 1)
            o = (((size_t)b * COUT + (co0 + c)) * 32 + oy) * 32 + ox0;
        else
            o = (((size_t)(b * NCH + chunk) * COUT + (co0 + c)) * 32 + oy) * 32 + ox0;
        *(float4*)(out + o)     = make_float4(acc[c][0], acc[c][1], acc[c][2], acc[c][3]);
        *(float4*)(out + o + 4) = make_float4(acc[c][4], acc[c][5], acc[c][6], acc[c][7]);
    }
}

// ---------------------------------------------------------------------------
// Smem-staged k4 s2 p1 conv (e2) (R9, proven).
// ---------------------------------------------------------------------------
template <int CIN, int COUT>
__global__ __launch_bounds__(128)
void conv4m_k(const float* __restrict__ in, const float* __restrict__ wt,
              const float* __restrict__ bs, float* __restrict__ out)
{
    __shared__ float sI[66 * 68];
    __shared__ float sW[64];

    const int t   = threadIdx.x;
    const int ox0 = (t & 3) * 8;
    const int oy  = t >> 2;
    const int co0 = blockIdx.y * 4;
    const int b   = blockIdx.z;
    const int ixb = ox0 * 2 - 1;

    for (int i = t; i < (66 * 68) / 4; i += 128)
        *(float4*)(sI + i * 4) = make_float4(0.f, 0.f, 0.f, 0.f);

    float acc[4][8];
#pragma unroll
    for (int c = 0; c < 4; c++) {
        float bv = __ldg(bs + co0 + c);
#pragma unroll
        for (int j = 0; j < 8; j++) acc[c][j] = bv;
    }

    const float* inb = in + (size_t)b * CIN * 4096;

#pragma unroll 1
    for (int ci = 0; ci < CIN; ci++) {
        __syncthreads();
        const float* ip = inb + ci * 4096;
#pragma unroll
        for (int m = 0; m < 8; m++) {
            int idx = m * 128 + t;
            int y   = idx >> 4;
            int xg  = (idx & 15) * 4;
            float4 v = *(const float4*)(ip + y * 64 + xg);
            *(float4*)(sI + (y + 1) * 68 + xg) = v;
        }
        if (t < 16) {
            int c  = t >> 2;
            int ky = t & 3;
            *(float4*)(sW + t * 4) =
                *(const float4*)(wt + ((size_t)(co0 + c) * CIN + ci) * 16 + ky * 4);
        }
        __syncthreads();

#pragma unroll
        for (int ky = 0; ky < 4; ky++) {
            const float* row = sI + (oy * 2 + ky) * 68;
            float w[18];
            w[0] = (ox0 > 0) ? row[ixb] : 0.f;
#pragma unroll
            for (int m = 0; m < 4; m++) {
                float4 v = *(const float4*)(row + 2 * ox0 + 4 * m);
                w[1 + 4 * m] = v.x; w[2 + 4 * m] = v.y;
                w[3 + 4 * m] = v.z; w[4 + 4 * m] = v.w;
            }
            w[17] = row[ixb + 17];
#pragma unroll
            for (int c = 0; c < 4; c++) {
                float4 wv = *(const float4*)(sW + (c * 4 + ky) * 4);
                float wk[4] = {wv.x, wv.y, wv.z, wv.w};
#pragma unroll
                for (int kx = 0; kx < 4; kx++)
#pragma unroll
                    for (int j = 0; j < 8; j++)
                        acc[c][j] = fmaf(w[j * 2 + kx], wk[kx], acc[c][j]);
            }
        }
    }

#pragma unroll
    for (int c = 0; c < 4; c++) {
        size_t o = (((size_t)b * COUT + (co0 + c)) * 32 + oy) * 32 + ox0;
        float v[8];
#pragma unroll
        for (int j = 0; j < 8; j++) v[j] = fmaxf(acc[c][j], 0.f);
        *(float4*)(out + o)     = make_float4(v[0], v[1], v[2], v[3]);
        *(float4*)(out + o + 4) = make_float4(v[4], v[5], v[6], v[7]);
    }
}

// ---------------------------------------------------------------------------
// Smem-staged ConvTranspose2d(k=4,s=2,p=1) for dt1 (R9, proven).
// ---------------------------------------------------------------------------
template <int CIN, int COUT>
__global__ __launch_bounds__(128)
void dc4m_k(const float* __restrict__ in, const float* __restrict__ wt,
            const float* __restrict__ bs, float* __restrict__ out)
{
    __shared__ float sI[4 * 360];
    __shared__ float sW[4 * 64];

    const int t   = threadIdx.x;
    const int bx  = blockIdx.x;
    const int ox0 = (t & 7) * 8;
    const int oy  = bx * 16 + (t >> 3);
    const int co0 = blockIdx.y * 4;
    const int b   = blockIdx.z;
    const int iy0 = bx * 8 - 1;
    const int ixb = ox0 / 2 - 1;
    const int oyp = oy & 1;

    float acc[4][8];
#pragma unroll
    for (int c = 0; c < 4; c++) {
        float bv = __ldg(bs + co0 + c);
#pragma unroll
        for (int j = 0; j < 8; j++) acc[c][j] = bv;
    }

    const float* inb = in + (size_t)b * CIN * 1024;

#pragma unroll 1
    for (int cc = 0; cc < CIN; cc += 4) {
        __syncthreads();
        for (int i = t; i < 360; i += 128) {
            int q   = i / 90;
            int rem = i - q * 90;
            int r   = rem / 9;
            int xf  = rem - r * 9;
            int iy  = iy0 + r;
            float4 v = make_float4(0.f, 0.f, 0.f, 0.f);
            if (xf < 8 && iy >= 0 && iy < 32) {
                v = *(const float4*)(inb + (cc + q) * 1024 + iy * 32 + xf * 4);
                v.x = fmaxf(v.x, 0.f); v.y = fmaxf(v.y, 0.f);
                v.z = fmaxf(v.z, 0.f); v.w = fmaxf(v.w, 0.f);
            }
            *(float4*)(sI + q * 360 + r * 36 + xf * 4) = v;
        }
        for (int i = t; i < 64; i += 128) {
            int q  = i >> 4;
            int rm = i & 15;
            int c  = rm >> 2;
            int ky = rm & 3;
            *(float4*)(sW + i * 4) =
                *(const float4*)(wt + ((size_t)(co0 + c) * CIN + cc + q) * 16 + ky * 4);
        }
        __syncthreads();

#pragma unroll
        for (int q = 0; q < 4; q++) {
            const float* si = sI + q * 360;
#pragma unroll
            for (int tt = 0; tt < 2; tt++) {
                int ky = oyp + 2 * tt;
                int r  = ((oy - 2 + ky) >> 1) - iy0;
                const float* row = si + r * 36;
                float u[6];
                u[0] = (ixb >= 0) ? row[ixb] : 0.f;
                float4 v = *(const float4*)(row + ixb + 1);
                u[1] = v.x; u[2] = v.y; u[3] = v.z; u[4] = v.w;
                u[5] = row[ixb + 5];
#pragma unroll
                for (int c = 0; c < 4; c++) {
                    float4 wv = *(const float4*)(sW + (q * 16 + c * 4 + ky) * 4);
#pragma unroll
                    for (int j = 0; j < 8; j++) {
                        const int jo = j & 1;
                        const int sh = (j + 1) >> 1;
                        float wl = jo ? wv.y : wv.x;
                        float wh = jo ? wv.w : wv.z;
                        acc[c][j] = fmaf(u[sh],     wl, acc[c][j]);
                        acc[c][j] = fmaf(u[sh + 1], wh, acc[c][j]);
                    }
                }
            }
        }
    }

#pragma unroll
    for (int c = 0; c < 4; c++) {
        size_t o = (((size_t)b * COUT + (co0 + c)) * 64 + oy) * 64 + ox0;
        float v[8];
#pragma unroll
        for (int j = 0; j < 8; j++) v[j] = fmaxf(acc[c][j], 0.f);
        *(float4*)(out + o)     = make_float4(v[0], v[1], v[2], v[3]);
        *(float4*)(out + o + 4) = make_float4(v[4], v[5], v[6], v[7]);
    }
}

// ---------------------------------------------------------------------------
// NEW: smem-staged ConvTranspose2d(k=4,s=2,p=1) for dt2: in 64x64 -> out
// 128x128, COUT=3, no relu. Scalar stores (out base misaligned).
// Block: 8 out rows x 128 cols; 4-ci chunks of 6 padded rows.
// ---------------------------------------------------------------------------
template <int CIN>
__global__ __launch_bounds__(128)
void dc4m3_k(const float* __restrict__ in, const float* __restrict__ wt,
             const float* __restrict__ bs, float* __restrict__ out)
{
    __shared__ float sI[4 * 408];   // 4 ci x 6 rows x 68 (cols 64..67 zero pad)
    __shared__ float sW[4 * 48];    // 4 ci x 3 co x 16 taps

    const int t   = threadIdx.x;
    const int bx  = blockIdx.x;
    const int ox0 = (t & 15) * 8;
    const int oy  = bx * 8 + (t >> 4);
    const int b   = blockIdx.z;
    const int iy0 = bx * 4 - 1;        // global iy of staged row r=0
    const int ixb = ox0 / 2 - 1;
    const int oyp = oy & 1;

    float acc[3][8];
#pragma unroll
    for (int c = 0; c < 3; c++) {
        float bv = __ldg(bs + c);
#pragma unroll
        for (int j = 0; j < 8; j++) acc[c][j] = bv;
    }

    const float* inb = in + (size_t)b * CIN * 4096;

#pragma unroll 1
    for (int cc = 0; cc < CIN; cc += 4) {
        __syncthreads();
        // stage 4 ci x 6 rows x 17 float4 (last f4 zero pad; OOB rows zero)
        for (int i = t; i < 408; i += 128) {
            int q   = i / 102;
            int rem = i - q * 102;
            int r   = rem / 17;
            int xf  = rem - r * 17;
            int iy  = iy0 + r;
            float4 v = make_float4(0.f, 0.f, 0.f, 0.f);
            if (xf < 16 && iy >= 0 && iy < 64)
                v = *(const float4*)(inb + (cc + q) * 4096 + iy * 64 + xf * 4);
            *(float4*)(sI + q * 408 + r * 68 + xf * 4) = v;
        }
        // stage weights: 4 ci x 3 co x 4 ky float4
        for (int i = t; i < 48; i += 128) {
            int q  = i / 12;
            int rm = i - q * 12;
            int c  = rm >> 2;
            int ky = rm & 3;
            *(float4*)(sW + (q * 48 + c * 16 + ky * 4)) =
                *(const float4*)(wt + ((size_t)c * CIN + cc + q) * 16 + ky * 4);
        }
        __syncthreads();

#pragma unroll
        for (int q = 0; q < 4; q++) {
            const float* si = sI + q * 408;
#pragma unroll
            for (int tt = 0; tt < 2; tt++) {
                int ky = oyp + 2 * tt;
                int r  = ((oy - 2 + ky) >> 1) - iy0;
                const float* row = si + r * 68;
                float u[6];
                u[0] = (ixb >= 0) ? row[ixb] : 0.f;
                float4 v = *(const float4*)(row + ixb + 1);   // aligned (ox0/2 mult 4)
                u[1] = v.x; u[2] = v.y; u[3] = v.z; u[4] = v.w;
                u[5] = row[ixb + 5];                          // col<=64: zero pad
#pragma unroll
                for (int c = 0; c < 3; c++) {
                    float4 wv = *(const float4*)(sW + q * 48 + c * 16 + ky * 4);
#pragma unroll
                    for (int j = 0; j < 8; j++) {
                        const int jo = j & 1;
                        const int sh = (j + 1) >> 1;
                        float wl = jo ? wv.y : wv.x;
                        float wh = jo ? wv.w : wv.z;
                        acc[c][j] = fmaf(u[sh],     wl, acc[c][j]);
                        acc[c][j] = fmaf(u[sh + 1], wh, acc[c][j]);
                    }
                }
            }
        }
    }

#pragma unroll
    for (int c = 0; c < 3; c++) {
        size_t o = (((size_t)b * 3 + c) * 128 + oy) * 128 + ox0;
#pragma unroll
        for (int j = 0; j < 8; j++) out[o + j] = acc[c][j];   // misaligned base
    }
}

// ---------------------------------------------------------------------------
// Fused: sum 4 res3x3 partials -> relu -> 1x1 (32->128) -> + residual.
// Round 10: TCO=8 (halves partial re-read traffic), weights in smem.
// ---------------------------------------------------------------------------
__global__ __launch_bounds__(128)
void conv1r8_k(const float* __restrict__ part, const float* __restrict__ wt,
               const float* __restrict__ res, float* __restrict__ out)
{
    __shared__ float sW[8 * 32];   // [c][ci]

    const int t   = threadIdx.x;
    const int ox0 = (t & 3) * 8;
    const int oy  = t >> 2;
    const int co0 = blockIdx.y * 8;
    const int b   = blockIdx.z;

    // stage 8x32 weights once
    for (int i = t; i < 256; i += 128)
        sW[i] = __ldg(wt + (co0 + (i >> 5)) * 32 + (i & 31));
    __syncthreads();

    float acc[8][8];
#pragma unroll
    for (int c = 0; c < 8; c++)
#pragma unroll
        for (int j = 0; j < 8; j++) acc[c][j] = 0.f;

    const float* pb = part + (size_t)(b * 4) * 32 * 1024 + oy * 32 + ox0;

#pragma unroll 1
    for (int ci = 0; ci < 32; ci++) {
        const float* p = pb + ci * 1024;
        float w[8] = {0, 0, 0, 0, 0, 0, 0, 0};
#pragma unroll
        for (int ch = 0; ch < 4; ch++) {
            const float* pc = p + ch * 32 * 1024;
            float4 v0 = *(const float4*)pc;
            float4 v1 = *(const float4*)(pc + 4);
            w[0] += v0.x; w[1] += v0.y; w[2] += v0.z; w[3] += v0.w;
            w[4] += v1.x; w[5] += v1.y; w[6] += v1.z; w[7] += v1.w;
        }
#pragma unroll
        for (int m = 0; m < 8; m++) w[m] = fmaxf(w[m], 0.f);
#pragma unroll
        for (int c = 0; c < 8; c++) {
            float wv = sW[c * 32 + ci];
#pragma unroll
            for (int j = 0; j < 8; j++)
                acc[c][j] = fmaf(w[j], wv, acc[c][j]);
        }
    }

#pragma unroll
    for (int c = 0; c < 8; c++) {
        size_t o = (((size_t)b * 128 + (co0 + c)) * 32 + oy) * 32 + ox0;
        float4 r0 = *(const float4*)(res + o);
        float4 r1 = *(const float4*)(res + o + 4);
        *(float4*)(out + o) = make_float4(acc[c][0] + r0.x, acc[c][1] + r0.y,
                                          acc[c][2] + r0.z, acc[c][3] + r0.w);
        *(float4*)(out + o + 4) = make_float4(acc[c][4] + r1.x, acc[c][5] + r1.y,
                                              acc[c][6] + r1.z, acc[c][7] + r1.w);
    }
}

// ---------------------------------------------------------------------------
// VQ (R2, proven; grid now 256x128)
// ---------------------------------------------------------------------------
__global__ void cnorm_kernel(const float* __restrict__ cb, float* __restrict__ cn)
{
    int k = blockIdx.x * blockDim.x + threadIdx.x;
    if (k >= 512) return;
    const float* c = cb + k * 64;
    float s = 0.f;
#pragma unroll
    for (int d = 0; d < 64; d++) s = fmaf(c[d], c[d], s);
    cn[k] = s;
}

__global__ __launch_bounds__(128)
void vq_kernel(const float* __restrict__ z, const float* __restrict__ cb,
               const float* __restrict__ cn, int* __restrict__ idx,
               float* __restrict__ q, float* __restrict__ err)
{
    int p = blockIdx.x * blockDim.x + threadIdx.x;  // 0..32767
    if (p >= 32768) return;
    int b = p >> 10, s = p & 1023;
    const float* zp = z + (size_t)b * 64 * 1024 + s;
    float zv[64];
#pragma unroll
    for (int d = 0; d < 64; d++) zv[d] = zp[d * 1024];

    float best = 3.4e38f;
    int bk = 0;
#pragma unroll 1
    for (int k = 0; k < 512; k++) {
        const float4* c4 = (const float4*)(cb + (size_t)k * 64);
        float d0 = 0.f, d1 = 0.f, d2 = 0.f, d3 = 0.f;
#pragma unroll
        for (int m = 0; m < 16; m++) {
            float4 cv = __ldg(c4 + m);
            d0 = fmaf(zv[4 * m],     cv.x, d0);
            d1 = fmaf(zv[4 * m + 1], cv.y, d1);
            d2 = fmaf(zv[4 * m + 2], cv.z, d2);
            d3 = fmaf(zv[4 * m + 3], cv.w, d3);
        }
        float dist = __ldg(cn + k) - 2.f * ((d0 + d1) + (d2 + d3));
        if (dist < best) { best = dist; bk = k; }   // strict <: first-min (jnp.argmin)
    }
    idx[p] = bk;
    float* qp = q + (size_t)b * 64 * 1024 + s;
    const float* c = cb + (size_t)bk * 64;
    float e = 0.f;
#pragma unroll
    for (int d = 0; d < 64; d++) {
        float cd = __ldg(c + d);
        qp[d * 1024] = cd;
        float df = zv[d] - cd;
        e = fmaf(df, df, e);
    }
    err[p] = e;
}

__global__ __launch_bounds__(512)
void stats_kernel(const int* __restrict__ idx, const float* __restrict__ err,
                  float* __restrict__ out0, float* __restrict__ outp)
{
    __shared__ int   h[512];
    __shared__ float sm[512];
    int t = threadIdx.x;
    h[t] = 0;
    float s = 0.f;
    __syncthreads();
    for (int i = t; i < 32768; i += 512) {
        atomicAdd(&h[idx[i]], 1);
        s += err[i];
    }
    sm[t] = s;
    __syncthreads();
    for (int off = 256; off > 0; off >>= 1) {
        if (t < off) sm[t] += sm[t + off];
        __syncthreads();
    }
    if (t == 0) out0[0] = 1.25f * sm[0] / 2097152.0f;   // (1+beta)*mse
    __syncthreads();
    float pr = (float)h[t] * (1.0f / 32768.0f);
    sm[t] = pr * logf(pr + 1e-10f);
    __syncthreads();
    for (int off = 256; off > 0; off >>= 1) {
        if (t < off) sm[t] += sm[t + off];
        __syncthreads();
    }
    if (t == 0) outp[0] = expf(-sm[0]);
}

// ---------------------------------------------------------------------------
// Launch
// ---------------------------------------------------------------------------
extern "C" void kernel_launch(void* const* d_in, const int* in_sizes, int n_in,
                              void* d_out, int out_size)
{
    const float* x     = (const float*)d_in[0];
    const float* e_w1  = (const float*)d_in[1];
    const float* e_b1  = (const float*)d_in[2];
    const float* e_w2  = (const float*)d_in[3];
    const float* e_b2  = (const float*)d_in[4];
    const float* e_w3  = (const float*)d_in[5];
    const float* e_b3  = (const float*)d_in[6];
    const float* e_r1a = (const float*)d_in[7];
    const float* e_r1b = (const float*)d_in[8];
    const float* e_r2a = (const float*)d_in[9];
    const float* e_r2b = (const float*)d_in[10];
    const float* pre_w = (const float*)d_in[11];
    const float* pre_b = (const float*)d_in[12];
    const float* cb    = (const float*)d_in[13];
    const float* d_w1  = (const float*)d_in[14];
    const float* d_b1  = (const float*)d_in[15];
    const float* d_r1a = (const float*)d_in[16];
    const float* d_r1b = (const float*)d_in[17];
    const float* d_r2a = (const float*)d_in[18];
    const float* d_r2b = (const float*)d_in[19];
    const float* dt_w1 = (const float*)d_in[20];
    const float* dt_b1 = (const float*)d_in[21];
    const float* dt_w2 = (const float*)d_in[22];
    const float* dt_b2 = (const float*)d_in[23];
    float* out = (float*)d_out;

    float *A, *Bf, *Cc, *Z, *Q, *G, *cn, *err;
    int *idx;
    cudaGetSymbolAddress((void**)&A,    g_A);
    cudaGetSymbolAddress((void**)&Bf,   g_B);
    cudaGetSymbolAddress((void**)&Cc,   g_C);
    cudaGetSymbolAddress((void**)&Z,    g_Z);
    cudaGetSymbolAddress((void**)&Q,    g_Q);
    cudaGetSymbolAddress((void**)&G,    g_G);
    cudaGetSymbolAddress((void**)&cn,   g_cnorm);
    cudaGetSymbolAddress((void**)&err,  g_err);
    cudaGetSymbolAddress((void**)&idx,  g_idx);

    dim3 blk(128);

    // ---- encoder ----
    conv_k<4,4,2,1,4, 3,128,128, 64,64,64, false,true,true,false>
        <<<dim3(4, 16, 32), blk>>>(x, e_w1, e_b1, A, nullptr);
    conv4m_k<64, 128><<<dim3(1, 32, 32), blk>>>(A, e_w2, e_b2, Bf);
    conv3m_k<128, 128, 128, 1, false, true>
        <<<dim3(1, 32, 32), blk>>>(Bf, e_w3, e_b3, Cc);
    conv3m_k<32, 128, 32, 4, true, false>
        <<<dim3(4, 8, 32), blk>>>(Cc, e_r1a, nullptr, A);
    conv1r8_k<<<dim3(1, 16, 32), blk>>>(A, e_r1b, Cc, Cc);
    conv3m_k<32, 128, 32, 4, true, false>
        <<<dim3(4, 8, 32), blk>>>(Cc, e_r2a, nullptr, A);
    conv1r8_k<<<dim3(1, 16, 32), blk>>>(A, e_r2b, Cc, Cc);
    conv_k<1,1,1,0,4, 128,32,32, 64,32,32, true,false,true,false>
        <<<dim3(1, 16, 32), blk>>>(Cc, pre_w, pre_b, Z, nullptr);

    // ---- vector quantizer ----
    cnorm_kernel<<<2, 256>>>(cb, cn);
    vq_kernel<<<256, 128>>>(Z, cb, cn, idx, Q, err);
    stats_kernel<<<1, 512>>>(idx, err, out, out + (out_size - 1));

    // ---- decoder ----
    conv3m_k<64, 64, 128, 1, false, true>
        <<<dim3(1, 32, 32), blk>>>(Q, d_w1, d_b1, G);
    conv3m_k<32, 128, 32, 4, true, false>
        <<<dim3(4, 8, 32), blk>>>(G, d_r1a, nullptr, A);
    conv1r8_k<<<dim3(1, 16, 32), blk>>>(A, d_r1b, G, G);
    conv3m_k<32, 128, 32, 4, true, false>
        <<<dim3(4, 8, 32), blk>>>(G, d_r2a, nullptr, A);
    conv1r8_k<<<dim3(1, 16, 32), blk>>>(A, d_r2b, G, G);
    dc4m_k<128, 64><<<dim3(4, 16, 32), blk>>>(G, dt_w1, dt_b1, A);
    // dt2 (smem): A -> x_recon into d_out+1
    dc4m3_k<64><<<dim3(16, 1, 32), blk>>>(A, dt_w2, dt_b2, out + 1);
}

// round 11
// speedup vs baseline: 1.4164x; 1.0040x over previous
#include <cuda_runtime.h>
#include <math.h>

// ---------------------------------------------------------------------------
// VQ-VAE forward, fp32. Round 10: conv1r TCO=8 (halves partial re-read
// traffic), dt2 smem-staged deconv, VQ grid 256x128. Rest identical to R9.
// Output layout: [loss, x_recon(1572864), perplexity]
// ---------------------------------------------------------------------------

// Scratch (device globals; no allocation allowed)
__device__ float g_A[32u * 64 * 64 * 64];    // e1 out / dt1 out / res partials
__device__ float g_B[32u * 128 * 32 * 32];   // e2 out
__device__ float g_C[32u * 128 * 32 * 32];   // e3 out + encoder res stack
__device__ float g_Z[32u * 64 * 32 * 32];    // pre-VQ z
__device__ float g_Q[32u * 64 * 32 * 32];    // quantized q
__device__ float g_G[32u * 128 * 32 * 32];   // decoder stack
__device__ int   g_idx[32768];
__device__ float g_cnorm[512];
__device__ float g_err[32768];

// ---------------------------------------------------------------------------
// Generic direct conv (R2, proven): used for e1 (k4s2) and pre (1x1).
// ---------------------------------------------------------------------------
template <int KH, int KW, int S, int P, int TCO,
          int CIN, int HIN, int WIN, int COUT, int HOUT, int WOUT,
          bool IN_RELU, bool OUT_RELU, bool BIAS, bool ADD>
__global__ __launch_bounds__(128)
void conv_k(const float* __restrict__ in, const float* __restrict__ wt,
            const float* __restrict__ bs, float* __restrict__ out,
            const float* __restrict__ res)
{
    constexpr int TX   = 8;
    constexpr int WINW = (TX - 1) * S + KW;
    static_assert((HOUT * WOUT / TX) % 128 == 0, "tiles fill blocks");

    int tid = blockIdx.x * 128 + threadIdx.x;
    int ox0 = (tid * TX) % WOUT;
    int oy  = (tid * TX) / WOUT;
    int co0 = blockIdx.y * TCO;
    int b   = blockIdx.z;

    float acc[TCO][TX];
#pragma unroll
    for (int c = 0; c < TCO; c++) {
        float bv = BIAS ? __ldg(bs + co0 + c) : 0.f;
#pragma unroll
        for (int j = 0; j < TX; j++) acc[c][j] = bv;
    }

    const float* inb = in + (size_t)b * CIN * HIN * WIN;
    const int ixb = ox0 * S - P;

#pragma unroll 1
    for (int ci = 0; ci < CIN; ci++) {
        const float* ip  = inb + ci * HIN * WIN;
        const float* wci = wt + ((size_t)co0 * CIN + ci) * KH * KW;
#pragma unroll
        for (int ky = 0; ky < KH; ky++) {
            int iy = oy * S - P + ky;
            if (P > 0 && (iy < 0 || iy >= HIN)) continue;
            const float* row = ip + iy * WIN;
            float w[WINW];
            if constexpr (P == 0) {
                float4 v0 = *(const float4*)(row + ox0);
                float4 v1 = *(const float4*)(row + ox0 + 4);
                w[0] = v0.x; w[1] = v0.y; w[2] = v0.z; w[3] = v0.w;
                w[4] = v1.x; w[5] = v1.y; w[6] = v1.z; w[7] = v1.w;
            } else {
                w[0] = (ixb >= 0) ? row[ixb] : 0.f;
#pragma unroll
                for (int m = 0; m < (WINW - 2) / 4; m++) {
                    float4 v = *(const float4*)(row + ixb + 1 + 4 * m);
                    w[1 + 4 * m] = v.x; w[2 + 4 * m] = v.y;
                    w[3 + 4 * m] = v.z; w[4 + 4 * m] = v.w;
                }
                w[WINW - 1] = (ixb + WINW - 1 < WIN) ? row[ixb + WINW - 1] : 0.f;
            }
            if (IN_RELU) {
#pragma unroll
                for (int m = 0; m < WINW; m++) w[m] = fmaxf(w[m], 0.f);
            }
#pragma unroll
            for (int c = 0; c < TCO; c++) {
                const float* wp = wci + c * CIN * KH * KW + ky * KW;
                if constexpr (KW == 4) {
                    float4 wv = *(const float4*)wp;
                    float wk[4] = {wv.x, wv.y, wv.z, wv.w};
#pragma unroll
                    for (int kx = 0; kx < 4; kx++)
#pragma unroll
                        for (int j = 0; j < TX; j++)
                            acc[c][j] = fmaf(w[j * S + kx], wk[kx], acc[c][j]);
                } else {
#pragma unroll
                    for (int kx = 0; kx < KW; kx++) {
                        float wv = __ldg(wp + kx);
#pragma unroll
                        for (int j = 0; j < TX; j++)
                            acc[c][j] = fmaf(w[j * S + kx], wv, acc[c][j]);
                    }
                }
            }
        }
    }

#pragma unroll
    for (int c = 0; c < TCO; c++) {
        size_t o = (((size_t)b * COUT + (co0 + c)) * HOUT + oy) * WOUT + ox0;
        float v[TX];
#pragma unroll
        for (int j = 0; j < TX; j++) v[j] = acc[c][j];
        if (ADD) {
            float4 r0 = *(const float4*)(res + o);
            float4 r1 = *(const float4*)(res + o + 4);
            v[0] += r0.x; v[1] += r0.y; v[2] += r0.z; v[3] += r0.w;
            v[4] += r1.x; v[5] += r1.y; v[6] += r1.z; v[7] += r1.w;
        }
        if (OUT_RELU) {
#pragma unroll
            for (int j = 0; j < TX; j++) v[j] = fmaxf(v[j], 0.f);
        }
        *(float4*)(out + o)     = make_float4(v[0], v[1], v[2], v[3]);
        *(float4*)(out + o + 4) = make_float4(v[4], v[5], v[6], v[7]);
    }
}

// ---------------------------------------------------------------------------
// Smem-staged 3x3 s1 p1 conv on 32x32 maps (R8, proven).
// ---------------------------------------------------------------------------
template <int CINC, int CIN_TOTAL, int COUT, int NCH, bool IN_RELU, bool BIAS>
__global__ __launch_bounds__(128)
void conv3m_k(const float* __restrict__ in, const float* __restrict__ wt,
              const float* __restrict__ bs, float* __restrict__ out)
{
    __shared__ float sW[4 * 36];          // current 4 ci: [q][c*9 + tap]
    __shared__ float sI[4 * 36 * 32];     // 4 channels, rows padded to 36

    const int t     = threadIdx.x;
    const int ox0   = (t & 3) * 8;
    const int oy    = t >> 2;
    const int chunk = blockIdx.x;
    const int co0   = blockIdx.y * 4;
    const int b     = blockIdx.z;
    const int ci0   = chunk * CINC;

    float acc[4][8];
#pragma unroll
    for (int c = 0; c < 4; c++) {
        float bv = (NCH == 1 && BIAS) ? __ldg(bs + co0 + c) : 0.f;
#pragma unroll
        for (int j = 0; j < 8; j++) acc[c][j] = bv;
    }

    const float* inb = in + ((size_t)b * CIN_TOTAL + ci0) * 1024;

#pragma unroll 1
    for (int cc = 0; cc < CINC; cc += 4) {
        __syncthreads();
#pragma unroll
        for (int m = 0; m < 8; m++) {
            int idx = m * 128 + t;
            int q   = idx >> 8;
            int rem = idx & 255;
            int y   = rem >> 3;
            int xg  = (rem & 7) * 4;
            float4 v = *(const float4*)(inb + (cc + q) * 1024 + y * 32 + xg);
            if (IN_RELU) {
                v.x = fmaxf(v.x, 0.f); v.y = fmaxf(v.y, 0.f);
                v.z = fmaxf(v.z, 0.f); v.w = fmaxf(v.w, 0.f);
            }
            *(float4*)(sI + q * 1152 + y * 36 + xg) = v;
        }
        for (int i = t; i < 144; i += 128) {
            int q   = i / 36;
            int r   = i - q * 36;
            int c   = r / 9;
            int tap = r - c * 9;
            sW[i] =
                __ldg(wt + ((size_t)(co0 + c) * CIN_TOTAL + ci0 + cc + q) * 9 + tap);
        }
        __syncthreads();

#pragma unroll
        for (int q = 0; q < 4; q++) {
            const float* sw = sW + q * 36;
            const float* si = sI + q * 1152;
#pragma unroll
            for (int ky = 0; ky < 3; ky++) {
                int iy = oy - 1 + ky;
                if (iy < 0 || iy >= 32) continue;
                const float* row = si + iy * 36;
                float w[10];
                w[0] = (ox0 > 0) ? row[ox0 - 1] : 0.f;
                float4 v0 = *(const float4*)(row + ox0);
                float4 v1 = *(const float4*)(row + ox0 + 4);
                w[1] = v0.x; w[2] = v0.y; w[3] = v0.z; w[4] = v0.w;
                w[5] = v1.x; w[6] = v1.y; w[7] = v1.z; w[8] = v1.w;
                w[9] = (ox0 < 24) ? row[ox0 + 8] : 0.f;
#pragma unroll
                for (int c = 0; c < 4; c++) {
                    float w0 = sw[c * 9 + ky * 3];
                    float w1 = sw[c * 9 + ky * 3 + 1];
                    float w2 = sw[c * 9 + ky * 3 + 2];
#pragma unroll
                    for (int j = 0; j < 8; j++) {
                        acc[c][j] = fmaf(w[j],     w0, acc[c][j]);
                        acc[c][j] = fmaf(w[j + 1], w1, acc[c][j]);
                        acc[c][j] = fmaf(w[j + 2], w2, acc[c][j]);
                    }
                }
            }
        }
    }

#pragma unroll
    for (int c = 0; c < 4; c++) {
        size_t o;
        if (NCH == 1)
            o = (((size_t)b * COUT + (co0 + c)) * 32 + oy) * 32 + ox0;
        else
            o = (((size_t)(b * NCH + chunk) * COUT + (co0 + c)) * 32 + oy) * 32 + ox0;
        *(float4*)(out + o)     = make_float4(acc[c][0], acc[c][1], acc[c][2], acc[c][3]);
        *(float4*)(out + o + 4) = make_float4(acc[c][4], acc[c][5], acc[c][6], acc[c][7]);
    }
}

// ---------------------------------------------------------------------------
// Smem-staged k4 s2 p1 conv (e2) (R9, proven).
// ---------------------------------------------------------------------------
template <int CIN, int COUT>
__global__ __launch_bounds__(128)
void conv4m_k(const float* __restrict__ in, const float* __restrict__ wt,
              const float* __restrict__ bs, float* __restrict__ out)
{
    __shared__ float sI[66 * 68];
    __shared__ float sW[64];

    const int t   = threadIdx.x;
    const int ox0 = (t & 3) * 8;
    const int oy  = t >> 2;
    const int co0 = blockIdx.y * 4;
    const int b   = blockIdx.z;
    const int ixb = ox0 * 2 - 1;

    for (int i = t; i < (66 * 68) / 4; i += 128)
        *(float4*)(sI + i * 4) = make_float4(0.f, 0.f, 0.f, 0.f);

    float acc[4][8];
#pragma unroll
    for (int c = 0; c < 4; c++) {
        float bv = __ldg(bs + co0 + c);
#pragma unroll
        for (int j = 0; j < 8; j++) acc[c][j] = bv;
    }

    const float* inb = in + (size_t)b * CIN * 4096;

#pragma unroll 1
    for (int ci = 0; ci < CIN; ci++) {
        __syncthreads();
        const float* ip = inb + ci * 4096;
#pragma unroll
        for (int m = 0; m < 8; m++) {
            int idx = m * 128 + t;
            int y   = idx >> 4;
            int xg  = (idx & 15) * 4;
            float4 v = *(const float4*)(ip + y * 64 + xg);
            *(float4*)(sI + (y + 1) * 68 + xg) = v;
        }
        if (t < 16) {
            int c  = t >> 2;
            int ky = t & 3;
            *(float4*)(sW + t * 4) =
                *(const float4*)(wt + ((size_t)(co0 + c) * CIN + ci) * 16 + ky * 4);
        }
        __syncthreads();

#pragma unroll
        for (int ky = 0; ky < 4; ky++) {
            const float* row = sI + (oy * 2 + ky) * 68;
            float w[18];
            w[0] = (ox0 > 0) ? row[ixb] : 0.f;
#pragma unroll
            for (int m = 0; m < 4; m++) {
                float4 v = *(const float4*)(row + 2 * ox0 + 4 * m);
                w[1 + 4 * m] = v.x; w[2 + 4 * m] = v.y;
                w[3 + 4 * m] = v.z; w[4 + 4 * m] = v.w;
            }
            w[17] = row[ixb + 17];
#pragma unroll
            for (int c = 0; c < 4; c++) {
                float4 wv = *(const float4*)(sW + (c * 4 + ky) * 4);
                float wk[4] = {wv.x, wv.y, wv.z, wv.w};
#pragma unroll
                for (int kx = 0; kx < 4; kx++)
#pragma unroll
                    for (int j = 0; j < 8; j++)
                        acc[c][j] = fmaf(w[j * 2 + kx], wk[kx], acc[c][j]);
            }
        }
    }

#pragma unroll
    for (int c = 0; c < 4; c++) {
        size_t o = (((size_t)b * COUT + (co0 + c)) * 32 + oy) * 32 + ox0;
        float v[8];
#pragma unroll
        for (int j = 0; j < 8; j++) v[j] = fmaxf(acc[c][j], 0.f);
        *(float4*)(out + o)     = make_float4(v[0], v[1], v[2], v[3]);
        *(float4*)(out + o + 4) = make_float4(v[4], v[5], v[6], v[7]);
    }
}

// ---------------------------------------------------------------------------
// Smem-staged ConvTranspose2d(k=4,s=2,p=1) for dt1 (R9, proven).
// ---------------------------------------------------------------------------
template <int CIN, int COUT>
__global__ __launch_bounds__(128)
void dc4m_k(const float* __restrict__ in, const float* __restrict__ wt,
            const float* __restrict__ bs, float* __restrict__ out)
{
    __shared__ float sI[4 * 360];
    __shared__ float sW[4 * 64];

    const int t   = threadIdx.x;
    const int bx  = blockIdx.x;
    const int ox0 = (t & 7) * 8;
    const int oy  = bx * 16 + (t >> 3);
    const int co0 = blockIdx.y * 4;
    const int b   = blockIdx.z;
    const int iy0 = bx * 8 - 1;
    const int ixb = ox0 / 2 - 1;
    const int oyp = oy & 1;

    float acc[4][8];
#pragma unroll
    for (int c = 0; c < 4; c++) {
        float bv = __ldg(bs + co0 + c);
#pragma unroll
        for (int j = 0; j < 8; j++) acc[c][j] = bv;
    }

    const float* inb = in + (size_t)b * CIN * 1024;

#pragma unroll 1
    for (int cc = 0; cc < CIN; cc += 4) {
        __syncthreads();
        for (int i = t; i < 360; i += 128) {
            int q   = i / 90;
            int rem = i - q * 90;
            int r   = rem / 9;
            int xf  = rem - r * 9;
            int iy  = iy0 + r;
            float4 v = make_float4(0.f, 0.f, 0.f, 0.f);
            if (xf < 8 && iy >= 0 && iy < 32) {
                v = *(const float4*)(inb + (cc + q) * 1024 + iy * 32 + xf * 4);
                v.x = fmaxf(v.x, 0.f); v.y = fmaxf(v.y, 0.f);
                v.z = fmaxf(v.z, 0.f); v.w = fmaxf(v.w, 0.f);
            }
            *(float4*)(sI + q * 360 + r * 36 + xf * 4) = v;
        }
        for (int i = t; i < 64; i += 128) {
            int q  = i >> 4;
            int rm = i & 15;
            int c  = rm >> 2;
            int ky = rm & 3;
            *(float4*)(sW + i * 4) =
                *(const float4*)(wt + ((size_t)(co0 + c) * CIN + cc + q) * 16 + ky * 4);
        }
        __syncthreads();

#pragma unroll
        for (int q = 0; q < 4; q++) {
            const float* si = sI + q * 360;
#pragma unroll
            for (int tt = 0; tt < 2; tt++) {
                int ky = oyp + 2 * tt;
                int r  = ((oy - 2 + ky) >> 1) - iy0;
                const float* row = si + r * 36;
                float u[6];
                u[0] = (ixb >= 0) ? row[ixb] : 0.f;
                float4 v = *(const float4*)(row + ixb + 1);
                u[1] = v.x; u[2] = v.y; u[3] = v.z; u[4] = v.w;
                u[5] = row[ixb + 5];
#pragma unroll
                for (int c = 0; c < 4; c++) {
                    float4 wv = *(const float4*)(sW + (q * 16 + c * 4 + ky) * 4);
#pragma unroll
                    for (int j = 0; j < 8; j++) {
                        const int jo = j & 1;
                        const int sh = (j + 1) >> 1;
                        float wl = jo ? wv.y : wv.x;
                        float wh = jo ? wv.w : wv.z;
                        acc[c][j] = fmaf(u[sh],     wl, acc[c][j]);
                        acc[c][j] = fmaf(u[sh + 1], wh, acc[c][j]);
                    }
                }
            }
        }
    }

#pragma unroll
    for (int c = 0; c < 4; c++) {
        size_t o = (((size_t)b * COUT + (co0 + c)) * 64 + oy) * 64 + ox0;
        float v[8];
#pragma unroll
        for (int j = 0; j < 8; j++) v[j] = fmaxf(acc[c][j], 0.f);
        *(float4*)(out + o)     = make_float4(v[0], v[1], v[2], v[3]);
        *(float4*)(out + o + 4) = make_float4(v[4], v[5], v[6], v[7]);
    }
}

// ---------------------------------------------------------------------------
// NEW: smem-staged ConvTranspose2d(k=4,s=2,p=1) for dt2: in 64x64 -> out
// 128x128, COUT=3, no relu. Scalar stores (out base misaligned).
// Block: 8 out rows x 128 cols; 4-ci chunks of 6 padded rows.
// ---------------------------------------------------------------------------
template <int CIN>
__global__ __launch_bounds__(128)
void dc4m3_k(const float* __restrict__ in, const float* __restrict__ wt,
             const float* __restrict__ bs, float* __restrict__ out)
{
    __shared__ float sI[4 * 408];   // 4 ci x 6 rows x 68 (cols 64..67 zero pad)
    __shared__ float sW[4 * 48];    // 4 ci x 3 co x 16 taps

    const int t   = threadIdx.x;
    const int bx  = blockIdx.x;
    const int ox0 = (t & 15) * 8;
    const int oy  = bx * 8 + (t >> 4);
    const int b   = blockIdx.z;
    const int iy0 = bx * 4 - 1;        // global iy of staged row r=0
    const int ixb = ox0 / 2 - 1;
    const int oyp = oy & 1;

    float acc[3][8];
#pragma unroll
    for (int c = 0; c < 3; c++) {
        float bv = __ldg(bs + c);
#pragma unroll
        for (int j = 0; j < 8; j++) acc[c][j] = bv;
    }

    const float* inb = in + (size_t)b * CIN * 4096;

#pragma unroll 1
    for (int cc = 0; cc < CIN; cc += 4) {
        __syncthreads();
        // stage 4 ci x 6 rows x 17 float4 (last f4 zero pad; OOB rows zero)
        for (int i = t; i < 408; i += 128) {
            int q   = i / 102;
            int rem = i - q * 102;
            int r   = rem / 17;
            int xf  = rem - r * 17;
            int iy  = iy0 + r;
            float4 v = make_float4(0.f, 0.f, 0.f, 0.f);
            if (xf < 16 && iy >= 0 && iy < 64)
                v = *(const float4*)(inb + (cc + q) * 4096 + iy * 64 + xf * 4);
            *(float4*)(sI + q * 408 + r * 68 + xf * 4) = v;
        }
        // stage weights: 4 ci x 3 co x 4 ky float4
        for (int i = t; i < 48; i += 128) {
            int q  = i / 12;
            int rm = i - q * 12;
            int c  = rm >> 2;
            int ky = rm & 3;
            *(float4*)(sW + (q * 48 + c * 16 + ky * 4)) =
                *(const float4*)(wt + ((size_t)c * CIN + cc + q) * 16 + ky * 4);
        }
        __syncthreads();

#pragma unroll
        for (int q = 0; q < 4; q++) {
            const float* si = sI + q * 408;
#pragma unroll
            for (int tt = 0; tt < 2; tt++) {
                int ky = oyp + 2 * tt;
                int r  = ((oy - 2 + ky) >> 1) - iy0;
                const float* row = si + r * 68;
                float u[6];
                u[0] = (ixb >= 0) ? row[ixb] : 0.f;
                float4 v = *(const float4*)(row + ixb + 1);   // aligned (ox0/2 mult 4)
                u[1] = v.x; u[2] = v.y; u[3] = v.z; u[4] = v.w;
                u[5] = row[ixb + 5];                          // col<=64: zero pad
#pragma unroll
                for (int c = 0; c < 3; c++) {
                    float4 wv = *(const float4*)(sW + q * 48 + c * 16 + ky * 4);
#pragma unroll
                    for (int j = 0; j < 8; j++) {
                        const int jo = j & 1;
                        const int sh = (j + 1) >> 1;
                        float wl = jo ? wv.y : wv.x;
                        float wh = jo ? wv.w : wv.z;
                        acc[c][j] = fmaf(u[sh],     wl, acc[c][j]);
                        acc[c][j] = fmaf(u[sh + 1], wh, acc[c][j]);
                    }
                }
            }
        }
    }

#pragma unroll
    for (int c = 0; c < 3; c++) {
        size_t o = (((size_t)b * 3 + c) * 128 + oy) * 128 + ox0;
#pragma unroll
        for (int j = 0; j < 8; j++) out[o + j] = acc[c][j];   // misaligned base
    }
}

// ---------------------------------------------------------------------------
// Fused: sum 4 res3x3 partials -> relu -> 1x1 (32->128) -> + residual.
// Round 10: TCO=8 (halves partial re-read traffic), weights in smem.
// ---------------------------------------------------------------------------
__global__ __launch_bounds__(128)
void conv1r8_k(const float* __restrict__ part, const float* __restrict__ wt,
               const float* __restrict__ res, float* __restrict__ out)
{
    __shared__ float sW[8 * 32];   // [c][ci]

    const int t   = threadIdx.x;
    const int ox0 = (t & 3) * 8;
    const int oy  = t >> 2;
    const int co0 = blockIdx.y * 8;
    const int b   = blockIdx.z;

    // stage 8x32 weights once
    for (int i = t; i < 256; i += 128)
        sW[i] = __ldg(wt + (co0 + (i >> 5)) * 32 + (i & 31));
    __syncthreads();

    float acc[8][8];
#pragma unroll
    for (int c = 0; c < 8; c++)
#pragma unroll
        for (int j = 0; j < 8; j++) acc[c][j] = 0.f;

    const float* pb = part + (size_t)(b * 4) * 32 * 1024 + oy * 32 + ox0;

#pragma unroll 1
    for (int ci = 0; ci < 32; ci++) {
        const float* p = pb + ci * 1024;
        float w[8] = {0, 0, 0, 0, 0, 0, 0, 0};
#pragma unroll
        for (int ch = 0; ch < 4; ch++) {
            const float* pc = p + ch * 32 * 1024;
            float4 v0 = *(const float4*)pc;
            float4 v1 = *(const float4*)(pc + 4);
            w[0] += v0.x; w[1] += v0.y; w[2] += v0.z; w[3] += v0.w;
            w[4] += v1.x; w[5] += v1.y; w[6] += v1.z; w[7] += v1.w;
        }
#pragma unroll
        for (int m = 0; m < 8; m++) w[m] = fmaxf(w[m], 0.f);
#pragma unroll
        for (int c = 0; c < 8; c++) {
            float wv = sW[c * 32 + ci];
#pragma unroll
            for (int j = 0; j < 8; j++)
                acc[c][j] = fmaf(w[j], wv, acc[c][j]);
        }
    }

#pragma unroll
    for (int c = 0; c < 8; c++) {
        size_t o = (((size_t)b * 128 + (co0 + c)) * 32 + oy) * 32 + ox0;
        float4 r0 = *(const float4*)(res + o);
        float4 r1 = *(const float4*)(res + o + 4);
        *(float4*)(out + o) = make_float4(acc[c][0] + r0.x, acc[c][1] + r0.y,
                                          acc[c][2] + r0.z, acc[c][3] + r0.w);
        *(float4*)(out + o + 4) = make_float4(acc[c][4] + r1.x, acc[c][5] + r1.y,
                                              acc[c][6] + r1.z, acc[c][7] + r1.w);
    }
}

// ---------------------------------------------------------------------------
// VQ (R2, proven; grid now 256x128)
// ---------------------------------------------------------------------------
__global__ void cnorm_kernel(const float* __restrict__ cb, float* __restrict__ cn)
{
    int k = blockIdx.x * blockDim.x + threadIdx.x;
    if (k >= 512) return;
    const float* c = cb + k * 64;
    float s = 0.f;
#pragma unroll
    for (int d = 0; d < 64; d++) s = fmaf(c[d], c[d], s);
    cn[k] = s;
}

__global__ __launch_bounds__(128)
void vq_kernel(const float* __restrict__ z, const float* __restrict__ cb,
               const float* __restrict__ cn, int* __restrict__ idx,
               float* __restrict__ q, float* __restrict__ err)
{
    int p = blockIdx.x * blockDim.x + threadIdx.x;  // 0..32767
    if (p >= 32768) return;
    int b = p >> 10, s = p & 1023;
    const float* zp = z + (size_t)b * 64 * 1024 + s;
    float zv[64];
#pragma unroll
    for (int d = 0; d < 64; d++) zv[d] = zp[d * 1024];

    float best = 3.4e38f;
    int bk = 0;
#pragma unroll 1
    for (int k = 0; k < 512; k++) {
        const float4* c4 = (const float4*)(cb + (size_t)k * 64);
        float d0 = 0.f, d1 = 0.f, d2 = 0.f, d3 = 0.f;
#pragma unroll
        for (int m = 0; m < 16; m++) {
            float4 cv = __ldg(c4 + m);
            d0 = fmaf(zv[4 * m],     cv.x, d0);
            d1 = fmaf(zv[4 * m + 1], cv.y, d1);
            d2 = fmaf(zv[4 * m + 2], cv.z, d2);
            d3 = fmaf(zv[4 * m + 3], cv.w, d3);
        }
        float dist = __ldg(cn + k) - 2.f * ((d0 + d1) + (d2 + d3));
        if (dist < best) { best = dist; bk = k; }   // strict <: first-min (jnp.argmin)
    }
    idx[p] = bk;
    float* qp = q + (size_t)b * 64 * 1024 + s;
    const float* c = cb + (size_t)bk * 64;
    float e = 0.f;
#pragma unroll
    for (int d = 0; d < 64; d++) {
        float cd = __ldg(c + d);
        qp[d * 1024] = cd;
        float df = zv[d] - cd;
        e = fmaf(df, df, e);
    }
    err[p] = e;
}

__global__ __launch_bounds__(512)
void stats_kernel(const int* __restrict__ idx, const float* __restrict__ err,
                  float* __restrict__ out0, float* __restrict__ outp)
{
    __shared__ int   h[512];
    __shared__ float sm[512];
    int t = threadIdx.x;
    h[t] = 0;
    float s = 0.f;
    __syncthreads();
    for (int i = t; i < 32768; i += 512) {
        atomicAdd(&h[idx[i]], 1);
        s += err[i];
    }
    sm[t] = s;
    __syncthreads();
    for (int off = 256; off > 0; off >>= 1) {
        if (t < off) sm[t] += sm[t + off];
        __syncthreads();
    }
    if (t == 0) out0[0] = 1.25f * sm[0] / 2097152.0f;   // (1+beta)*mse
    __syncthreads();
    float pr = (float)h[t] * (1.0f / 32768.0f);
    sm[t] = pr * logf(pr + 1e-10f);
    __syncthreads();
    for (int off = 256; off > 0; off >>= 1) {
        if (t < off) sm[t] += sm[t + off];
        __syncthreads();
    }
    if (t == 0) outp[0] = expf(-sm[0]);
}

// ---------------------------------------------------------------------------
// Launch
// ---------------------------------------------------------------------------
extern "C" void kernel_launch(void* const* d_in, const int* in_sizes, int n_in,
                              void* d_out, int out_size)
{
    const float* x     = (const float*)d_in[0];
    const float* e_w1  = (const float*)d_in[1];
    const float* e_b1  = (const float*)d_in[2];
    const float* e_w2  = (const float*)d_in[3];
    const float* e_b2  = (const float*)d_in[4];
    const float* e_w3  = (const float*)d_in[5];
    const float* e_b3  = (const float*)d_in[6];
    const float* e_r1a = (const float*)d_in[7];
    const float* e_r1b = (const float*)d_in[8];
    const float* e_r2a = (const float*)d_in[9];
    const float* e_r2b = (const float*)d_in[10];
    const float* pre_w = (const float*)d_in[11];
    const float* pre_b = (const float*)d_in[12];
    const float* cb    = (const float*)d_in[13];
    const float* d_w1  = (const float*)d_in[14];
    const float* d_b1  = (const float*)d_in[15];
    const float* d_r1a = (const float*)d_in[16];
    const float* d_r1b = (const float*)d_in[17];
    const float* d_r2a = (const float*)d_in[18];
    const float* d_r2b = (const float*)d_in[19];
    const float* dt_w1 = (const float*)d_in[20];
    const float* dt_b1 = (const float*)d_in[21];
    const float* dt_w2 = (const float*)d_in[22];
    const float* dt_b2 = (const float*)d_in[23];
    float* out = (float*)d_out;

    float *A, *Bf, *Cc, *Z, *Q, *G, *cn, *err;
    int *idx;
    cudaGetSymbolAddress((void**)&A,    g_A);
    cudaGetSymbolAddress((void**)&Bf,   g_B);
    cudaGetSymbolAddress((void**)&Cc,   g_C);
    cudaGetSymbolAddress((void**)&Z,    g_Z);
    cudaGetSymbolAddress((void**)&Q,    g_Q);
    cudaGetSymbolAddress((void**)&G,    g_G);
    cudaGetSymbolAddress((void**)&cn,   g_cnorm);
    cudaGetSymbolAddress((void**)&err,  g_err);
    cudaGetSymbolAddress((void**)&idx,  g_idx);

    dim3 blk(128);

    // ---- encoder ----
    conv_k<4,4,2,1,4, 3,128,128, 64,64,64, false,true,true,false>
        <<<dim3(4, 16, 32), blk>>>(x, e_w1, e_b1, A, nullptr);
    conv4m_k<64, 128><<<dim3(1, 32, 32), blk>>>(A, e_w2, e_b2, Bf);
    conv3m_k<128, 128, 128, 1, false, true>
        <<<dim3(1, 32, 32), blk>>>(Bf, e_w3, e_b3, Cc);
    conv3m_k<32, 128, 32, 4, true, false>
        <<<dim3(4, 8, 32), blk>>>(Cc, e_r1a, nullptr, A);
    conv1r8_k<<<dim3(1, 16, 32), blk>>>(A, e_r1b, Cc, Cc);
    conv3m_k<32, 128, 32, 4, true, false>
        <<<dim3(4, 8, 32), blk>>>(Cc, e_r2a, nullptr, A);
    conv1r8_k<<<dim3(1, 16, 32), blk>>>(A, e_r2b, Cc, Cc);
    conv_k<1,1,1,0,4, 128,32,32, 64,32,32, true,false,true,false>
        <<<dim3(1, 16, 32), blk>>>(Cc, pre_w, pre_b, Z, nullptr);

    // ---- vector quantizer ----
    cnorm_kernel<<<2, 256>>>(cb, cn);
    vq_kernel<<<256, 128>>>(Z, cb, cn, idx, Q, err);
    stats_kernel<<<1, 512>>>(idx, err, out, out + (out_size - 1));

    // ---- decoder ----
    conv3m_k<64, 64, 128, 1, false, true>
        <<<dim3(1, 32, 32), blk>>>(Q, d_w1, d_b1, G);
    conv3m_k<32, 128, 32, 4, true, false>
        <<<dim3(4, 8, 32), blk>>>(G, d_r1a, nullptr, A);
    conv1r8_k<<<dim3(1, 16, 32), blk>>>(A, d_r1b, G, G);
    conv3m_k<32, 128, 32, 4, true, false>
        <<<dim3(4, 8, 32), blk>>>(G, d_r2a, nullptr, A);
    conv1r8_k<<<dim3(1, 16, 32), blk>>>(A, d_r2b, G, G);
    dc4m_k<128, 64><<<dim3(4, 16, 32), blk>>>(G, dt_w1, dt_b1, A);
    // dt2 (smem): A -> x_recon into d_out+1
    dc4m3_k<64><<<dim3(16, 1, 32), blk>>>(A, dt_w2, dt_b2, out + 1);
}